// round 13
// baseline (speedup 1.0000x reference)
#include <cuda_runtime.h>
#include <cuda_fp16.h>
#include <stdint.h>
#include <math.h>

#define NMAX 10000
#define EMAX 160000
#define NBLK ((EMAX + 63) / 64)

// ---------------- scratch ----------------
__device__ float g_hemtx[EMAX * 64];
__device__ float g_xhat[EMAX * 3];
__device__ float g_w[EMAX * 4];
__device__ float g_expsum[NMAX * 4];
__device__ int   g_counts[NMAX];
__device__ int   g_off[NMAX + 1];
__device__ int   g_cursor[NMAX];
__device__ int   g_eid[EMAX];
__device__ float g_he[NMAX * 256];
__device__ float g_cnorm[NMAX * 256];
__device__ float g_dv[NMAX * 3];
__device__ float g_phe[NBLK * 2 * 256];
__device__ float g_pcomb[NBLK * 2 * 3 * 256];
__device__ __half g_wx[256 * 256];           // W_xmix^T fp16 [n][k]
__device__ uint32_t g_ewi[4096];
__device__ uint32_t g_ew1a[4096];
__device__ uint32_t g_ew1b[2048];
__device__ uint32_t g_ew2[2048];

__device__ __forceinline__ float siluf(float x) { return x / (1.f + __expf(-x)); }
__device__ __forceinline__ float fast_tanh(float x) {
    float y; asm("tanh.approx.f32 %0, %1;" : "=f"(y) : "f"(x)); return y;
}
__device__ __forceinline__ void mma16816h(float* d, const uint32_t* a, const uint32_t* b) {
    asm volatile("mma.sync.aligned.m16n8k16.row.col.f32.f16.f16.f32 "
        "{%0,%1,%2,%3}, {%4,%5,%6,%7}, {%8,%9}, {%0,%1,%2,%3};"
        : "+f"(d[0]), "+f"(d[1]), "+f"(d[2]), "+f"(d[3])
        : "r"(a[0]), "r"(a[1]), "r"(a[2]), "r"(a[3]), "r"(b[0]), "r"(b[1]));
}
__device__ __forceinline__ uint32_t pack2h(float a, float b) {
    __half2 p = __floats2half2_rn(a, b);
    return *(uint32_t*)&p;
}
__device__ __forceinline__ uint32_t smem_u32(const void* p) {
    uint32_t a;
    asm("{ .reg .u64 t; cvta.to.shared.u64 t, %1; cvt.u32.u64 %0, t; }" : "=r"(a) : "l"(p));
    return a;
}
#define LDSM4(r0, r1, r2, r3, addr) \
    asm volatile("ldmatrix.sync.aligned.m8n8.x4.shared.b16 {%0,%1,%2,%3}, [%4];" \
        : "=r"(r0), "=r"(r1), "=r"(r2), "=r"(r3) : "r"(addr))
#define CP_ASYNC16(dst, src) \
    asm volatile("cp.async.cg.shared.global [%0], [%1], 16;" :: "r"(dst), "l"(src) : "memory")
#define CP_COMMIT() asm volatile("cp.async.commit_group;" ::: "memory")
#define CP_WAIT0()  asm volatile("cp.async.wait_group 0;" ::: "memory")

// ---------------- K0: init + weight prep ----------------
__global__ void k_init(int N,
                       const float* __restrict__ W_xmix,
                       const float* __restrict__ W_in,
                       const float* __restrict__ W_out1,
                       const float* __restrict__ W_out2) {
    int i = blockIdx.x * blockDim.x + threadIdx.x;
    if (i < N * 4) g_expsum[i] = 0.f;
    if (i < N) g_counts[i] = 0;
    if (i < 65536) {
        int n = i >> 8, k = i & 255;
        g_wx[n * 256 + k] = __float2half_rn(W_xmix[k * 256 + n]);
    }
    if (i < 4096) {
        int n = i >> 6, k0 = (i & 63) * 2;
        float w0 = (n < 50) ? W_in[k0 * 50 + n] : 0.f;
        float w1 = (n < 50) ? W_in[(k0 + 1) * 50 + n] : 0.f;
        g_ewi[i] = pack2h(w0, w1);
    } else if (i < 8192) {
        int j = i - 4096;
        int n = j >> 6, k0 = (j & 63) * 2;
        g_ew1a[j] = pack2h(W_out1[k0 * 64 + n], W_out1[(k0 + 1) * 64 + n]);
    } else if (i < 10240) {
        int j = i - 8192;
        int n = j >> 5, k0 = (j & 31) * 2;
        float w0 = (k0 < 50) ? W_out1[(128 + k0) * 64 + n] : ((k0 == 50) ? W_out1[178 * 64 + n] : 0.f);
        int k1 = k0 + 1;
        float w1 = (k1 < 50) ? W_out1[(128 + k1) * 64 + n] : ((k1 == 50) ? W_out1[178 * 64 + n] : 0.f);
        g_ew1b[j] = pack2h(w0, w1);
    } else if (i < 12288) {
        int j = i - 10240;
        int n = j >> 5, k0 = (j & 31) * 2;
        g_ew2[j] = pack2h(W_out2[k0 * 64 + n], W_out2[(k0 + 1) * 64 + n]);
    }
}

// ---------------- K1: edge MLP via fp16 mma.sync + ldmatrix ----------------
#define O_A     0
#define O_X     4352
#define O_M     6656
#define O_WI    8960
#define O_W1A   13312
#define O_W1B   17664
#define O_W2    19968
#define O_HE    22272
#define O_BIN   26496
#define O_BO1   26560
#define O_BO2   26624
#define O_MEAN  26688
#define O_BETA  26752
#define O_WA    26816
#define O_BA    27072
#define O_NORM  27076
#define O_EX    27140
#define O_XHT   27204
#define E_SMEM  (27400 * 4)

__global__ void __launch_bounds__(256, 2)
k_edge_mma(const float* __restrict__ h, const float* __restrict__ x,
           const int* __restrict__ idxs,
           const float* __restrict__ rbf_means, const float* __restrict__ rbf_betas,
           const float* __restrict__ b_in, const float* __restrict__ b_out1,
           const float* __restrict__ b_out2,
           const float* __restrict__ W_att, const float* __restrict__ b_att, int E)
{
    extern __shared__ uint32_t su[];
    float* sf = (float*)su;
    int tid = threadIdx.x, lid = tid & 31, wid = tid >> 5;
    int g = lid >> 2, tg = lid & 3;
    int mrow = (wid & 3) * 16, ncol = (wid >> 2) * 32;

    for (int i = tid; i < 4096; i += 256) {
        int n = i >> 6, kk = i & 63;
        su[O_WI  + n * 68 + kk] = g_ewi[i];
        su[O_W1A + n * 68 + kk] = g_ew1a[i];
    }
    for (int i = tid; i < 2048; i += 256) {
        int n = i >> 5, kk = i & 31;
        su[O_W1B + n * 36 + kk] = g_ew1b[i];
        su[O_W2  + n * 36 + kk] = g_ew2[i];
    }
    if (tid < 64) {
        sf[O_BIN + tid]  = (tid < 50) ? b_in[tid] : 0.f;
        sf[O_BO1 + tid]  = b_out1[tid];
        sf[O_BO2 + tid]  = b_out2[tid];
        sf[O_MEAN + tid] = (tid < 50) ? rbf_means[tid] : 0.f;
        sf[O_BETA + tid] = (tid < 50) ? rbf_betas[tid] : 1.f;
    }
    if (tid < 256) sf[O_WA + tid] = W_att[tid];
    if (tid < 4)   sf[O_BA + tid] = b_att[tid];
    __syncthreads();

    uint32_t sbase = smem_u32(su);
    int mq = lid >> 3, rr = lid & 7;
    int rA = mrow + (mq & 1) * 8 + rr;
    int cA = (mq >> 1) * 4;
    uint32_t adA  = sbase + (O_A  + rA * 68 + cA) * 4;
    uint32_t adX  = sbase + (O_X  + rA * 36 + cA) * 4;
    uint32_t adM  = sbase + (O_M  + rA * 36 + cA) * 4;
    int rB = (mq >> 1) * 8 + rr;
    int cB = (mq & 1) * 4;
    uint32_t adWI0  = sbase + (O_WI  + (ncol + rB) * 68 + cB) * 4;
    uint32_t adWI1  = sbase + (O_WI  + (ncol + 16 + rB) * 68 + cB) * 4;
    uint32_t adW1A0 = sbase + (O_W1A + (ncol + rB) * 68 + cB) * 4;
    uint32_t adW1A1 = sbase + (O_W1A + (ncol + 16 + rB) * 68 + cB) * 4;
    uint32_t adW1B0 = sbase + (O_W1B + (ncol + rB) * 36 + cB) * 4;
    uint32_t adW1B1 = sbase + (O_W1B + (ncol + 16 + rB) * 36 + cB) * 4;
    uint32_t adW20  = sbase + (O_W2  + (ncol + rB) * 36 + cB) * 4;
    uint32_t adW21  = sbase + (O_W2  + (ncol + 16 + rB) * 36 + cB) * 4;

    int ntiles = (E + 63) / 64;
    for (int tile = blockIdx.x; tile < ntiles; tile += gridDim.x) {
        int e0 = tile * 64, ne = min(64, E - e0);

        if (tid < 64) {
            float nrm = 0.f, xh0 = 0.f, xh1 = 0.f, xh2 = 0.f;
            if (tid < ne) {
                int s = idxs[2 * (e0 + tid)], d = idxs[2 * (e0 + tid) + 1];
                float dx = x[3 * s]     - x[3 * d];
                float dy = x[3 * s + 1] - x[3 * d + 1];
                float dz = x[3 * s + 2] - x[3 * d + 2];
                nrm = sqrtf(dx * dx + dy * dy + dz * dz + 1e-14f);
                float inv = 1.f / (nrm + 1e-5f);
                xh0 = dx * inv; xh1 = dy * inv; xh2 = dz * inv;
                atomicAdd(&g_counts[s], 1);
            }
            sf[O_NORM + tid] = nrm;
            sf[O_EX + tid]   = __expf(-nrm);
            sf[O_XHT + tid * 3] = xh0; sf[O_XHT + tid * 3 + 1] = xh1; sf[O_XHT + tid * 3 + 2] = xh2;
        }
        {
            int el = tid >> 2, part = tid & 3;
            uint32_t hb[16];
            if (el < ne) {
                int node = idxs[2 * (e0 + el) + (part >> 1)];
                const float4* hp = (const float4*)&h[node * 64 + (part & 1) * 32];
                #pragma unroll
                for (int i2 = 0; i2 < 8; i2++) {
                    float4 v = hp[i2];
                    hb[i2 * 2]     = pack2h(v.x, v.y);
                    hb[i2 * 2 + 1] = pack2h(v.z, v.w);
                }
            } else {
                #pragma unroll
                for (int i2 = 0; i2 < 16; i2++) hb[i2] = 0u;
            }
            uint4* dh = (uint4*)&su[O_A + el * 68 + part * 16];
            #pragma unroll
            for (int i2 = 0; i2 < 4; i2++)
                dh[i2] = make_uint4(hb[i2*4], hb[i2*4+1], hb[i2*4+2], hb[i2*4+3]);
        }
        __syncthreads();

        float acc[4][4];

        // ---- G1 ----
        #pragma unroll
        for (int nt = 0; nt < 4; nt++)
            #pragma unroll
            for (int q = 0; q < 4; q++) acc[nt][q] = 0.f;
        #pragma unroll
        for (int ks = 0; ks < 8; ks++) {
            uint32_t aH[4];
            LDSM4(aH[0], aH[1], aH[2], aH[3], adA + ks * 32);
            uint32_t b0, b1, b2, b3;
            LDSM4(b0, b1, b2, b3, adWI0 + ks * 32);
            { uint32_t bb[2] = { b0, b1 }; mma16816h(acc[0], aH, bb); }
            { uint32_t bb[2] = { b2, b3 }; mma16816h(acc[1], aH, bb); }
            LDSM4(b0, b1, b2, b3, adWI1 + ks * 32);
            { uint32_t bb[2] = { b0, b1 }; mma16816h(acc[2], aH, bb); }
            { uint32_t bb[2] = { b2, b3 }; mma16816h(acc[3], aH, bb); }
        }
        #pragma unroll
        for (int nt = 0; nt < 4; nt++) {
            #pragma unroll
            for (int hh = 0; hh < 2; hh++) {
                int row = mrow + g + hh * 8;
                int c0 = ncol + nt * 8 + tg * 2;
                float v0 = acc[nt][hh * 2]     + sf[O_BIN + c0];
                float v1 = acc[nt][hh * 2 + 1] + sf[O_BIN + c0 + 1];
                float ex = sf[O_EX + row];
                float x0, x1;
                if (c0 < 50) { float d = ex - sf[O_MEAN + c0]; x0 = __expf(-sf[O_BETA + c0] * d * d) * v0; }
                else x0 = (c0 == 50) ? sf[O_NORM + row] : 0.f;
                if (c0 + 1 < 50) { float d = ex - sf[O_MEAN + c0 + 1]; x1 = __expf(-sf[O_BETA + c0 + 1] * d * d) * v1; }
                else x1 = 0.f;
                su[O_X + row * 36 + (c0 >> 1)] = pack2h(x0, x1);
            }
        }
        __syncthreads();

        // ---- G2 ----
        #pragma unroll
        for (int nt = 0; nt < 4; nt++)
            #pragma unroll
            for (int q = 0; q < 4; q++) acc[nt][q] = 0.f;
        #pragma unroll
        for (int ks = 0; ks < 8; ks++) {
            uint32_t aH[4];
            LDSM4(aH[0], aH[1], aH[2], aH[3], adA + ks * 32);
            uint32_t b0, b1, b2, b3;
            LDSM4(b0, b1, b2, b3, adW1A0 + ks * 32);
            { uint32_t bb[2] = { b0, b1 }; mma16816h(acc[0], aH, bb); }
            { uint32_t bb[2] = { b2, b3 }; mma16816h(acc[1], aH, bb); }
            LDSM4(b0, b1, b2, b3, adW1A1 + ks * 32);
            { uint32_t bb[2] = { b0, b1 }; mma16816h(acc[2], aH, bb); }
            { uint32_t bb[2] = { b2, b3 }; mma16816h(acc[3], aH, bb); }
        }
        #pragma unroll
        for (int ks = 0; ks < 4; ks++) {
            uint32_t aH[4];
            LDSM4(aH[0], aH[1], aH[2], aH[3], adX + ks * 32);
            uint32_t b0, b1, b2, b3;
            LDSM4(b0, b1, b2, b3, adW1B0 + ks * 32);
            { uint32_t bb[2] = { b0, b1 }; mma16816h(acc[0], aH, bb); }
            { uint32_t bb[2] = { b2, b3 }; mma16816h(acc[1], aH, bb); }
            LDSM4(b0, b1, b2, b3, adW1B1 + ks * 32);
            { uint32_t bb[2] = { b0, b1 }; mma16816h(acc[2], aH, bb); }
            { uint32_t bb[2] = { b2, b3 }; mma16816h(acc[3], aH, bb); }
        }
        #pragma unroll
        for (int nt = 0; nt < 4; nt++) {
            #pragma unroll
            for (int hh = 0; hh < 2; hh++) {
                int row = mrow + g + hh * 8;
                int c0 = ncol + nt * 8 + tg * 2;
                float m0 = siluf(acc[nt][hh * 2]     + sf[O_BO1 + c0]);
                float m1 = siluf(acc[nt][hh * 2 + 1] + sf[O_BO1 + c0 + 1]);
                su[O_M + row * 36 + (c0 >> 1)] = pack2h(m0, m1);
            }
        }
        __syncthreads();

        // ---- G3 ----
        #pragma unroll
        for (int nt = 0; nt < 4; nt++)
            #pragma unroll
            for (int q = 0; q < 4; q++) acc[nt][q] = 0.f;
        #pragma unroll
        for (int ks = 0; ks < 4; ks++) {
            uint32_t aH[4];
            LDSM4(aH[0], aH[1], aH[2], aH[3], adM + ks * 32);
            uint32_t b0, b1, b2, b3;
            LDSM4(b0, b1, b2, b3, adW20 + ks * 32);
            { uint32_t bb[2] = { b0, b1 }; mma16816h(acc[0], aH, bb); }
            { uint32_t bb[2] = { b2, b3 }; mma16816h(acc[1], aH, bb); }
            LDSM4(b0, b1, b2, b3, adW21 + ks * 32);
            { uint32_t bb[2] = { b0, b1 }; mma16816h(acc[2], aH, bb); }
            { uint32_t bb[2] = { b2, b3 }; mma16816h(acc[3], aH, bb); }
        }
        #pragma unroll
        for (int nt = 0; nt < 4; nt++) {
            #pragma unroll
            for (int hh = 0; hh < 2; hh++) {
                int row = mrow + g + hh * 8;
                int c0 = ncol + nt * 8 + tg * 2;
                sf[O_HE + row * 66 + c0]     = acc[nt][hh * 2]     + sf[O_BO2 + c0];
                sf[O_HE + row * 66 + c0 + 1] = acc[nt][hh * 2 + 1] + sf[O_BO2 + c0 + 1];
            }
        }
        __syncthreads();

        // att: logits -> exp -> g_w, expsum (no max shift)
        {
            int el = tid >> 2, a = tid & 3;
            if (el < ne) {
                float acc2 = sf[O_BA + a];
                const float* hv = &sf[O_HE + el * 66];
                #pragma unroll 8
                for (int c = 0; c < 64; c++) acc2 += hv[c] * sf[O_WA + c * 4 + a];
                float lg = (acc2 > 0.f) ? acc2 : 2.f * (__expf(acc2 * 0.5f) - 1.f);
                float w = __expf(lg);
                int s = idxs[2 * (e0 + el)];
                g_w[(e0 + el) * 4 + a] = w;
                atomicAdd(&g_expsum[s * 4 + a], w);
            }
        }
        for (int i = tid; i < ne * 16; i += 256) {
            int el = i >> 4, c = (i & 15) * 4;
            float4 o = make_float4(sf[O_HE + el * 66 + c], sf[O_HE + el * 66 + c + 1],
                                   sf[O_HE + el * 66 + c + 2], sf[O_HE + el * 66 + c + 3]);
            *(float4*)&g_hemtx[(size_t)(e0 + el) * 64 + c] = o;
        }
        for (int i = tid; i < ne * 3; i += 256) g_xhat[e0 * 3 + i] = sf[O_XHT + i];
        __syncthreads();
    }
}

// ---------------- K2: exclusive scan (shuffle-based) ----------------
__global__ void k_scan(int N) {
    __shared__ int wsum[32];
    int t = threadIdx.x, lane = t & 31, w = t >> 5;
    int chunk = (N + 1023) / 1024;
    int base = t * chunk;
    int vals[16];
    int loc = 0;
    for (int k = 0; k < chunk; k++) {
        int idx = base + k;
        int v = (idx < N) ? g_counts[idx] : 0;
        vals[k] = loc; loc += v;
    }
    int inc = loc;
    #pragma unroll
    for (int o = 1; o < 32; o <<= 1) {
        int v = __shfl_up_sync(0xFFFFFFFFu, inc, o);
        if (lane >= o) inc += v;
    }
    if (lane == 31) wsum[w] = inc;
    __syncthreads();
    if (w == 0) {
        int v2 = wsum[lane];
        int i2 = v2;
        #pragma unroll
        for (int o = 1; o < 32; o <<= 1) {
            int x2 = __shfl_up_sync(0xFFFFFFFFu, i2, o);
            if (lane >= o) i2 += x2;
        }
        wsum[lane] = i2 - v2;
    }
    __syncthreads();
    int excl = wsum[w] + (inc - loc);
    for (int k = 0; k < chunk; k++) {
        int idx = base + k;
        if (idx < N) { g_off[idx] = excl + vals[k]; g_cursor[idx] = excl + vals[k]; }
    }
    if (t == 1023) g_off[N] = excl + loc;
}

// ---------------- K3: CSR fill (pure) ----------------
__global__ void k_fill(const int* __restrict__ idxs, int E) {
    int e = blockIdx.x * blockDim.x + threadIdx.x;
    if (e >= E) return;
    int s = idxs[2 * e];
    int p = atomicAdd(&g_cursor[s], 1);
    g_eid[p] = e;
}

// ---------------- K5: fused xmix GEMM + aggregation (cp.async double-buffered W) ----------------
#define XG_A    0
#define XG_W0   8448
#define XG_W1   17664
#define XG_XH   26880
#define XG_NODE 27072
#define XG_WV   27136
#define XG_RED  27392
#define XG_SMEM (27420 * 4)

__global__ void __launch_bounds__(256, 2)
k_xagg(const int* __restrict__ idxs, const float* __restrict__ W_vmix, int E)
{
    extern __shared__ uint32_t su[];
    float* sf = (float*)su;
    int tid = threadIdx.x, lid = tid & 31, wid = tid >> 5;
    int p0 = blockIdx.x * 64;
    uint32_t* pA = su + XG_A;
    uint32_t* pC = su + XG_W0;
    int* sN = (int*)(su + XG_NODE);
    uint32_t sbase = smem_u32(su);

    {
        uint32_t dst = sbase + (XG_W0 + tid * 36) * 4;
        const char* src = (const char*)&g_wx[tid * 256];
        #pragma unroll
        for (int i = 0; i < 9; i++) CP_ASYNC16(dst + i * 16, src + i * 16);
        CP_COMMIT();
    }

    {
        int sl = tid & 63, kq = tid >> 6;
        int e = -1, s = -1;
        float att[4], hm[16];
        int p = p0 + sl;
        if (p < E) {
            e = g_eid[p];
            s = idxs[2 * e];
            #pragma unroll
            for (int a = 0; a < 4; a++) att[a] = g_w[e * 4 + a] / g_expsum[s * 4 + a];
            const float4* hp = (const float4*)&g_hemtx[(size_t)e * 64 + kq * 16];
            #pragma unroll
            for (int i = 0; i < 4; i++) {
                float4 v = hp[i];
                hm[i * 4] = v.x; hm[i * 4 + 1] = v.y; hm[i * 4 + 2] = v.z; hm[i * 4 + 3] = v.w;
            }
        } else {
            #pragma unroll
            for (int a = 0; a < 4; a++) att[a] = 0.f;
            #pragma unroll
            for (int i = 0; i < 16; i++) hm[i] = 0.f;
        }
        if (kq == 0) {
            sN[sl] = s;
            float x0 = 0.f, x1 = 0.f, x2 = 0.f;
            if (e >= 0) { x0 = g_xhat[e * 3]; x1 = g_xhat[e * 3 + 1]; x2 = g_xhat[e * 3 + 2]; }
            sf[XG_XH + sl * 3] = x0; sf[XG_XH + sl * 3 + 1] = x1; sf[XG_XH + sl * 3 + 2] = x2;
        }
        #pragma unroll
        for (int j = 0; j < 32; j++) {
            int kl = 2 * j;
            float m = hm[kl >> 2];
            pA[sl * 132 + ((kq * 64 + kl) >> 1)] = pack2h(m * att[kl & 3], m * att[(kl + 1) & 3]);
        }
        sf[XG_WV + tid] = W_vmix[tid];
    }
    CP_WAIT0();
    __syncthreads();

    int g = lid >> 2, tg = lid & 3;
    int mrow = (wid & 1) * 32;
    int ncol = (wid >> 1) * 64;

    int mq = lid >> 3, rr = lid & 7;
    uint32_t adA0 = sbase + (XG_A + (mrow + (mq & 1) * 8 + rr) * 132 + (mq >> 1) * 4) * 4;
    uint32_t adA1 = adA0 + 16 * 132 * 4;
    int rB = (mq >> 1) * 8 + rr;
    int cB = (mq & 1) * 4;
    uint32_t adW0 = sbase + (XG_W0 + (ncol + rB) * 36 + cB) * 4;
    uint32_t adW1 = adW0 + 16 * 36 * 4;
    uint32_t adW2 = adW0 + 32 * 36 * 4;
    uint32_t adW3 = adW0 + 48 * 36 * 4;
    const uint32_t BUFD = (XG_W1 - XG_W0) * 4;

    float acc[2][8][4];
    #pragma unroll
    for (int mt = 0; mt < 2; mt++)
        #pragma unroll
        for (int nt = 0; nt < 8; nt++)
            #pragma unroll
            for (int q = 0; q < 4; q++) acc[mt][nt][q] = 0.f;

    #pragma unroll
    for (int kc = 0; kc < 4; kc++) {
        if (kc < 3) {
            uint32_t dst = sbase + ((((kc + 1) & 1) ? XG_W1 : XG_W0) + tid * 36) * 4;
            const char* src = (const char*)&g_wx[tid * 256 + (kc + 1) * 64];
            #pragma unroll
            for (int i = 0; i < 9; i++) CP_ASYNC16(dst + i * 16, src + i * 16);
            CP_COMMIT();
        }
        uint32_t boff = (kc & 1) ? BUFD : 0u;
        #pragma unroll
        for (int ks = 0; ks < 4; ks++) {
            uint32_t aoff = kc * 128 + ks * 32;
            uint32_t aH[2][4];
            LDSM4(aH[0][0], aH[0][1], aH[0][2], aH[0][3], adA0 + aoff);
            LDSM4(aH[1][0], aH[1][1], aH[1][2], aH[1][3], adA1 + aoff);
            uint32_t woff = boff + ks * 32;
            uint32_t b0, b1, b2, b3;
            #define XAGG_PAIR(ADDR, NT) \
                LDSM4(b0, b1, b2, b3, (ADDR) + woff); \
                { uint32_t bb[2] = { b0, b1 }; mma16816h(acc[0][NT], aH[0], bb); mma16816h(acc[1][NT], aH[1], bb); } \
                { uint32_t bb[2] = { b2, b3 }; mma16816h(acc[0][(NT)+1], aH[0], bb); mma16816h(acc[1][(NT)+1], aH[1], bb); }
            XAGG_PAIR(adW0, 0)
            XAGG_PAIR(adW1, 2)
            XAGG_PAIR(adW2, 4)
            XAGG_PAIR(adW3, 6)
            #undef XAGG_PAIR
        }
        if (kc < 3) {
            CP_WAIT0();
            __syncthreads();
        }
    }

    #pragma unroll
    for (int mt = 0; mt < 2; mt++)
        #pragma unroll
        for (int nt = 0; nt < 8; nt++) {
            int rl = mrow + mt * 16 + g;
            int col = ncol + nt * 8 + tg * 2;
            float* a = acc[mt][nt];
            pC[rl * 132 + (col >> 1)]       = pack2h(fast_tanh(a[0]), fast_tanh(a[1]));
            pC[(rl + 8) * 132 + (col >> 1)] = pack2h(fast_tanh(a[2]), fast_tanh(a[3]));
        }
    __syncthreads();

    {
        int c = tid;
        int blk = blockIdx.x;
        float wv = sf[XG_WV + c];
        float accH = 0.f, a0 = 0.f, a1 = 0.f, a2 = 0.f;
        int segStart = 0;
        for (int sl = 0; sl < 64; sl++) {
            int n = sN[sl];
            if (n >= 0) {
                uint32_t ap = pA[sl * 132 + (c >> 1)];
                __half2 av2 = *(__half2*)&ap;
                float Av = (c & 1) ? __high2float(av2) : __low2float(av2);
                accH += Av;
                uint32_t cp = pC[sl * 132 + (c >> 1)];
                __half2 h2 = *(__half2*)&cp;
                float cf = (c & 1) ? __high2float(h2) : __low2float(h2);
                a0 += cf * sf[XG_XH + sl * 3];
                a1 += cf * sf[XG_XH + sl * 3 + 1];
                a2 += cf * sf[XG_XH + sl * 3 + 2];
            }
            bool segEnd = (sl == 63) || (sN[sl + 1] != n);
            if (segEnd) {
                if (n >= 0) {
                    int beg = g_off[n], end = g_off[n + 1];
                    bool full = (beg == p0 + segStart) && (end == p0 + sl + 1);
                    if (full) {
                        float invc = 1.f / ((float)(end - beg) + 1.f);
                        g_he[n * 256 + c] = accH;
                        float s0 = a0 * invc, s1 = a1 * invc, s2 = a2 * invc;
                        g_cnorm[n * 256 + c] = s0 * s0 + s1 * s1 + s2 * s2;
                        float r0 = wv * s0, r1 = wv * s1, r2 = wv * s2;
                        #pragma unroll
                        for (int o = 16; o > 0; o >>= 1) {
                            r0 += __shfl_xor_sync(0xFFFFFFFFu, r0, o);
                            r1 += __shfl_xor_sync(0xFFFFFFFFu, r1, o);
                            r2 += __shfl_xor_sync(0xFFFFFFFFu, r2, o);
                        }
                        if (lid == 0) {
                            sf[XG_RED + wid * 3]     = r0;
                            sf[XG_RED + wid * 3 + 1] = r1;
                            sf[XG_RED + wid * 3 + 2] = r2;
                        }
                        __syncthreads();
                        if (c < 3) {
                            float s = 0.f;
                            #pragma unroll
                            for (int w = 0; w < 8; w++) s += sf[XG_RED + w * 3 + c];
                            g_dv[n * 3 + c] = s;
                        }
                        __syncthreads();
                    } else {
                        int slot = (segStart == 0) ? 0 : 1;
                        g_phe[((size_t)blk * 2 + slot) * 256 + c] = accH;
                        g_pcomb[(((size_t)blk * 2 + slot) * 3 + 0) * 256 + c] = a0;
                        g_pcomb[(((size_t)blk * 2 + slot) * 3 + 1) * 256 + c] = a1;
                        g_pcomb[(((size_t)blk * 2 + slot) * 3 + 2) * 256 + c] = a2;
                    }
                }
                accH = 0.f; a0 = 0.f; a1 = 0.f; a2 = 0.f;
                segStart = sl + 1;
            }
        }
    }
}

// ---------------- K7: node MLPs (with fused k_fin) ----------------
__global__ void k_node(const float* __restrict__ h, const float* __restrict__ x,
                       const float* __restrict__ v, const float* __restrict__ W_vmix,
                       const float* __restrict__ W_post1, const float* __restrict__ b_post1,
                       const float* __restrict__ W_post2, const float* __restrict__ b_post2,
                       const float* __restrict__ W_node1, const float* __restrict__ b_node1,
                       const float* __restrict__ W_node2, const float* __restrict__ b_node2,
                       const float* __restrict__ W_vel1,  const float* __restrict__ b_vel1,
                       const float* __restrict__ W_vel2,
                       float* __restrict__ out_h, float* __restrict__ out_x,
                       float* __restrict__ out_v, int N)
{
    extern __shared__ float sm[];
    float* sCN = sm;
    float* sHE = sCN + 8192;
    float* sH  = sHE + 8192;
    float* sT  = sH  + 2048;
    float* sHC = sT  + 2048;
    float* sHN = sHC + 2048;
    float* sBp1 = sHN + 2048;
    float* sBp2 = sBp1 + 64;
    float* sBn1 = sBp2 + 64;
    float* sBn2 = sBn1 + 64;
    float* sBv1 = sBn2 + 64;
    float* sWv2 = sBv1 + 64;
    float* sDV  = sWv2 + 64;     // 96
    float* sRED = sDV + 96;      // 24
    float* sWbuf = sRED + 24;

    int tid = threadIdx.x;
    int lid = tid & 31, wrp = tid >> 5;
    int n0 = blockIdx.x * 32;
    int nn = min(32, N - n0);

    if (tid < 64) {
        sBp1[tid] = b_post1[tid]; sBp2[tid] = b_post2[tid];
        sBn1[tid] = b_node1[tid]; sBn2[tid] = b_node2[tid];
        sBv1[tid] = b_vel1[tid];  sWv2[tid] = W_vel2[tid];
    }

    // ---- load he/cnorm/dv with inline k_fin for boundary nodes ----
    {
        int c = tid;
        float wv = W_vmix[c];
        for (int ln = 0; ln < 32; ln++) {
            int n = n0 + ln;
            if (n >= N) { sHE[ln * 256 + c] = 0.f; sCN[ln * 256 + c] = 0.f; continue; }
            int beg = g_off[n], end = g_off[n + 1];
            if (end == beg) {
                sHE[ln * 256 + c] = 0.f;
                sCN[ln * 256 + c] = 0.f;
                if (c < 3) sDV[ln * 3 + c] = 0.f;
                continue;
            }
            int b0 = beg >> 6, b1 = (end - 1) >> 6;
            if (b0 == b1) {
                sHE[ln * 256 + c] = g_he[n * 256 + c];
                sCN[ln * 256 + c] = g_cnorm[n * 256 + c];
                if (c < 3) sDV[ln * 3 + c] = g_dv[n * 3 + c];
            } else {
                float accH = 0.f, a0 = 0.f, a1 = 0.f, a2 = 0.f;
                for (int b = b0; b <= b1; b++) {
                    int slot = (b == b0 && (beg & 63) != 0) ? 1 : 0;
                    size_t base = ((size_t)b * 2 + slot);
                    accH += g_phe[base * 256 + c];
                    a0 += g_pcomb[(base * 3 + 0) * 256 + c];
                    a1 += g_pcomb[(base * 3 + 1) * 256 + c];
                    a2 += g_pcomb[(base * 3 + 2) * 256 + c];
                }
                sHE[ln * 256 + c] = accH;
                float invc = 1.f / ((float)(end - beg) + 1.f);
                float s0 = a0 * invc, s1 = a1 * invc, s2 = a2 * invc;
                sCN[ln * 256 + c] = s0 * s0 + s1 * s1 + s2 * s2;
                float r0 = wv * s0, r1 = wv * s1, r2 = wv * s2;
                #pragma unroll
                for (int o = 16; o > 0; o >>= 1) {
                    r0 += __shfl_xor_sync(0xFFFFFFFFu, r0, o);
                    r1 += __shfl_xor_sync(0xFFFFFFFFu, r1, o);
                    r2 += __shfl_xor_sync(0xFFFFFFFFu, r2, o);
                }
                if (lid == 0) { sRED[wrp * 3] = r0; sRED[wrp * 3 + 1] = r1; sRED[wrp * 3 + 2] = r2; }
                __syncthreads();
                if (c < 3) {
                    float s = 0.f;
                    #pragma unroll
                    for (int w = 0; w < 8; w++) s += sRED[w * 3 + c];
                    sDV[ln * 3 + c] = s;
                }
                __syncthreads();
            }
        }
    }
    for (int i = tid; i < 2048; i += 256) sH[i] = (i < nn * 64) ? h[n0 * 64 + i] : 0.f;
    __syncthreads();

    int gq = tid >> 4;
    int j0 = (tid & 15) * 4;
    int ln0 = gq * 2, ln1 = ln0 + 1;

    for (int i = tid; i < 16384; i += 256) sWbuf[i] = W_post1[i];
    __syncthreads();
    {
        float A0[4] = { sBp1[j0], sBp1[j0+1], sBp1[j0+2], sBp1[j0+3] };
        float A1[4] = { A0[0], A0[1], A0[2], A0[3] };
        const float* c0p = &sCN[ln0 * 256];
        const float* c1p = &sCN[ln1 * 256];
        #pragma unroll 4
        for (int c = 0; c < 256; c++) {
            float4 w = *(const float4*)&sWbuf[c * 64 + j0];
            float h0 = c0p[c], h1 = c1p[c];
            A0[0] += h0 * w.x; A0[1] += h0 * w.y; A0[2] += h0 * w.z; A0[3] += h0 * w.w;
            A1[0] += h1 * w.x; A1[1] += h1 * w.y; A1[2] += h1 * w.z; A1[3] += h1 * w.w;
        }
        float* o0 = &sT[ln0 * 64 + j0];
        float* o1 = &sT[ln1 * 64 + j0];
        o0[0] = siluf(A0[0]); o0[1] = siluf(A0[1]); o0[2] = siluf(A0[2]); o0[3] = siluf(A0[3]);
        o1[0] = siluf(A1[0]); o1[1] = siluf(A1[1]); o1[2] = siluf(A1[2]); o1[3] = siluf(A1[3]);
    }
    __syncthreads();

    for (int i = tid; i < 4096; i += 256) sWbuf[i] = W_post2[i];
    __syncthreads();
    {
        float A0[4] = { sBp2[j0], sBp2[j0+1], sBp2[j0+2], sBp2[j0+3] };
        float A1[4] = { A0[0], A0[1], A0[2], A0[3] };
        const float* t0p = &sT[ln0 * 64];
        const float* t1p = &sT[ln1 * 64];
        #pragma unroll 4
        for (int c = 0; c < 64; c++) {
            float4 w = *(const float4*)&sWbuf[c * 64 + j0];
            float h0 = t0p[c], h1 = t1p[c];
            A0[0] += h0 * w.x; A0[1] += h0 * w.y; A0[2] += h0 * w.z; A0[3] += h0 * w.w;
            A1[0] += h1 * w.x; A1[1] += h1 * w.y; A1[2] += h1 * w.z; A1[3] += h1 * w.w;
        }
        float* o0 = &sHC[ln0 * 64 + j0];
        float* o1 = &sHC[ln1 * 64 + j0];
        o0[0] = siluf(A0[0]); o0[1] = siluf(A0[1]); o0[2] = siluf(A0[2]); o0[3] = siluf(A0[3]);
        o1[0] = siluf(A1[0]); o1[1] = siluf(A1[1]); o1[2] = siluf(A1[2]); o1[3] = siluf(A1[3]);
    }
    __syncthreads();

    for (int i = tid; i < 24576; i += 256) sWbuf[i] = W_node1[i];
    __syncthreads();
    {
        float A0[4] = { sBn1[j0], sBn1[j0+1], sBn1[j0+2], sBn1[j0+3] };
        float A1[4] = { A0[0], A0[1], A0[2], A0[3] };
        const float* h0p = &sH[ln0 * 64];
        const float* h1p = &sH[ln1 * 64];
        #pragma unroll 4
        for (int c = 0; c < 64; c++) {
            float4 w = *(const float4*)&sWbuf[c * 64 + j0];
            float h0 = h0p[c], h1 = h1p[c];
            A0[0] += h0 * w.x; A0[1] += h0 * w.y; A0[2] += h0 * w.z; A0[3] += h0 * w.w;
            A1[0] += h1 * w.x; A1[1] += h1 * w.y; A1[2] += h1 * w.z; A1[3] += h1 * w.w;
        }
        const float* e0p = &sHE[ln0 * 256];
        const float* e1p = &sHE[ln1 * 256];
        #pragma unroll 4
        for (int c = 0; c < 256; c++) {
            float4 w = *(const float4*)&sWbuf[(64 + c) * 64 + j0];
            float h0 = e0p[c], h1 = e1p[c];
            A0[0] += h0 * w.x; A0[1] += h0 * w.y; A0[2] += h0 * w.z; A0[3] += h0 * w.w;
            A1[0] += h1 * w.x; A1[1] += h1 * w.y; A1[2] += h1 * w.z; A1[3] += h1 * w.w;
        }
        const float* q0p = &sHC[ln0 * 64];
        const float* q1p = &sHC[ln1 * 64];
        #pragma unroll 4
        for (int c = 0; c < 64; c++) {
            float4 w = *(const float4*)&sWbuf[(320 + c) * 64 + j0];
            float h0 = q0p[c], h1 = q1p[c];
            A0[0] += h0 * w.x; A0[1] += h0 * w.y; A0[2] += h0 * w.z; A0[3] += h0 * w.w;
            A1[0] += h1 * w.x; A1[1] += h1 * w.y; A1[2] += h1 * w.z; A1[3] += h1 * w.w;
        }
        float* o0 = &sT[ln0 * 64 + j0];
        float* o1 = &sT[ln1 * 64 + j0];
        o0[0] = siluf(A0[0]); o0[1] = siluf(A0[1]); o0[2] = siluf(A0[2]); o0[3] = siluf(A0[3]);
        o1[0] = siluf(A1[0]); o1[1] = siluf(A1[1]); o1[2] = siluf(A1[2]); o1[3] = siluf(A1[3]);
    }
    __syncthreads();

    for (int i = tid; i < 4096; i += 256) sWbuf[i] = W_node2[i];
    __syncthreads();
    {
        float A0[4] = { sBn2[j0], sBn2[j0+1], sBn2[j0+2], sBn2[j0+3] };
        float A1[4] = { A0[0], A0[1], A0[2], A0[3] };
        const float* t0p = &sT[ln0 * 64];
        const float* t1p = &sT[ln1 * 64];
        #pragma unroll 4
        for (int c = 0; c < 64; c++) {
            float4 w = *(const float4*)&sWbuf[c * 64 + j0];
            float h0 = t0p[c], h1 = t1p[c];
            A0[0] += h0 * w.x; A0[1] += h0 * w.y; A0[2] += h0 * w.z; A0[3] += h0 * w.w;
            A1[0] += h1 * w.x; A1[1] += h1 * w.y; A1[2] += h1 * w.z; A1[3] += h1 * w.w;
        }
        float r0[4], r1[4];
        #pragma unroll
        for (int q = 0; q < 4; q++) {
            r0[q] = sH[ln0 * 64 + j0 + q] + siluf(A0[q]);
            r1[q] = sH[ln1 * 64 + j0 + q] + siluf(A1[q]);
        }
        float* o0 = &sHN[ln0 * 64 + j0];
        float* o1 = &sHN[ln1 * 64 + j0];
        #pragma unroll
        for (int q = 0; q < 4; q++) { o0[q] = r0[q]; o1[q] = r1[q]; }
        if (ln0 < nn) *(float4*)&out_h[(n0 + ln0) * 64 + j0] = make_float4(r0[0], r0[1], r0[2], r0[3]);
        if (ln1 < nn) *(float4*)&out_h[(n0 + ln1) * 64 + j0] = make_float4(r1[0], r1[1], r1[2], r1[3]);
    }
    __syncthreads();

    for (int i = tid; i < 4096; i += 256) sWbuf[i] = W_vel1[i];
    __syncthreads();
    {
        float A0[4] = { sBv1[j0], sBv1[j0+1], sBv1[j0+2], sBv1[j0+3] };
        float A1[4] = { A0[0], A0[1], A0[2], A0[3] };
        const float* n0p = &sHN[ln0 * 64];
        const float* n1p = &sHN[ln1 * 64];
        #pragma unroll 4
        for (int c = 0; c < 64; c++) {
            float4 w = *(const float4*)&sWbuf[c * 64 + j0];
            float h0 = n0p[c], h1 = n1p[c];
            A0[0] += h0 * w.x; A0[1] += h0 * w.y; A0[2] += h0 * w.z; A0[3] += h0 * w.w;
            A1[0] += h1 * w.x; A1[1] += h1 * w.y; A1[2] += h1 * w.z; A1[3] += h1 * w.w;
        }
        float* o0 = &sT[ln0 * 64 + j0];
        float* o1 = &sT[ln1 * 64 + j0];
        #pragma unroll
        for (int q = 0; q < 4; q++) {
            o0[q] = siluf(A0[q]) * sWv2[j0 + q];
            o1[q] = siluf(A1[q]) * sWv2[j0 + q];
        }
    }
    __syncthreads();

    if (tid < nn) {
        int ln = tid;
        float s = 0.f;
        #pragma unroll 8
        for (int k = 0; k < 64; k++) s += sT[ln * 64 + k];
        float scale = 2.f / (1.f + __expf(-s));
        int n = n0 + ln;
        #pragma unroll
        for (int d = 0; d < 3; d++) {
            float vn = sDV[ln * 3 + d] + scale * v[n * 3 + d];
            out_v[n * 3 + d] = vn;
            out_x[n * 3 + d] = x[n * 3 + d] + vn;
        }
    }
}

// ---------------- launch ----------------
extern "C" void kernel_launch(void* const* d_in, const int* in_sizes, int n_in,
                              void* d_out, int out_size)
{
    const float* h        = (const float*)d_in[0];
    const float* x        = (const float*)d_in[1];
    const float* v        = (const float*)d_in[2];
    const int*   idxs     = (const int*)  d_in[3];
    const float* rbf_mean = (const float*)d_in[4];
    const float* rbf_beta = (const float*)d_in[5];
    const float* W_in     = (const float*)d_in[6];
    const float* b_in     = (const float*)d_in[7];
    const float* W_out1   = (const float*)d_in[8];
    const float* b_out1   = (const float*)d_in[9];
    const float* W_out2   = (const float*)d_in[10];
    const float* b_out2   = (const float*)d_in[11];
    const float* W_att    = (const float*)d_in[12];
    const float* b_att    = (const float*)d_in[13];
    const float* W_xmix   = (const float*)d_in[14];
    const float* W_post1  = (const float*)d_in[15];
    const float* b_post1  = (const float*)d_in[16];
    const float* W_post2  = (const float*)d_in[17];
    const float* b_post2  = (const float*)d_in[18];
    const float* W_node1  = (const float*)d_in[19];
    const float* b_node1  = (const float*)d_in[20];
    const float* W_node2  = (const float*)d_in[21];
    const float* b_node2  = (const float*)d_in[22];
    const float* W_vmix   = (const float*)d_in[23];
    const float* W_vel1   = (const float*)d_in[24];
    const float* b_vel1   = (const float*)d_in[25];
    const float* W_vel2   = (const float*)d_in[26];

    int N = in_sizes[0] / 64;
    int E = in_sizes[3] / 2;

    float* out  = (float*)d_out;
    float* outh = out;
    float* outx = out + (size_t)N * 64;
    float* outv = out + (size_t)N * 67;

    const int SM_NODE = (8192 * 2 + 2048 * 4 + 64 * 6 + 96 + 24 + 24576) * 4;

    cudaFuncSetAttribute(k_edge_mma, cudaFuncAttributeMaxDynamicSharedMemorySize, E_SMEM);
    cudaFuncSetAttribute(k_xagg,     cudaFuncAttributeMaxDynamicSharedMemorySize, XG_SMEM);
    cudaFuncSetAttribute(k_node,     cudaFuncAttributeMaxDynamicSharedMemorySize, SM_NODE);

    k_init<<<256, 256>>>(N, W_xmix, W_in, W_out1, W_out2);
    k_edge_mma<<<296, 256, E_SMEM>>>(h, x, idxs, rbf_mean, rbf_beta,
                                     b_in, b_out1, b_out2, W_att, b_att, E);
    k_scan<<<1, 1024>>>(N);
    k_fill<<<(E + 255) / 256, 256>>>(idxs, E);
    k_xagg<<<(E + 63) / 64, 256, XG_SMEM>>>(idxs, W_vmix, E);
    k_node<<<(N + 31) / 32, 256, SM_NODE>>>(h, x, v, W_vmix,
                                            W_post1, b_post1, W_post2, b_post2,
                                            W_node1, b_node1, W_node2, b_node2,
                                            W_vel1, b_vel1, W_vel2,
                                            outh, outx, outv, N);
}

// round 14
// speedup vs baseline: 1.0451x; 1.0451x over previous
#include <cuda_runtime.h>
#include <cuda_fp16.h>
#include <stdint.h>
#include <math.h>

#define NMAX 10000
#define EMAX 160000
#define NBLK ((EMAX + 63) / 64)

// ---------------- scratch ----------------
__device__ float g_hemtx[EMAX * 64];
__device__ float g_xhat[EMAX * 3];
__device__ float g_w[EMAX * 4];
__device__ float g_expsum[NMAX * 4];
__device__ int   g_counts[NMAX];
__device__ int   g_off[NMAX + 1];
__device__ int   g_cursor[NMAX];
__device__ int   g_eid[EMAX];
__device__ float g_he[NMAX * 256];
__device__ float g_cnorm[NMAX * 256];
__device__ float g_dv[NMAX * 3];
__device__ float g_phe[NBLK * 2 * 256];
__device__ float g_pcomb[NBLK * 2 * 3 * 256];
__device__ __half g_wx[256 * 256];           // W_xmix^T fp16 [n][k]
__device__ uint32_t g_ewi[4096];
__device__ uint32_t g_ew1a[4096];
__device__ uint32_t g_ew1b[2048];
__device__ uint32_t g_ew2[2048];

__device__ __forceinline__ float siluf(float x) { return x / (1.f + __expf(-x)); }
__device__ __forceinline__ float fast_tanh(float x) {
    float y; asm("tanh.approx.f32 %0, %1;" : "=f"(y) : "f"(x)); return y;
}
__device__ __forceinline__ void mma16816h(float* d, const uint32_t* a, const uint32_t* b) {
    asm volatile("mma.sync.aligned.m16n8k16.row.col.f32.f16.f16.f32 "
        "{%0,%1,%2,%3}, {%4,%5,%6,%7}, {%8,%9}, {%0,%1,%2,%3};"
        : "+f"(d[0]), "+f"(d[1]), "+f"(d[2]), "+f"(d[3])
        : "r"(a[0]), "r"(a[1]), "r"(a[2]), "r"(a[3]), "r"(b[0]), "r"(b[1]));
}
__device__ __forceinline__ uint32_t pack2h(float a, float b) {
    __half2 p = __floats2half2_rn(a, b);
    return *(uint32_t*)&p;
}
__device__ __forceinline__ uint32_t smem_u32(const void* p) {
    uint32_t a;
    asm("{ .reg .u64 t; cvta.to.shared.u64 t, %1; cvt.u32.u64 %0, t; }" : "=r"(a) : "l"(p));
    return a;
}
#define LDSM4(r0, r1, r2, r3, addr) \
    asm volatile("ldmatrix.sync.aligned.m8n8.x4.shared.b16 {%0,%1,%2,%3}, [%4];" \
        : "=r"(r0), "=r"(r1), "=r"(r2), "=r"(r3) : "r"(addr))
#define CP_ASYNC16(dst, src) \
    asm volatile("cp.async.cg.shared.global [%0], [%1], 16;" :: "r"(dst), "l"(src) : "memory")
#define CP_COMMIT() asm volatile("cp.async.commit_group;" ::: "memory")
#define CP_WAIT0()  asm volatile("cp.async.wait_group 0;" ::: "memory")

// ---------------- K0: init + weight prep ----------------
__global__ void k_init(int N,
                       const float* __restrict__ W_xmix,
                       const float* __restrict__ W_in,
                       const float* __restrict__ W_out1,
                       const float* __restrict__ W_out2) {
    int i = blockIdx.x * blockDim.x + threadIdx.x;
    if (i < N * 4) g_expsum[i] = 0.f;
    if (i < N) g_counts[i] = 0;
    if (i < 65536) {
        int n = i >> 8, k = i & 255;
        g_wx[n * 256 + k] = __float2half_rn(W_xmix[k * 256 + n]);
    }
    if (i < 4096) {
        int n = i >> 6, k0 = (i & 63) * 2;
        float w0 = (n < 50) ? W_in[k0 * 50 + n] : 0.f;
        float w1 = (n < 50) ? W_in[(k0 + 1) * 50 + n] : 0.f;
        g_ewi[i] = pack2h(w0, w1);
    } else if (i < 8192) {
        int j = i - 4096;
        int n = j >> 6, k0 = (j & 63) * 2;
        g_ew1a[j] = pack2h(W_out1[k0 * 64 + n], W_out1[(k0 + 1) * 64 + n]);
    } else if (i < 10240) {
        int j = i - 8192;
        int n = j >> 5, k0 = (j & 31) * 2;
        float w0 = (k0 < 50) ? W_out1[(128 + k0) * 64 + n] : ((k0 == 50) ? W_out1[178 * 64 + n] : 0.f);
        int k1 = k0 + 1;
        float w1 = (k1 < 50) ? W_out1[(128 + k1) * 64 + n] : ((k1 == 50) ? W_out1[178 * 64 + n] : 0.f);
        g_ew1b[j] = pack2h(w0, w1);
    } else if (i < 12288) {
        int j = i - 10240;
        int n = j >> 5, k0 = (j & 31) * 2;
        g_ew2[j] = pack2h(W_out2[k0 * 64 + n], W_out2[(k0 + 1) * 64 + n]);
    }
}

// ---------------- K1: edge MLP via fp16 mma.sync + ldmatrix (fused exp/expsum) ----------------
#define O_A     0
#define O_X     4352
#define O_M     6656
#define O_WI    8960
#define O_W1A   13312
#define O_W1B   17664
#define O_W2    19968
#define O_HE    22272
#define O_BIN   26496
#define O_BO1   26560
#define O_BO2   26624
#define O_MEAN  26688
#define O_BETA  26752
#define O_WA    26816
#define O_BA    27072
#define O_NORM  27076
#define O_EX    27140
#define O_XHT   27204
#define E_SMEM  (27400 * 4)

__global__ void __launch_bounds__(256, 2)
k_edge_mma(const float* __restrict__ h, const float* __restrict__ x,
           const int* __restrict__ idxs,
           const float* __restrict__ rbf_means, const float* __restrict__ rbf_betas,
           const float* __restrict__ b_in, const float* __restrict__ b_out1,
           const float* __restrict__ b_out2,
           const float* __restrict__ W_att, const float* __restrict__ b_att, int E)
{
    extern __shared__ uint32_t su[];
    float* sf = (float*)su;
    int tid = threadIdx.x, lid = tid & 31, wid = tid >> 5;
    int g = lid >> 2, tg = lid & 3;
    int mrow = (wid & 3) * 16, ncol = (wid >> 2) * 32;

    for (int i = tid; i < 4096; i += 256) {
        int n = i >> 6, kk = i & 63;
        su[O_WI  + n * 68 + kk] = g_ewi[i];
        su[O_W1A + n * 68 + kk] = g_ew1a[i];
    }
    for (int i = tid; i < 2048; i += 256) {
        int n = i >> 5, kk = i & 31;
        su[O_W1B + n * 36 + kk] = g_ew1b[i];
        su[O_W2  + n * 36 + kk] = g_ew2[i];
    }
    if (tid < 64) {
        sf[O_BIN + tid]  = (tid < 50) ? b_in[tid] : 0.f;
        sf[O_BO1 + tid]  = b_out1[tid];
        sf[O_BO2 + tid]  = b_out2[tid];
        sf[O_MEAN + tid] = (tid < 50) ? rbf_means[tid] : 0.f;
        sf[O_BETA + tid] = (tid < 50) ? rbf_betas[tid] : 1.f;
    }
    if (tid < 256) sf[O_WA + tid] = W_att[tid];
    if (tid < 4)   sf[O_BA + tid] = b_att[tid];
    __syncthreads();

    uint32_t sbase = smem_u32(su);
    int mq = lid >> 3, rr = lid & 7;
    int rA = mrow + (mq & 1) * 8 + rr;
    int cA = (mq >> 1) * 4;
    uint32_t adA  = sbase + (O_A  + rA * 68 + cA) * 4;
    uint32_t adX  = sbase + (O_X  + rA * 36 + cA) * 4;
    uint32_t adM  = sbase + (O_M  + rA * 36 + cA) * 4;
    int rB = (mq >> 1) * 8 + rr;
    int cB = (mq & 1) * 4;
    uint32_t adWI0  = sbase + (O_WI  + (ncol + rB) * 68 + cB) * 4;
    uint32_t adWI1  = sbase + (O_WI  + (ncol + 16 + rB) * 68 + cB) * 4;
    uint32_t adW1A0 = sbase + (O_W1A + (ncol + rB) * 68 + cB) * 4;
    uint32_t adW1A1 = sbase + (O_W1A + (ncol + 16 + rB) * 68 + cB) * 4;
    uint32_t adW1B0 = sbase + (O_W1B + (ncol + rB) * 36 + cB) * 4;
    uint32_t adW1B1 = sbase + (O_W1B + (ncol + 16 + rB) * 36 + cB) * 4;
    uint32_t adW20  = sbase + (O_W2  + (ncol + rB) * 36 + cB) * 4;
    uint32_t adW21  = sbase + (O_W2  + (ncol + 16 + rB) * 36 + cB) * 4;

    int ntiles = (E + 63) / 64;
    for (int tile = blockIdx.x; tile < ntiles; tile += gridDim.x) {
        int e0 = tile * 64, ne = min(64, E - e0);

        if (tid < 64) {
            float nrm = 0.f, xh0 = 0.f, xh1 = 0.f, xh2 = 0.f;
            if (tid < ne) {
                int s = idxs[2 * (e0 + tid)], d = idxs[2 * (e0 + tid) + 1];
                float dx = x[3 * s]     - x[3 * d];
                float dy = x[3 * s + 1] - x[3 * d + 1];
                float dz = x[3 * s + 2] - x[3 * d + 2];
                nrm = sqrtf(dx * dx + dy * dy + dz * dz + 1e-14f);
                float inv = 1.f / (nrm + 1e-5f);
                xh0 = dx * inv; xh1 = dy * inv; xh2 = dz * inv;
                atomicAdd(&g_counts[s], 1);
            }
            sf[O_NORM + tid] = nrm;
            sf[O_EX + tid]   = __expf(-nrm);
            sf[O_XHT + tid * 3] = xh0; sf[O_XHT + tid * 3 + 1] = xh1; sf[O_XHT + tid * 3 + 2] = xh2;
        }
        {
            int el = tid >> 2, part = tid & 3;
            uint32_t hb[16];
            if (el < ne) {
                int node = idxs[2 * (e0 + el) + (part >> 1)];
                const float4* hp = (const float4*)&h[node * 64 + (part & 1) * 32];
                #pragma unroll
                for (int i2 = 0; i2 < 8; i2++) {
                    float4 v = hp[i2];
                    hb[i2 * 2]     = pack2h(v.x, v.y);
                    hb[i2 * 2 + 1] = pack2h(v.z, v.w);
                }
            } else {
                #pragma unroll
                for (int i2 = 0; i2 < 16; i2++) hb[i2] = 0u;
            }
            uint4* dh = (uint4*)&su[O_A + el * 68 + part * 16];
            #pragma unroll
            for (int i2 = 0; i2 < 4; i2++)
                dh[i2] = make_uint4(hb[i2*4], hb[i2*4+1], hb[i2*4+2], hb[i2*4+3]);
        }
        __syncthreads();

        float acc[4][4];

        // ---- G1 ----
        #pragma unroll
        for (int nt = 0; nt < 4; nt++)
            #pragma unroll
            for (int q = 0; q < 4; q++) acc[nt][q] = 0.f;
        #pragma unroll
        for (int ks = 0; ks < 8; ks++) {
            uint32_t aH[4];
            LDSM4(aH[0], aH[1], aH[2], aH[3], adA + ks * 32);
            uint32_t b0, b1, b2, b3;
            LDSM4(b0, b1, b2, b3, adWI0 + ks * 32);
            { uint32_t bb[2] = { b0, b1 }; mma16816h(acc[0], aH, bb); }
            { uint32_t bb[2] = { b2, b3 }; mma16816h(acc[1], aH, bb); }
            LDSM4(b0, b1, b2, b3, adWI1 + ks * 32);
            { uint32_t bb[2] = { b0, b1 }; mma16816h(acc[2], aH, bb); }
            { uint32_t bb[2] = { b2, b3 }; mma16816h(acc[3], aH, bb); }
        }
        #pragma unroll
        for (int nt = 0; nt < 4; nt++) {
            #pragma unroll
            for (int hh = 0; hh < 2; hh++) {
                int row = mrow + g + hh * 8;
                int c0 = ncol + nt * 8 + tg * 2;
                float v0 = acc[nt][hh * 2]     + sf[O_BIN + c0];
                float v1 = acc[nt][hh * 2 + 1] + sf[O_BIN + c0 + 1];
                float ex = sf[O_EX + row];
                float x0, x1;
                if (c0 < 50) { float d = ex - sf[O_MEAN + c0]; x0 = __expf(-sf[O_BETA + c0] * d * d) * v0; }
                else x0 = (c0 == 50) ? sf[O_NORM + row] : 0.f;
                if (c0 + 1 < 50) { float d = ex - sf[O_MEAN + c0 + 1]; x1 = __expf(-sf[O_BETA + c0 + 1] * d * d) * v1; }
                else x1 = 0.f;
                su[O_X + row * 36 + (c0 >> 1)] = pack2h(x0, x1);
            }
        }
        __syncthreads();

        // ---- G2 ----
        #pragma unroll
        for (int nt = 0; nt < 4; nt++)
            #pragma unroll
            for (int q = 0; q < 4; q++) acc[nt][q] = 0.f;
        #pragma unroll
        for (int ks = 0; ks < 8; ks++) {
            uint32_t aH[4];
            LDSM4(aH[0], aH[1], aH[2], aH[3], adA + ks * 32);
            uint32_t b0, b1, b2, b3;
            LDSM4(b0, b1, b2, b3, adW1A0 + ks * 32);
            { uint32_t bb[2] = { b0, b1 }; mma16816h(acc[0], aH, bb); }
            { uint32_t bb[2] = { b2, b3 }; mma16816h(acc[1], aH, bb); }
            LDSM4(b0, b1, b2, b3, adW1A1 + ks * 32);
            { uint32_t bb[2] = { b0, b1 }; mma16816h(acc[2], aH, bb); }
            { uint32_t bb[2] = { b2, b3 }; mma16816h(acc[3], aH, bb); }
        }
        #pragma unroll
        for (int ks = 0; ks < 4; ks++) {
            uint32_t aH[4];
            LDSM4(aH[0], aH[1], aH[2], aH[3], adX + ks * 32);
            uint32_t b0, b1, b2, b3;
            LDSM4(b0, b1, b2, b3, adW1B0 + ks * 32);
            { uint32_t bb[2] = { b0, b1 }; mma16816h(acc[0], aH, bb); }
            { uint32_t bb[2] = { b2, b3 }; mma16816h(acc[1], aH, bb); }
            LDSM4(b0, b1, b2, b3, adW1B1 + ks * 32);
            { uint32_t bb[2] = { b0, b1 }; mma16816h(acc[2], aH, bb); }
            { uint32_t bb[2] = { b2, b3 }; mma16816h(acc[3], aH, bb); }
        }
        #pragma unroll
        for (int nt = 0; nt < 4; nt++) {
            #pragma unroll
            for (int hh = 0; hh < 2; hh++) {
                int row = mrow + g + hh * 8;
                int c0 = ncol + nt * 8 + tg * 2;
                float m0 = siluf(acc[nt][hh * 2]     + sf[O_BO1 + c0]);
                float m1 = siluf(acc[nt][hh * 2 + 1] + sf[O_BO1 + c0 + 1]);
                su[O_M + row * 36 + (c0 >> 1)] = pack2h(m0, m1);
            }
        }
        __syncthreads();

        // ---- G3 ----
        #pragma unroll
        for (int nt = 0; nt < 4; nt++)
            #pragma unroll
            for (int q = 0; q < 4; q++) acc[nt][q] = 0.f;
        #pragma unroll
        for (int ks = 0; ks < 4; ks++) {
            uint32_t aH[4];
            LDSM4(aH[0], aH[1], aH[2], aH[3], adM + ks * 32);
            uint32_t b0, b1, b2, b3;
            LDSM4(b0, b1, b2, b3, adW20 + ks * 32);
            { uint32_t bb[2] = { b0, b1 }; mma16816h(acc[0], aH, bb); }
            { uint32_t bb[2] = { b2, b3 }; mma16816h(acc[1], aH, bb); }
            LDSM4(b0, b1, b2, b3, adW21 + ks * 32);
            { uint32_t bb[2] = { b0, b1 }; mma16816h(acc[2], aH, bb); }
            { uint32_t bb[2] = { b2, b3 }; mma16816h(acc[3], aH, bb); }
        }
        #pragma unroll
        for (int nt = 0; nt < 4; nt++) {
            #pragma unroll
            for (int hh = 0; hh < 2; hh++) {
                int row = mrow + g + hh * 8;
                int c0 = ncol + nt * 8 + tg * 2;
                sf[O_HE + row * 66 + c0]     = acc[nt][hh * 2]     + sf[O_BO2 + c0];
                sf[O_HE + row * 66 + c0 + 1] = acc[nt][hh * 2 + 1] + sf[O_BO2 + c0 + 1];
            }
        }
        __syncthreads();

        // att: logits -> exp -> g_w, expsum (no max shift)
        {
            int el = tid >> 2, a = tid & 3;
            if (el < ne) {
                float acc2 = sf[O_BA + a];
                const float* hv = &sf[O_HE + el * 66];
                #pragma unroll 8
                for (int c = 0; c < 64; c++) acc2 += hv[c] * sf[O_WA + c * 4 + a];
                float lg = (acc2 > 0.f) ? acc2 : 2.f * (__expf(acc2 * 0.5f) - 1.f);
                float w = __expf(lg);
                int s = idxs[2 * (e0 + el)];
                g_w[(e0 + el) * 4 + a] = w;
                atomicAdd(&g_expsum[s * 4 + a], w);
            }
        }
        for (int i = tid; i < ne * 16; i += 256) {
            int el = i >> 4, c = (i & 15) * 4;
            float4 o = make_float4(sf[O_HE + el * 66 + c], sf[O_HE + el * 66 + c + 1],
                                   sf[O_HE + el * 66 + c + 2], sf[O_HE + el * 66 + c + 3]);
            *(float4*)&g_hemtx[(size_t)(e0 + el) * 64 + c] = o;
        }
        for (int i = tid; i < ne * 3; i += 256) g_xhat[e0 * 3 + i] = sf[O_XHT + i];
        __syncthreads();
    }
}

// ---------------- K2: exclusive scan (shuffle-based) ----------------
__global__ void k_scan(int N) {
    __shared__ int wsum[32];
    int t = threadIdx.x, lane = t & 31, w = t >> 5;
    int chunk = (N + 1023) / 1024;
    int base = t * chunk;
    int vals[16];
    int loc = 0;
    for (int k = 0; k < chunk; k++) {
        int idx = base + k;
        int v = (idx < N) ? g_counts[idx] : 0;
        vals[k] = loc; loc += v;
    }
    int inc = loc;
    #pragma unroll
    for (int o = 1; o < 32; o <<= 1) {
        int v = __shfl_up_sync(0xFFFFFFFFu, inc, o);
        if (lane >= o) inc += v;
    }
    if (lane == 31) wsum[w] = inc;
    __syncthreads();
    if (w == 0) {
        int v2 = wsum[lane];
        int i2 = v2;
        #pragma unroll
        for (int o = 1; o < 32; o <<= 1) {
            int x2 = __shfl_up_sync(0xFFFFFFFFu, i2, o);
            if (lane >= o) i2 += x2;
        }
        wsum[lane] = i2 - v2;
    }
    __syncthreads();
    int excl = wsum[w] + (inc - loc);
    for (int k = 0; k < chunk; k++) {
        int idx = base + k;
        if (idx < N) { g_off[idx] = excl + vals[k]; g_cursor[idx] = excl + vals[k]; }
    }
    if (t == 1023) g_off[N] = excl + loc;
}

// ---------------- K3: CSR fill (pure) ----------------
__global__ void k_fill(const int* __restrict__ idxs, int E) {
    int e = blockIdx.x * blockDim.x + threadIdx.x;
    if (e >= E) return;
    int s = idxs[2 * e];
    int p = atomicAdd(&g_cursor[s], 1);
    g_eid[p] = e;
}

// ---------------- K5: fused xmix GEMM + aggregation (cp.async double-buffered W) ----------------
#define XG_A    0
#define XG_W0   8448
#define XG_W1   17664
#define XG_XH   26880
#define XG_NODE 27072
#define XG_WV   27136
#define XG_RED  27392
#define XG_SMEM (27420 * 4)

__global__ void __launch_bounds__(256, 2)
k_xagg(const int* __restrict__ idxs, const float* __restrict__ W_vmix, int E)
{
    extern __shared__ uint32_t su[];
    float* sf = (float*)su;
    int tid = threadIdx.x, lid = tid & 31, wid = tid >> 5;
    int p0 = blockIdx.x * 64;
    uint32_t* pA = su + XG_A;
    uint32_t* pC = su + XG_W0;
    int* sN = (int*)(su + XG_NODE);
    uint32_t sbase = smem_u32(su);

    {
        uint32_t dst = sbase + (XG_W0 + tid * 36) * 4;
        const char* src = (const char*)&g_wx[tid * 256];
        #pragma unroll
        for (int i = 0; i < 9; i++) CP_ASYNC16(dst + i * 16, src + i * 16);
        CP_COMMIT();
    }

    {
        int sl = tid & 63, kq = tid >> 6;
        int e = -1, s = -1;
        float att[4], hm[16];
        int p = p0 + sl;
        if (p < E) {
            e = g_eid[p];
            s = idxs[2 * e];
            #pragma unroll
            for (int a = 0; a < 4; a++) att[a] = g_w[e * 4 + a] / g_expsum[s * 4 + a];
            const float4* hp = (const float4*)&g_hemtx[(size_t)e * 64 + kq * 16];
            #pragma unroll
            for (int i = 0; i < 4; i++) {
                float4 v = hp[i];
                hm[i * 4] = v.x; hm[i * 4 + 1] = v.y; hm[i * 4 + 2] = v.z; hm[i * 4 + 3] = v.w;
            }
        } else {
            #pragma unroll
            for (int a = 0; a < 4; a++) att[a] = 0.f;
            #pragma unroll
            for (int i = 0; i < 16; i++) hm[i] = 0.f;
        }
        if (kq == 0) {
            sN[sl] = s;
            float x0 = 0.f, x1 = 0.f, x2 = 0.f;
            if (e >= 0) { x0 = g_xhat[e * 3]; x1 = g_xhat[e * 3 + 1]; x2 = g_xhat[e * 3 + 2]; }
            sf[XG_XH + sl * 3] = x0; sf[XG_XH + sl * 3 + 1] = x1; sf[XG_XH + sl * 3 + 2] = x2;
        }
        #pragma unroll
        for (int j = 0; j < 32; j++) {
            int kl = 2 * j;
            float m = hm[kl >> 2];
            pA[sl * 132 + ((kq * 64 + kl) >> 1)] = pack2h(m * att[kl & 3], m * att[(kl + 1) & 3]);
        }
        sf[XG_WV + tid] = W_vmix[tid];
    }
    CP_WAIT0();
    __syncthreads();

    int g = lid >> 2, tg = lid & 3;
    int mrow = (wid & 1) * 32;
    int ncol = (wid >> 1) * 64;

    int mq = lid >> 3, rr = lid & 7;
    uint32_t adA0 = sbase + (XG_A + (mrow + (mq & 1) * 8 + rr) * 132 + (mq >> 1) * 4) * 4;
    uint32_t adA1 = adA0 + 16 * 132 * 4;
    int rB = (mq >> 1) * 8 + rr;
    int cB = (mq & 1) * 4;
    uint32_t adW0 = sbase + (XG_W0 + (ncol + rB) * 36 + cB) * 4;
    uint32_t adW1 = adW0 + 16 * 36 * 4;
    uint32_t adW2 = adW0 + 32 * 36 * 4;
    uint32_t adW3 = adW0 + 48 * 36 * 4;
    const uint32_t BUFD = (XG_W1 - XG_W0) * 4;

    float acc[2][8][4];
    #pragma unroll
    for (int mt = 0; mt < 2; mt++)
        #pragma unroll
        for (int nt = 0; nt < 8; nt++)
            #pragma unroll
            for (int q = 0; q < 4; q++) acc[mt][nt][q] = 0.f;

    #pragma unroll
    for (int kc = 0; kc < 4; kc++) {
        if (kc < 3) {
            uint32_t dst = sbase + ((((kc + 1) & 1) ? XG_W1 : XG_W0) + tid * 36) * 4;
            const char* src = (const char*)&g_wx[tid * 256 + (kc + 1) * 64];
            #pragma unroll
            for (int i = 0; i < 9; i++) CP_ASYNC16(dst + i * 16, src + i * 16);
            CP_COMMIT();
        }
        uint32_t boff = (kc & 1) ? BUFD : 0u;
        #pragma unroll
        for (int ks = 0; ks < 4; ks++) {
            uint32_t aoff = kc * 128 + ks * 32;
            uint32_t aH[2][4];
            LDSM4(aH[0][0], aH[0][1], aH[0][2], aH[0][3], adA0 + aoff);
            LDSM4(aH[1][0], aH[1][1], aH[1][2], aH[1][3], adA1 + aoff);
            uint32_t woff = boff + ks * 32;
            uint32_t b0, b1, b2, b3;
            #define XAGG_PAIR(ADDR, NT) \
                LDSM4(b0, b1, b2, b3, (ADDR) + woff); \
                { uint32_t bb[2] = { b0, b1 }; mma16816h(acc[0][NT], aH[0], bb); mma16816h(acc[1][NT], aH[1], bb); } \
                { uint32_t bb[2] = { b2, b3 }; mma16816h(acc[0][(NT)+1], aH[0], bb); mma16816h(acc[1][(NT)+1], aH[1], bb); }
            XAGG_PAIR(adW0, 0)
            XAGG_PAIR(adW1, 2)
            XAGG_PAIR(adW2, 4)
            XAGG_PAIR(adW3, 6)
            #undef XAGG_PAIR
        }
        if (kc < 3) {
            CP_WAIT0();
            __syncthreads();
        }
    }

    #pragma unroll
    for (int mt = 0; mt < 2; mt++)
        #pragma unroll
        for (int nt = 0; nt < 8; nt++) {
            int rl = mrow + mt * 16 + g;
            int col = ncol + nt * 8 + tg * 2;
            float* a = acc[mt][nt];
            pC[rl * 132 + (col >> 1)]       = pack2h(fast_tanh(a[0]), fast_tanh(a[1]));
            pC[(rl + 8) * 132 + (col >> 1)] = pack2h(fast_tanh(a[2]), fast_tanh(a[3]));
        }
    __syncthreads();

    {
        int c = tid;
        int blk = blockIdx.x;
        float wv = sf[XG_WV + c];
        float accH = 0.f, a0 = 0.f, a1 = 0.f, a2 = 0.f;
        int segStart = 0;
        for (int sl = 0; sl < 64; sl++) {
            int n = sN[sl];
            if (n >= 0) {
                uint32_t ap = pA[sl * 132 + (c >> 1)];
                __half2 av2 = *(__half2*)&ap;
                float Av = (c & 1) ? __high2float(av2) : __low2float(av2);
                accH += Av;
                uint32_t cp = pC[sl * 132 + (c >> 1)];
                __half2 h2 = *(__half2*)&cp;
                float cf = (c & 1) ? __high2float(h2) : __low2float(h2);
                a0 += cf * sf[XG_XH + sl * 3];
                a1 += cf * sf[XG_XH + sl * 3 + 1];
                a2 += cf * sf[XG_XH + sl * 3 + 2];
            }
            bool segEnd = (sl == 63) || (sN[sl + 1] != n);
            if (segEnd) {
                if (n >= 0) {
                    int beg = g_off[n], end = g_off[n + 1];
                    bool full = (beg == p0 + segStart) && (end == p0 + sl + 1);
                    if (full) {
                        float invc = 1.f / ((float)(end - beg) + 1.f);
                        g_he[n * 256 + c] = accH;
                        float s0 = a0 * invc, s1 = a1 * invc, s2 = a2 * invc;
                        g_cnorm[n * 256 + c] = s0 * s0 + s1 * s1 + s2 * s2;
                        float r0 = wv * s0, r1 = wv * s1, r2 = wv * s2;
                        #pragma unroll
                        for (int o = 16; o > 0; o >>= 1) {
                            r0 += __shfl_xor_sync(0xFFFFFFFFu, r0, o);
                            r1 += __shfl_xor_sync(0xFFFFFFFFu, r1, o);
                            r2 += __shfl_xor_sync(0xFFFFFFFFu, r2, o);
                        }
                        if (lid == 0) {
                            sf[XG_RED + wid * 3]     = r0;
                            sf[XG_RED + wid * 3 + 1] = r1;
                            sf[XG_RED + wid * 3 + 2] = r2;
                        }
                        __syncthreads();
                        if (c < 3) {
                            float s = 0.f;
                            #pragma unroll
                            for (int w = 0; w < 8; w++) s += sf[XG_RED + w * 3 + c];
                            g_dv[n * 3 + c] = s;
                        }
                        __syncthreads();
                    } else {
                        int slot = (segStart == 0) ? 0 : 1;
                        g_phe[((size_t)blk * 2 + slot) * 256 + c] = accH;
                        g_pcomb[(((size_t)blk * 2 + slot) * 3 + 0) * 256 + c] = a0;
                        g_pcomb[(((size_t)blk * 2 + slot) * 3 + 1) * 256 + c] = a1;
                        g_pcomb[(((size_t)blk * 2 + slot) * 3 + 2) * 256 + c] = a2;
                    }
                }
                accH = 0.f; a0 = 0.f; a1 = 0.f; a2 = 0.f;
                segStart = sl + 1;
            }
        }
    }
}

// ---------------- K_fin: finish boundary + empty nodes ----------------
__global__ void k_fin(const float* __restrict__ W_vmix, int N) {
    __shared__ float red[24];
    int n = blockIdx.x;
    int c = threadIdx.x, lid = c & 31, wid = c >> 5;
    int beg = g_off[n], end = g_off[n + 1];
    if (end == beg) {
        g_he[n * 256 + c] = 0.f;
        g_cnorm[n * 256 + c] = 0.f;
        if (c < 3) g_dv[n * 3 + c] = 0.f;
        return;
    }
    int b0 = beg >> 6, b1 = (end - 1) >> 6;
    if (b0 == b1) return;

    float accH = 0.f, a0 = 0.f, a1 = 0.f, a2 = 0.f;
    for (int b = b0; b <= b1; b++) {
        int slot = (b == b0 && (beg & 63) != 0) ? 1 : 0;
        size_t base = ((size_t)b * 2 + slot);
        accH += g_phe[base * 256 + c];
        a0 += g_pcomb[(base * 3 + 0) * 256 + c];
        a1 += g_pcomb[(base * 3 + 1) * 256 + c];
        a2 += g_pcomb[(base * 3 + 2) * 256 + c];
    }
    g_he[n * 256 + c] = accH;
    float invc = 1.f / ((float)(end - beg) + 1.f);
    float s0 = a0 * invc, s1 = a1 * invc, s2 = a2 * invc;
    g_cnorm[n * 256 + c] = s0 * s0 + s1 * s1 + s2 * s2;
    float wv = W_vmix[c];
    float r0 = wv * s0, r1 = wv * s1, r2 = wv * s2;
    #pragma unroll
    for (int o = 16; o > 0; o >>= 1) {
        r0 += __shfl_xor_sync(0xFFFFFFFFu, r0, o);
        r1 += __shfl_xor_sync(0xFFFFFFFFu, r1, o);
        r2 += __shfl_xor_sync(0xFFFFFFFFu, r2, o);
    }
    if (lid == 0) { red[wid * 3] = r0; red[wid * 3 + 1] = r1; red[wid * 3 + 2] = r2; }
    __syncthreads();
    if (c < 3) {
        float s = 0.f;
        #pragma unroll
        for (int w = 0; w < 8; w++) s += red[w * 3 + c];
        g_dv[n * 3 + c] = s;
    }
}

// ---------------- K7: node MLPs (2-row x 4-col register blocking) ----------------
__global__ void k_node(const float* __restrict__ h, const float* __restrict__ x,
                       const float* __restrict__ v,
                       const float* __restrict__ W_post1, const float* __restrict__ b_post1,
                       const float* __restrict__ W_post2, const float* __restrict__ b_post2,
                       const float* __restrict__ W_node1, const float* __restrict__ b_node1,
                       const float* __restrict__ W_node2, const float* __restrict__ b_node2,
                       const float* __restrict__ W_vel1,  const float* __restrict__ b_vel1,
                       const float* __restrict__ W_vel2,
                       float* __restrict__ out_h, float* __restrict__ out_x,
                       float* __restrict__ out_v, int N)
{
    extern __shared__ float sm[];
    float* sCN = sm;
    float* sHE = sCN + 8192;
    float* sH  = sHE + 8192;
    float* sT  = sH  + 2048;
    float* sHC = sT  + 2048;
    float* sHN = sHC + 2048;
    float* sBp1 = sHN + 2048;
    float* sBp2 = sBp1 + 64;
    float* sBn1 = sBp2 + 64;
    float* sBn2 = sBn1 + 64;
    float* sBv1 = sBn2 + 64;
    float* sWv2 = sBv1 + 64;
    float* sWbuf = sWv2 + 64;

    int tid = threadIdx.x;
    int n0 = blockIdx.x * 32;
    int nn = min(32, N - n0);

    for (int i = tid; i < 8192; i += 256) {
        sCN[i] = (i < nn * 256) ? g_cnorm[n0 * 256 + i] : 0.f;
        sHE[i] = (i < nn * 256) ? g_he[n0 * 256 + i] : 0.f;
    }
    for (int i = tid; i < 2048; i += 256) sH[i] = (i < nn * 64) ? h[n0 * 64 + i] : 0.f;
    if (tid < 64) {
        sBp1[tid] = b_post1[tid]; sBp2[tid] = b_post2[tid];
        sBn1[tid] = b_node1[tid]; sBn2[tid] = b_node2[tid];
        sBv1[tid] = b_vel1[tid];  sWv2[tid] = W_vel2[tid];
    }
    __syncthreads();

    int gq = tid >> 4;
    int j0 = (tid & 15) * 4;
    int ln0 = gq * 2, ln1 = ln0 + 1;

    for (int i = tid; i < 16384; i += 256) sWbuf[i] = W_post1[i];
    __syncthreads();
    {
        float A0[4] = { sBp1[j0], sBp1[j0+1], sBp1[j0+2], sBp1[j0+3] };
        float A1[4] = { A0[0], A0[1], A0[2], A0[3] };
        const float* c0p = &sCN[ln0 * 256];
        const float* c1p = &sCN[ln1 * 256];
        #pragma unroll 4
        for (int c = 0; c < 256; c++) {
            float4 w = *(const float4*)&sWbuf[c * 64 + j0];
            float h0 = c0p[c], h1 = c1p[c];
            A0[0] += h0 * w.x; A0[1] += h0 * w.y; A0[2] += h0 * w.z; A0[3] += h0 * w.w;
            A1[0] += h1 * w.x; A1[1] += h1 * w.y; A1[2] += h1 * w.z; A1[3] += h1 * w.w;
        }
        float* o0 = &sT[ln0 * 64 + j0];
        float* o1 = &sT[ln1 * 64 + j0];
        o0[0] = siluf(A0[0]); o0[1] = siluf(A0[1]); o0[2] = siluf(A0[2]); o0[3] = siluf(A0[3]);
        o1[0] = siluf(A1[0]); o1[1] = siluf(A1[1]); o1[2] = siluf(A1[2]); o1[3] = siluf(A1[3]);
    }
    __syncthreads();

    for (int i = tid; i < 4096; i += 256) sWbuf[i] = W_post2[i];
    __syncthreads();
    {
        float A0[4] = { sBp2[j0], sBp2[j0+1], sBp2[j0+2], sBp2[j0+3] };
        float A1[4] = { A0[0], A0[1], A0[2], A0[3] };
        const float* t0p = &sT[ln0 * 64];
        const float* t1p = &sT[ln1 * 64];
        #pragma unroll 4
        for (int c = 0; c < 64; c++) {
            float4 w = *(const float4*)&sWbuf[c * 64 + j0];
            float h0 = t0p[c], h1 = t1p[c];
            A0[0] += h0 * w.x; A0[1] += h0 * w.y; A0[2] += h0 * w.z; A0[3] += h0 * w.w;
            A1[0] += h1 * w.x; A1[1] += h1 * w.y; A1[2] += h1 * w.z; A1[3] += h1 * w.w;
        }
        float* o0 = &sHC[ln0 * 64 + j0];
        float* o1 = &sHC[ln1 * 64 + j0];
        o0[0] = siluf(A0[0]); o0[1] = siluf(A0[1]); o0[2] = siluf(A0[2]); o0[3] = siluf(A0[3]);
        o1[0] = siluf(A1[0]); o1[1] = siluf(A1[1]); o1[2] = siluf(A1[2]); o1[3] = siluf(A1[3]);
    }
    __syncthreads();

    for (int i = tid; i < 24576; i += 256) sWbuf[i] = W_node1[i];
    __syncthreads();
    {
        float A0[4] = { sBn1[j0], sBn1[j0+1], sBn1[j0+2], sBn1[j0+3] };
        float A1[4] = { A0[0], A0[1], A0[2], A0[3] };
        const float* h0p = &sH[ln0 * 64];
        const float* h1p = &sH[ln1 * 64];
        #pragma unroll 4
        for (int c = 0; c < 64; c++) {
            float4 w = *(const float4*)&sWbuf[c * 64 + j0];
            float h0 = h0p[c], h1 = h1p[c];
            A0[0] += h0 * w.x; A0[1] += h0 * w.y; A0[2] += h0 * w.z; A0[3] += h0 * w.w;
            A1[0] += h1 * w.x; A1[1] += h1 * w.y; A1[2] += h1 * w.z; A1[3] += h1 * w.w;
        }
        const float* e0p = &sHE[ln0 * 256];
        const float* e1p = &sHE[ln1 * 256];
        #pragma unroll 4
        for (int c = 0; c < 256; c++) {
            float4 w = *(const float4*)&sWbuf[(64 + c) * 64 + j0];
            float h0 = e0p[c], h1 = e1p[c];
            A0[0] += h0 * w.x; A0[1] += h0 * w.y; A0[2] += h0 * w.z; A0[3] += h0 * w.w;
            A1[0] += h1 * w.x; A1[1] += h1 * w.y; A1[2] += h1 * w.z; A1[3] += h1 * w.w;
        }
        const float* q0p = &sHC[ln0 * 64];
        const float* q1p = &sHC[ln1 * 64];
        #pragma unroll 4
        for (int c = 0; c < 64; c++) {
            float4 w = *(const float4*)&sWbuf[(320 + c) * 64 + j0];
            float h0 = q0p[c], h1 = q1p[c];
            A0[0] += h0 * w.x; A0[1] += h0 * w.y; A0[2] += h0 * w.z; A0[3] += h0 * w.w;
            A1[0] += h1 * w.x; A1[1] += h1 * w.y; A1[2] += h1 * w.z; A1[3] += h1 * w.w;
        }
        float* o0 = &sT[ln0 * 64 + j0];
        float* o1 = &sT[ln1 * 64 + j0];
        o0[0] = siluf(A0[0]); o0[1] = siluf(A0[1]); o0[2] = siluf(A0[2]); o0[3] = siluf(A0[3]);
        o1[0] = siluf(A1[0]); o1[1] = siluf(A1[1]); o1[2] = siluf(A1[2]); o1[3] = siluf(A1[3]);
    }
    __syncthreads();

    for (int i = tid; i < 4096; i += 256) sWbuf[i] = W_node2[i];
    __syncthreads();
    {
        float A0[4] = { sBn2[j0], sBn2[j0+1], sBn2[j0+2], sBn2[j0+3] };
        float A1[4] = { A0[0], A0[1], A0[2], A0[3] };
        const float* t0p = &sT[ln0 * 64];
        const float* t1p = &sT[ln1 * 64];
        #pragma unroll 4
        for (int c = 0; c < 64; c++) {
            float4 w = *(const float4*)&sWbuf[c * 64 + j0];
            float h0 = t0p[c], h1 = t1p[c];
            A0[0] += h0 * w.x; A0[1] += h0 * w.y; A0[2] += h0 * w.z; A0[3] += h0 * w.w;
            A1[0] += h1 * w.x; A1[1] += h1 * w.y; A1[2] += h1 * w.z; A1[3] += h1 * w.w;
        }
        float r0[4], r1[4];
        #pragma unroll
        for (int q = 0; q < 4; q++) {
            r0[q] = sH[ln0 * 64 + j0 + q] + siluf(A0[q]);
            r1[q] = sH[ln1 * 64 + j0 + q] + siluf(A1[q]);
        }
        float* o0 = &sHN[ln0 * 64 + j0];
        float* o1 = &sHN[ln1 * 64 + j0];
        #pragma unroll
        for (int q = 0; q < 4; q++) { o0[q] = r0[q]; o1[q] = r1[q]; }
        if (ln0 < nn) *(float4*)&out_h[(n0 + ln0) * 64 + j0] = make_float4(r0[0], r0[1], r0[2], r0[3]);
        if (ln1 < nn) *(float4*)&out_h[(n0 + ln1) * 64 + j0] = make_float4(r1[0], r1[1], r1[2], r1[3]);
    }
    __syncthreads();

    for (int i = tid; i < 4096; i += 256) sWbuf[i] = W_vel1[i];
    __syncthreads();
    {
        float A0[4] = { sBv1[j0], sBv1[j0+1], sBv1[j0+2], sBv1[j0+3] };
        float A1[4] = { A0[0], A0[1], A0[2], A0[3] };
        const float* n0p = &sHN[ln0 * 64];
        const float* n1p = &sHN[ln1 * 64];
        #pragma unroll 4
        for (int c = 0; c < 64; c++) {
            float4 w = *(const float4*)&sWbuf[c * 64 + j0];
            float h0 = n0p[c], h1 = n1p[c];
            A0[0] += h0 * w.x; A0[1] += h0 * w.y; A0[2] += h0 * w.z; A0[3] += h0 * w.w;
            A1[0] += h1 * w.x; A1[1] += h1 * w.y; A1[2] += h1 * w.z; A1[3] += h1 * w.w;
        }
        float* o0 = &sT[ln0 * 64 + j0];
        float* o1 = &sT[ln1 * 64 + j0];
        #pragma unroll
        for (int q = 0; q < 4; q++) {
            o0[q] = siluf(A0[q]) * sWv2[j0 + q];
            o1[q] = siluf(A1[q]) * sWv2[j0 + q];
        }
    }
    __syncthreads();

    if (tid < nn) {
        int ln = tid;
        float s = 0.f;
        #pragma unroll 8
        for (int k = 0; k < 64; k++) s += sT[ln * 64 + k];
        float scale = 2.f / (1.f + __expf(-s));
        int n = n0 + ln;
        #pragma unroll
        for (int d = 0; d < 3; d++) {
            float vn = g_dv[n * 3 + d] + scale * v[n * 3 + d];
            out_v[n * 3 + d] = vn;
            out_x[n * 3 + d] = x[n * 3 + d] + vn;
        }
    }
}

// ---------------- launch ----------------
extern "C" void kernel_launch(void* const* d_in, const int* in_sizes, int n_in,
                              void* d_out, int out_size)
{
    const float* h        = (const float*)d_in[0];
    const float* x        = (const float*)d_in[1];
    const float* v        = (const float*)d_in[2];
    const int*   idxs     = (const int*)  d_in[3];
    const float* rbf_mean = (const float*)d_in[4];
    const float* rbf_beta = (const float*)d_in[5];
    const float* W_in     = (const float*)d_in[6];
    const float* b_in     = (const float*)d_in[7];
    const float* W_out1   = (const float*)d_in[8];
    const float* b_out1   = (const float*)d_in[9];
    const float* W_out2   = (const float*)d_in[10];
    const float* b_out2   = (const float*)d_in[11];
    const float* W_att    = (const float*)d_in[12];
    const float* b_att    = (const float*)d_in[13];
    const float* W_xmix   = (const float*)d_in[14];
    const float* W_post1  = (const float*)d_in[15];
    const float* b_post1  = (const float*)d_in[16];
    const float* W_post2  = (const float*)d_in[17];
    const float* b_post2  = (const float*)d_in[18];
    const float* W_node1  = (const float*)d_in[19];
    const float* b_node1  = (const float*)d_in[20];
    const float* W_node2  = (const float*)d_in[21];
    const float* b_node2  = (const float*)d_in[22];
    const float* W_vmix   = (const float*)d_in[23];
    const float* W_vel1   = (const float*)d_in[24];
    const float* b_vel1   = (const float*)d_in[25];
    const float* W_vel2   = (const float*)d_in[26];

    int N = in_sizes[0] / 64;
    int E = in_sizes[3] / 2;

    float* out  = (float*)d_out;
    float* outh = out;
    float* outx = out + (size_t)N * 64;
    float* outv = out + (size_t)N * 67;

    const int SM_NODE = (8192 * 2 + 2048 * 4 + 64 * 6 + 24576) * 4;

    cudaFuncSetAttribute(k_edge_mma, cudaFuncAttributeMaxDynamicSharedMemorySize, E_SMEM);
    cudaFuncSetAttribute(k_xagg,     cudaFuncAttributeMaxDynamicSharedMemorySize, XG_SMEM);
    cudaFuncSetAttribute(k_node,     cudaFuncAttributeMaxDynamicSharedMemorySize, SM_NODE);

    k_init<<<256, 256>>>(N, W_xmix, W_in, W_out1, W_out2);
    k_edge_mma<<<296, 256, E_SMEM>>>(h, x, idxs, rbf_mean, rbf_beta,
                                     b_in, b_out1, b_out2, W_att, b_att, E);
    k_scan<<<1, 1024>>>(N);
    k_fill<<<(E + 255) / 256, 256>>>(idxs, E);
    k_xagg<<<(E + 63) / 64, 256, XG_SMEM>>>(idxs, W_vmix, E);
    k_fin<<<N, 256>>>(W_vmix, N);
    k_node<<<(N + 31) / 32, 256, SM_NODE>>>(h, x, v,
                                            W_post1, b_post1, W_post2, b_post2,
                                            W_node1, b_node1, W_node2, b_node2,
                                            W_vel1, b_vel1, W_vel2,
                                            outh, outx, outv, N);
}

// round 15
// speedup vs baseline: 1.2936x; 1.2378x over previous
#include <cuda_runtime.h>
#include <cuda_fp16.h>
#include <stdint.h>
#include <math.h>

#define NMAX 10000
#define EMAX 160000
#define NBLK ((EMAX + 63) / 64)

// ---------------- scratch ----------------
__device__ float g_hemtx[EMAX * 64];
__device__ float g_xhat[EMAX * 3];
__device__ float g_w[EMAX * 4];
__device__ float g_expsum[NMAX * 4];
__device__ int   g_counts[NMAX];
__device__ int   g_off[NMAX + 1];
__device__ int   g_cursor[NMAX];
__device__ int   g_eid[EMAX];
__device__ float g_he[NMAX * 256];
__device__ float g_cnorm[NMAX * 256];
__device__ float g_dv[NMAX * 3];
__device__ float g_phe[NBLK * 2 * 256];
__device__ float g_pcomb[NBLK * 2 * 3 * 256];
__device__ __half g_wx[256 * 256];           // W_xmix^T fp16 [n][k]
__device__ uint32_t g_ewi[4096];
__device__ uint32_t g_ew1a[4096];
__device__ uint32_t g_ew1b[2048];
__device__ uint32_t g_ew2[2048];
// node-MLP weights, fp16x2 [n][k]
__device__ uint32_t g_nwp1[8192];            // W_post1^T 64x256
__device__ uint32_t g_nwn1[12288];           // W_node1^T 64x384
__device__ uint32_t g_nwp2[2048];            // W_post2^T 64x64
__device__ uint32_t g_nwn2[2048];            // W_node2^T 64x64
__device__ uint32_t g_nwv1[2048];            // W_vel1^T  64x64

__device__ __forceinline__ float siluf(float x) { return x / (1.f + __expf(-x)); }
__device__ __forceinline__ float fast_tanh(float x) {
    float y; asm("tanh.approx.f32 %0, %1;" : "=f"(y) : "f"(x)); return y;
}
__device__ __forceinline__ void mma16816h(float* d, const uint32_t* a, const uint32_t* b) {
    asm volatile("mma.sync.aligned.m16n8k16.row.col.f32.f16.f16.f32 "
        "{%0,%1,%2,%3}, {%4,%5,%6,%7}, {%8,%9}, {%0,%1,%2,%3};"
        : "+f"(d[0]), "+f"(d[1]), "+f"(d[2]), "+f"(d[3])
        : "r"(a[0]), "r"(a[1]), "r"(a[2]), "r"(a[3]), "r"(b[0]), "r"(b[1]));
}
__device__ __forceinline__ uint32_t pack2h(float a, float b) {
    __half2 p = __floats2half2_rn(a, b);
    return *(uint32_t*)&p;
}
__device__ __forceinline__ uint32_t smem_u32(const void* p) {
    uint32_t a;
    asm("{ .reg .u64 t; cvta.to.shared.u64 t, %1; cvt.u32.u64 %0, t; }" : "=r"(a) : "l"(p));
    return a;
}
#define LDSM4(r0, r1, r2, r3, addr) \
    asm volatile("ldmatrix.sync.aligned.m8n8.x4.shared.b16 {%0,%1,%2,%3}, [%4];" \
        : "=r"(r0), "=r"(r1), "=r"(r2), "=r"(r3) : "r"(addr))
#define CP_ASYNC16(dst, src) \
    asm volatile("cp.async.cg.shared.global [%0], [%1], 16;" :: "r"(dst), "l"(src) : "memory")
#define CP_COMMIT() asm volatile("cp.async.commit_group;" ::: "memory")
#define CP_WAIT0()  asm volatile("cp.async.wait_group 0;" ::: "memory")

// ---------------- K0: init + weight prep ----------------
__global__ void k_init(int N,
                       const float* __restrict__ W_xmix,
                       const float* __restrict__ W_in,
                       const float* __restrict__ W_out1,
                       const float* __restrict__ W_out2,
                       const float* __restrict__ W_post1,
                       const float* __restrict__ W_post2,
                       const float* __restrict__ W_node1,
                       const float* __restrict__ W_node2,
                       const float* __restrict__ W_vel1) {
    int i = blockIdx.x * blockDim.x + threadIdx.x;
    if (i < N * 4) g_expsum[i] = 0.f;
    if (i < N) g_counts[i] = 0;
    if (i < 65536) {
        int n = i >> 8, k = i & 255;
        g_wx[n * 256 + k] = __float2half_rn(W_xmix[k * 256 + n]);
    }
    if (i < 4096) {
        int n = i >> 6, k0 = (i & 63) * 2;
        float w0 = (n < 50) ? W_in[k0 * 50 + n] : 0.f;
        float w1 = (n < 50) ? W_in[(k0 + 1) * 50 + n] : 0.f;
        g_ewi[i] = pack2h(w0, w1);
    } else if (i < 8192) {
        int j = i - 4096;
        int n = j >> 6, k0 = (j & 63) * 2;
        g_ew1a[j] = pack2h(W_out1[k0 * 64 + n], W_out1[(k0 + 1) * 64 + n]);
    } else if (i < 10240) {
        int j = i - 8192;
        int n = j >> 5, k0 = (j & 31) * 2;
        float w0 = (k0 < 50) ? W_out1[(128 + k0) * 64 + n] : ((k0 == 50) ? W_out1[178 * 64 + n] : 0.f);
        int k1 = k0 + 1;
        float w1 = (k1 < 50) ? W_out1[(128 + k1) * 64 + n] : ((k1 == 50) ? W_out1[178 * 64 + n] : 0.f);
        g_ew1b[j] = pack2h(w0, w1);
    } else if (i < 12288) {
        int j = i - 10240;
        int n = j >> 5, k0 = (j & 31) * 2;
        g_ew2[j] = pack2h(W_out2[k0 * 64 + n], W_out2[(k0 + 1) * 64 + n]);
    } else if (i < 20480) {
        int j = i - 12288;
        int n = j >> 7, k0 = (j & 127) * 2;
        g_nwp1[j] = pack2h(W_post1[k0 * 64 + n], W_post1[(k0 + 1) * 64 + n]);
    } else if (i < 32768) {
        int j = i - 20480;
        int n = j / 192, kp = j % 192, k0 = kp * 2;
        g_nwn1[j] = pack2h(W_node1[k0 * 64 + n], W_node1[(k0 + 1) * 64 + n]);
    } else if (i < 34816) {
        int j = i - 32768;
        int n = j >> 5, k0 = (j & 31) * 2;
        g_nwp2[j] = pack2h(W_post2[k0 * 64 + n], W_post2[(k0 + 1) * 64 + n]);
    } else if (i < 36864) {
        int j = i - 34816;
        int n = j >> 5, k0 = (j & 31) * 2;
        g_nwn2[j] = pack2h(W_node2[k0 * 64 + n], W_node2[(k0 + 1) * 64 + n]);
    } else if (i < 38912) {
        int j = i - 36864;
        int n = j >> 5, k0 = (j & 31) * 2;
        g_nwv1[j] = pack2h(W_vel1[k0 * 64 + n], W_vel1[(k0 + 1) * 64 + n]);
    }
}

// ---------------- K1: edge MLP via fp16 mma.sync + ldmatrix (fused exp/expsum) ----------------
#define O_A     0
#define O_X     4352
#define O_M     6656
#define O_WI    8960
#define O_W1A   13312
#define O_W1B   17664
#define O_W2    19968
#define O_HE    22272
#define O_BIN   26496
#define O_BO1   26560
#define O_BO2   26624
#define O_MEAN  26688
#define O_BETA  26752
#define O_WA    26816
#define O_BA    27072
#define O_NORM  27076
#define O_EX    27140
#define O_XHT   27204
#define E_SMEM  (27400 * 4)

__global__ void __launch_bounds__(256, 2)
k_edge_mma(const float* __restrict__ h, const float* __restrict__ x,
           const int* __restrict__ idxs,
           const float* __restrict__ rbf_means, const float* __restrict__ rbf_betas,
           const float* __restrict__ b_in, const float* __restrict__ b_out1,
           const float* __restrict__ b_out2,
           const float* __restrict__ W_att, const float* __restrict__ b_att, int E)
{
    extern __shared__ uint32_t su[];
    float* sf = (float*)su;
    int tid = threadIdx.x, lid = tid & 31, wid = tid >> 5;
    int g = lid >> 2, tg = lid & 3;
    int mrow = (wid & 3) * 16, ncol = (wid >> 2) * 32;

    for (int i = tid; i < 4096; i += 256) {
        int n = i >> 6, kk = i & 63;
        su[O_WI  + n * 68 + kk] = g_ewi[i];
        su[O_W1A + n * 68 + kk] = g_ew1a[i];
    }
    for (int i = tid; i < 2048; i += 256) {
        int n = i >> 5, kk = i & 31;
        su[O_W1B + n * 36 + kk] = g_ew1b[i];
        su[O_W2  + n * 36 + kk] = g_ew2[i];
    }
    if (tid < 64) {
        sf[O_BIN + tid]  = (tid < 50) ? b_in[tid] : 0.f;
        sf[O_BO1 + tid]  = b_out1[tid];
        sf[O_BO2 + tid]  = b_out2[tid];
        sf[O_MEAN + tid] = (tid < 50) ? rbf_means[tid] : 0.f;
        sf[O_BETA + tid] = (tid < 50) ? rbf_betas[tid] : 1.f;
    }
    if (tid < 256) sf[O_WA + tid] = W_att[tid];
    if (tid < 4)   sf[O_BA + tid] = b_att[tid];
    __syncthreads();

    uint32_t sbase = smem_u32(su);
    int mq = lid >> 3, rr = lid & 7;
    int rA = mrow + (mq & 1) * 8 + rr;
    int cA = (mq >> 1) * 4;
    uint32_t adA  = sbase + (O_A  + rA * 68 + cA) * 4;
    uint32_t adX  = sbase + (O_X  + rA * 36 + cA) * 4;
    uint32_t adM  = sbase + (O_M  + rA * 36 + cA) * 4;
    int rB = (mq >> 1) * 8 + rr;
    int cB = (mq & 1) * 4;
    uint32_t adWI0  = sbase + (O_WI  + (ncol + rB) * 68 + cB) * 4;
    uint32_t adWI1  = sbase + (O_WI  + (ncol + 16 + rB) * 68 + cB) * 4;
    uint32_t adW1A0 = sbase + (O_W1A + (ncol + rB) * 68 + cB) * 4;
    uint32_t adW1A1 = sbase + (O_W1A + (ncol + 16 + rB) * 68 + cB) * 4;
    uint32_t adW1B0 = sbase + (O_W1B + (ncol + rB) * 36 + cB) * 4;
    uint32_t adW1B1 = sbase + (O_W1B + (ncol + 16 + rB) * 36 + cB) * 4;
    uint32_t adW20  = sbase + (O_W2  + (ncol + rB) * 36 + cB) * 4;
    uint32_t adW21  = sbase + (O_W2  + (ncol + 16 + rB) * 36 + cB) * 4;

    int ntiles = (E + 63) / 64;
    for (int tile = blockIdx.x; tile < ntiles; tile += gridDim.x) {
        int e0 = tile * 64, ne = min(64, E - e0);

        if (tid < 64) {
            float nrm = 0.f, xh0 = 0.f, xh1 = 0.f, xh2 = 0.f;
            if (tid < ne) {
                int s = idxs[2 * (e0 + tid)], d = idxs[2 * (e0 + tid) + 1];
                float dx = x[3 * s]     - x[3 * d];
                float dy = x[3 * s + 1] - x[3 * d + 1];
                float dz = x[3 * s + 2] - x[3 * d + 2];
                nrm = sqrtf(dx * dx + dy * dy + dz * dz + 1e-14f);
                float inv = 1.f / (nrm + 1e-5f);
                xh0 = dx * inv; xh1 = dy * inv; xh2 = dz * inv;
                atomicAdd(&g_counts[s], 1);
            }
            sf[O_NORM + tid] = nrm;
            sf[O_EX + tid]   = __expf(-nrm);
            sf[O_XHT + tid * 3] = xh0; sf[O_XHT + tid * 3 + 1] = xh1; sf[O_XHT + tid * 3 + 2] = xh2;
        }
        {
            int el = tid >> 2, part = tid & 3;
            uint32_t hb[16];
            if (el < ne) {
                int node = idxs[2 * (e0 + el) + (part >> 1)];
                const float4* hp = (const float4*)&h[node * 64 + (part & 1) * 32];
                #pragma unroll
                for (int i2 = 0; i2 < 8; i2++) {
                    float4 v = hp[i2];
                    hb[i2 * 2]     = pack2h(v.x, v.y);
                    hb[i2 * 2 + 1] = pack2h(v.z, v.w);
                }
            } else {
                #pragma unroll
                for (int i2 = 0; i2 < 16; i2++) hb[i2] = 0u;
            }
            uint4* dh = (uint4*)&su[O_A + el * 68 + part * 16];
            #pragma unroll
            for (int i2 = 0; i2 < 4; i2++)
                dh[i2] = make_uint4(hb[i2*4], hb[i2*4+1], hb[i2*4+2], hb[i2*4+3]);
        }
        __syncthreads();

        float acc[4][4];

        // ---- G1 ----
        #pragma unroll
        for (int nt = 0; nt < 4; nt++)
            #pragma unroll
            for (int q = 0; q < 4; q++) acc[nt][q] = 0.f;
        #pragma unroll
        for (int ks = 0; ks < 8; ks++) {
            uint32_t aH[4];
            LDSM4(aH[0], aH[1], aH[2], aH[3], adA + ks * 32);
            uint32_t b0, b1, b2, b3;
            LDSM4(b0, b1, b2, b3, adWI0 + ks * 32);
            { uint32_t bb[2] = { b0, b1 }; mma16816h(acc[0], aH, bb); }
            { uint32_t bb[2] = { b2, b3 }; mma16816h(acc[1], aH, bb); }
            LDSM4(b0, b1, b2, b3, adWI1 + ks * 32);
            { uint32_t bb[2] = { b0, b1 }; mma16816h(acc[2], aH, bb); }
            { uint32_t bb[2] = { b2, b3 }; mma16816h(acc[3], aH, bb); }
        }
        #pragma unroll
        for (int nt = 0; nt < 4; nt++) {
            #pragma unroll
            for (int hh = 0; hh < 2; hh++) {
                int row = mrow + g + hh * 8;
                int c0 = ncol + nt * 8 + tg * 2;
                float v0 = acc[nt][hh * 2]     + sf[O_BIN + c0];
                float v1 = acc[nt][hh * 2 + 1] + sf[O_BIN + c0 + 1];
                float ex = sf[O_EX + row];
                float x0, x1;
                if (c0 < 50) { float d = ex - sf[O_MEAN + c0]; x0 = __expf(-sf[O_BETA + c0] * d * d) * v0; }
                else x0 = (c0 == 50) ? sf[O_NORM + row] : 0.f;
                if (c0 + 1 < 50) { float d = ex - sf[O_MEAN + c0 + 1]; x1 = __expf(-sf[O_BETA + c0 + 1] * d * d) * v1; }
                else x1 = 0.f;
                su[O_X + row * 36 + (c0 >> 1)] = pack2h(x0, x1);
            }
        }
        __syncthreads();

        // ---- G2 ----
        #pragma unroll
        for (int nt = 0; nt < 4; nt++)
            #pragma unroll
            for (int q = 0; q < 4; q++) acc[nt][q] = 0.f;
        #pragma unroll
        for (int ks = 0; ks < 8; ks++) {
            uint32_t aH[4];
            LDSM4(aH[0], aH[1], aH[2], aH[3], adA + ks * 32);
            uint32_t b0, b1, b2, b3;
            LDSM4(b0, b1, b2, b3, adW1A0 + ks * 32);
            { uint32_t bb[2] = { b0, b1 }; mma16816h(acc[0], aH, bb); }
            { uint32_t bb[2] = { b2, b3 }; mma16816h(acc[1], aH, bb); }
            LDSM4(b0, b1, b2, b3, adW1A1 + ks * 32);
            { uint32_t bb[2] = { b0, b1 }; mma16816h(acc[2], aH, bb); }
            { uint32_t bb[2] = { b2, b3 }; mma16816h(acc[3], aH, bb); }
        }
        #pragma unroll
        for (int ks = 0; ks < 4; ks++) {
            uint32_t aH[4];
            LDSM4(aH[0], aH[1], aH[2], aH[3], adX + ks * 32);
            uint32_t b0, b1, b2, b3;
            LDSM4(b0, b1, b2, b3, adW1B0 + ks * 32);
            { uint32_t bb[2] = { b0, b1 }; mma16816h(acc[0], aH, bb); }
            { uint32_t bb[2] = { b2, b3 }; mma16816h(acc[1], aH, bb); }
            LDSM4(b0, b1, b2, b3, adW1B1 + ks * 32);
            { uint32_t bb[2] = { b0, b1 }; mma16816h(acc[2], aH, bb); }
            { uint32_t bb[2] = { b2, b3 }; mma16816h(acc[3], aH, bb); }
        }
        #pragma unroll
        for (int nt = 0; nt < 4; nt++) {
            #pragma unroll
            for (int hh = 0; hh < 2; hh++) {
                int row = mrow + g + hh * 8;
                int c0 = ncol + nt * 8 + tg * 2;
                float m0 = siluf(acc[nt][hh * 2]     + sf[O_BO1 + c0]);
                float m1 = siluf(acc[nt][hh * 2 + 1] + sf[O_BO1 + c0 + 1]);
                su[O_M + row * 36 + (c0 >> 1)] = pack2h(m0, m1);
            }
        }
        __syncthreads();

        // ---- G3 ----
        #pragma unroll
        for (int nt = 0; nt < 4; nt++)
            #pragma unroll
            for (int q = 0; q < 4; q++) acc[nt][q] = 0.f;
        #pragma unroll
        for (int ks = 0; ks < 4; ks++) {
            uint32_t aH[4];
            LDSM4(aH[0], aH[1], aH[2], aH[3], adM + ks * 32);
            uint32_t b0, b1, b2, b3;
            LDSM4(b0, b1, b2, b3, adW20 + ks * 32);
            { uint32_t bb[2] = { b0, b1 }; mma16816h(acc[0], aH, bb); }
            { uint32_t bb[2] = { b2, b3 }; mma16816h(acc[1], aH, bb); }
            LDSM4(b0, b1, b2, b3, adW21 + ks * 32);
            { uint32_t bb[2] = { b0, b1 }; mma16816h(acc[2], aH, bb); }
            { uint32_t bb[2] = { b2, b3 }; mma16816h(acc[3], aH, bb); }
        }
        #pragma unroll
        for (int nt = 0; nt < 4; nt++) {
            #pragma unroll
            for (int hh = 0; hh < 2; hh++) {
                int row = mrow + g + hh * 8;
                int c0 = ncol + nt * 8 + tg * 2;
                sf[O_HE + row * 66 + c0]     = acc[nt][hh * 2]     + sf[O_BO2 + c0];
                sf[O_HE + row * 66 + c0 + 1] = acc[nt][hh * 2 + 1] + sf[O_BO2 + c0 + 1];
            }
        }
        __syncthreads();

        // att: logits -> exp -> g_w, expsum
        {
            int el = tid >> 2, a = tid & 3;
            if (el < ne) {
                float acc2 = sf[O_BA + a];
                const float* hv = &sf[O_HE + el * 66];
                #pragma unroll 8
                for (int c = 0; c < 64; c++) acc2 += hv[c] * sf[O_WA + c * 4 + a];
                float lg = (acc2 > 0.f) ? acc2 : 2.f * (__expf(acc2 * 0.5f) - 1.f);
                float w = __expf(lg);
                int s = idxs[2 * (e0 + el)];
                g_w[(e0 + el) * 4 + a] = w;
                atomicAdd(&g_expsum[s * 4 + a], w);
            }
        }
        for (int i = tid; i < ne * 16; i += 256) {
            int el = i >> 4, c = (i & 15) * 4;
            float4 o = make_float4(sf[O_HE + el * 66 + c], sf[O_HE + el * 66 + c + 1],
                                   sf[O_HE + el * 66 + c + 2], sf[O_HE + el * 66 + c + 3]);
            *(float4*)&g_hemtx[(size_t)(e0 + el) * 64 + c] = o;
        }
        for (int i = tid; i < ne * 3; i += 256) g_xhat[e0 * 3 + i] = sf[O_XHT + i];
        __syncthreads();
    }
}

// ---------------- K2: exclusive scan (shuffle-based) ----------------
__global__ void k_scan(int N) {
    __shared__ int wsum[32];
    int t = threadIdx.x, lane = t & 31, w = t >> 5;
    int chunk = (N + 1023) / 1024;
    int base = t * chunk;
    int vals[16];
    int loc = 0;
    for (int k = 0; k < chunk; k++) {
        int idx = base + k;
        int v = (idx < N) ? g_counts[idx] : 0;
        vals[k] = loc; loc += v;
    }
    int inc = loc;
    #pragma unroll
    for (int o = 1; o < 32; o <<= 1) {
        int v = __shfl_up_sync(0xFFFFFFFFu, inc, o);
        if (lane >= o) inc += v;
    }
    if (lane == 31) wsum[w] = inc;
    __syncthreads();
    if (w == 0) {
        int v2 = wsum[lane];
        int i2 = v2;
        #pragma unroll
        for (int o = 1; o < 32; o <<= 1) {
            int x2 = __shfl_up_sync(0xFFFFFFFFu, i2, o);
            if (lane >= o) i2 += x2;
        }
        wsum[lane] = i2 - v2;
    }
    __syncthreads();
    int excl = wsum[w] + (inc - loc);
    for (int k = 0; k < chunk; k++) {
        int idx = base + k;
        if (idx < N) { g_off[idx] = excl + vals[k]; g_cursor[idx] = excl + vals[k]; }
    }
    if (t == 1023) g_off[N] = excl + loc;
}

// ---------------- K3: CSR fill (pure) ----------------
__global__ void k_fill(const int* __restrict__ idxs, int E) {
    int e = blockIdx.x * blockDim.x + threadIdx.x;
    if (e >= E) return;
    int s = idxs[2 * e];
    int p = atomicAdd(&g_cursor[s], 1);
    g_eid[p] = e;
}

// ---------------- K5: fused xmix GEMM + aggregation (cp.async double-buffered W) ----------------
#define XG_A    0
#define XG_W0   8448
#define XG_W1   17664
#define XG_XH   26880
#define XG_NODE 27072
#define XG_WV   27136
#define XG_RED  27392
#define XG_SMEM (27420 * 4)

__global__ void __launch_bounds__(256, 2)
k_xagg(const int* __restrict__ idxs, const float* __restrict__ W_vmix, int E)
{
    extern __shared__ uint32_t su[];
    float* sf = (float*)su;
    int tid = threadIdx.x, lid = tid & 31, wid = tid >> 5;
    int p0 = blockIdx.x * 64;
    uint32_t* pA = su + XG_A;
    uint32_t* pC = su + XG_W0;
    int* sN = (int*)(su + XG_NODE);
    uint32_t sbase = smem_u32(su);

    {
        uint32_t dst = sbase + (XG_W0 + tid * 36) * 4;
        const char* src = (const char*)&g_wx[tid * 256];
        #pragma unroll
        for (int i = 0; i < 9; i++) CP_ASYNC16(dst + i * 16, src + i * 16);
        CP_COMMIT();
    }

    {
        int sl = tid & 63, kq = tid >> 6;
        int e = -1, s = -1;
        float att[4], hm[16];
        int p = p0 + sl;
        if (p < E) {
            e = g_eid[p];
            s = idxs[2 * e];
            #pragma unroll
            for (int a = 0; a < 4; a++) att[a] = g_w[e * 4 + a] / g_expsum[s * 4 + a];
            const float4* hp = (const float4*)&g_hemtx[(size_t)e * 64 + kq * 16];
            #pragma unroll
            for (int i = 0; i < 4; i++) {
                float4 v = hp[i];
                hm[i * 4] = v.x; hm[i * 4 + 1] = v.y; hm[i * 4 + 2] = v.z; hm[i * 4 + 3] = v.w;
            }
        } else {
            #pragma unroll
            for (int a = 0; a < 4; a++) att[a] = 0.f;
            #pragma unroll
            for (int i = 0; i < 16; i++) hm[i] = 0.f;
        }
        if (kq == 0) {
            sN[sl] = s;
            float x0 = 0.f, x1 = 0.f, x2 = 0.f;
            if (e >= 0) { x0 = g_xhat[e * 3]; x1 = g_xhat[e * 3 + 1]; x2 = g_xhat[e * 3 + 2]; }
            sf[XG_XH + sl * 3] = x0; sf[XG_XH + sl * 3 + 1] = x1; sf[XG_XH + sl * 3 + 2] = x2;
        }
        #pragma unroll
        for (int j = 0; j < 32; j++) {
            int kl = 2 * j;
            float m = hm[kl >> 2];
            pA[sl * 132 + ((kq * 64 + kl) >> 1)] = pack2h(m * att[kl & 3], m * att[(kl + 1) & 3]);
        }
        sf[XG_WV + tid] = W_vmix[tid];
    }
    CP_WAIT0();
    __syncthreads();

    int g = lid >> 2, tg = lid & 3;
    int mrow = (wid & 1) * 32;
    int ncol = (wid >> 1) * 64;

    int mq = lid >> 3, rr = lid & 7;
    uint32_t adA0 = sbase + (XG_A + (mrow + (mq & 1) * 8 + rr) * 132 + (mq >> 1) * 4) * 4;
    uint32_t adA1 = adA0 + 16 * 132 * 4;
    int rB = (mq >> 1) * 8 + rr;
    int cB = (mq & 1) * 4;
    uint32_t adW0 = sbase + (XG_W0 + (ncol + rB) * 36 + cB) * 4;
    uint32_t adW1 = adW0 + 16 * 36 * 4;
    uint32_t adW2 = adW0 + 32 * 36 * 4;
    uint32_t adW3 = adW0 + 48 * 36 * 4;
    const uint32_t BUFD = (XG_W1 - XG_W0) * 4;

    float acc[2][8][4];
    #pragma unroll
    for (int mt = 0; mt < 2; mt++)
        #pragma unroll
        for (int nt = 0; nt < 8; nt++)
            #pragma unroll
            for (int q = 0; q < 4; q++) acc[mt][nt][q] = 0.f;

    #pragma unroll
    for (int kc = 0; kc < 4; kc++) {
        if (kc < 3) {
            uint32_t dst = sbase + ((((kc + 1) & 1) ? XG_W1 : XG_W0) + tid * 36) * 4;
            const char* src = (const char*)&g_wx[tid * 256 + (kc + 1) * 64];
            #pragma unroll
            for (int i = 0; i < 9; i++) CP_ASYNC16(dst + i * 16, src + i * 16);
            CP_COMMIT();
        }
        uint32_t boff = (kc & 1) ? BUFD : 0u;
        #pragma unroll
        for (int ks = 0; ks < 4; ks++) {
            uint32_t aoff = kc * 128 + ks * 32;
            uint32_t aH[2][4];
            LDSM4(aH[0][0], aH[0][1], aH[0][2], aH[0][3], adA0 + aoff);
            LDSM4(aH[1][0], aH[1][1], aH[1][2], aH[1][3], adA1 + aoff);
            uint32_t woff = boff + ks * 32;
            uint32_t b0, b1, b2, b3;
            #define XAGG_PAIR(ADDR, NT) \
                LDSM4(b0, b1, b2, b3, (ADDR) + woff); \
                { uint32_t bb[2] = { b0, b1 }; mma16816h(acc[0][NT], aH[0], bb); mma16816h(acc[1][NT], aH[1], bb); } \
                { uint32_t bb[2] = { b2, b3 }; mma16816h(acc[0][(NT)+1], aH[0], bb); mma16816h(acc[1][(NT)+1], aH[1], bb); }
            XAGG_PAIR(adW0, 0)
            XAGG_PAIR(adW1, 2)
            XAGG_PAIR(adW2, 4)
            XAGG_PAIR(adW3, 6)
            #undef XAGG_PAIR
        }
        if (kc < 3) {
            CP_WAIT0();
            __syncthreads();
        }
    }

    #pragma unroll
    for (int mt = 0; mt < 2; mt++)
        #pragma unroll
        for (int nt = 0; nt < 8; nt++) {
            int rl = mrow + mt * 16 + g;
            int col = ncol + nt * 8 + tg * 2;
            float* a = acc[mt][nt];
            pC[rl * 132 + (col >> 1)]       = pack2h(fast_tanh(a[0]), fast_tanh(a[1]));
            pC[(rl + 8) * 132 + (col >> 1)] = pack2h(fast_tanh(a[2]), fast_tanh(a[3]));
        }
    __syncthreads();

    {
        int c = tid;
        int blk = blockIdx.x;
        float wv = sf[XG_WV + c];
        float accH = 0.f, a0 = 0.f, a1 = 0.f, a2 = 0.f;
        int segStart = 0;
        for (int sl = 0; sl < 64; sl++) {
            int n = sN[sl];
            if (n >= 0) {
                uint32_t ap = pA[sl * 132 + (c >> 1)];
                __half2 av2 = *(__half2*)&ap;
                float Av = (c & 1) ? __high2float(av2) : __low2float(av2);
                accH += Av;
                uint32_t cp = pC[sl * 132 + (c >> 1)];
                __half2 h2 = *(__half2*)&cp;
                float cf = (c & 1) ? __high2float(h2) : __low2float(h2);
                a0 += cf * sf[XG_XH + sl * 3];
                a1 += cf * sf[XG_XH + sl * 3 + 1];
                a2 += cf * sf[XG_XH + sl * 3 + 2];
            }
            bool segEnd = (sl == 63) || (sN[sl + 1] != n);
            if (segEnd) {
                if (n >= 0) {
                    int beg = g_off[n], end = g_off[n + 1];
                    bool full = (beg == p0 + segStart) && (end == p0 + sl + 1);
                    if (full) {
                        float invc = 1.f / ((float)(end - beg) + 1.f);
                        g_he[n * 256 + c] = accH;
                        float s0 = a0 * invc, s1 = a1 * invc, s2 = a2 * invc;
                        g_cnorm[n * 256 + c] = s0 * s0 + s1 * s1 + s2 * s2;
                        float r0 = wv * s0, r1 = wv * s1, r2 = wv * s2;
                        #pragma unroll
                        for (int o = 16; o > 0; o >>= 1) {
                            r0 += __shfl_xor_sync(0xFFFFFFFFu, r0, o);
                            r1 += __shfl_xor_sync(0xFFFFFFFFu, r1, o);
                            r2 += __shfl_xor_sync(0xFFFFFFFFu, r2, o);
                        }
                        if (lid == 0) {
                            sf[XG_RED + wid * 3]     = r0;
                            sf[XG_RED + wid * 3 + 1] = r1;
                            sf[XG_RED + wid * 3 + 2] = r2;
                        }
                        __syncthreads();
                        if (c < 3) {
                            float s = 0.f;
                            #pragma unroll
                            for (int w = 0; w < 8; w++) s += sf[XG_RED + w * 3 + c];
                            g_dv[n * 3 + c] = s;
                        }
                        __syncthreads();
                    } else {
                        int slot = (segStart == 0) ? 0 : 1;
                        g_phe[((size_t)blk * 2 + slot) * 256 + c] = accH;
                        g_pcomb[(((size_t)blk * 2 + slot) * 3 + 0) * 256 + c] = a0;
                        g_pcomb[(((size_t)blk * 2 + slot) * 3 + 1) * 256 + c] = a1;
                        g_pcomb[(((size_t)blk * 2 + slot) * 3 + 2) * 256 + c] = a2;
                    }
                }
                accH = 0.f; a0 = 0.f; a1 = 0.f; a2 = 0.f;
                segStart = sl + 1;
            }
        }
    }
}

// ---------------- K_fin: finish boundary + empty nodes ----------------
__global__ void k_fin(const float* __restrict__ W_vmix, int N) {
    __shared__ float red[24];
    int n = blockIdx.x;
    int c = threadIdx.x, lid = c & 31, wid = c >> 5;
    int beg = g_off[n], end = g_off[n + 1];
    if (end == beg) {
        g_he[n * 256 + c] = 0.f;
        g_cnorm[n * 256 + c] = 0.f;
        if (c < 3) g_dv[n * 3 + c] = 0.f;
        return;
    }
    int b0 = beg >> 6, b1 = (end - 1) >> 6;
    if (b0 == b1) return;

    float accH = 0.f, a0 = 0.f, a1 = 0.f, a2 = 0.f;
    for (int b = b0; b <= b1; b++) {
        int slot = (b == b0 && (beg & 63) != 0) ? 1 : 0;
        size_t base = ((size_t)b * 2 + slot);
        accH += g_phe[base * 256 + c];
        a0 += g_pcomb[(base * 3 + 0) * 256 + c];
        a1 += g_pcomb[(base * 3 + 1) * 256 + c];
        a2 += g_pcomb[(base * 3 + 2) * 256 + c];
    }
    g_he[n * 256 + c] = accH;
    float invc = 1.f / ((float)(end - beg) + 1.f);
    float s0 = a0 * invc, s1 = a1 * invc, s2 = a2 * invc;
    g_cnorm[n * 256 + c] = s0 * s0 + s1 * s1 + s2 * s2;
    float wv = W_vmix[c];
    float r0 = wv * s0, r1 = wv * s1, r2 = wv * s2;
    #pragma unroll
    for (int o = 16; o > 0; o >>= 1) {
        r0 += __shfl_xor_sync(0xFFFFFFFFu, r0, o);
        r1 += __shfl_xor_sync(0xFFFFFFFFu, r1, o);
        r2 += __shfl_xor_sync(0xFFFFFFFFu, r2, o);
    }
    if (lid == 0) { red[wid * 3] = r0; red[wid * 3 + 1] = r1; red[wid * 3 + 2] = r2; }
    __syncthreads();
    if (c < 3) {
        float s = 0.f;
        #pragma unroll
        for (int w = 0; w < 8; w++) s += red[w * 3 + c];
        g_dv[n * 3 + c] = s;
    }
}

// ---------------- K7: node MLPs via fp16 mma.sync ----------------
// smem u32 offsets
#define NO_CN   0        // 32*132 A fp16 (cnorm)
#define NO_N3   4224     // 32*196 A fp16 (concat h|he|hcomb)
#define NO_T    10496    // 32*36 fp16
#define NO_HN   11648    // 32*36 fp16 (h_new)
#define NO_H    12800    // 32*64 f32 (h, then S5 out)
#define NO_B    14848    // 384 f32 biases
#define NO_W    15232    // 12544 max (64*196)
#define N_SMEM  (27776 * 4)

#define NODE_GEMM(ABASE, ASTRIDE, BSTRIDE, KSTEPS, ACC) \
    { uint32_t adA = sbase + ((ABASE) + (mrow + (mq & 1) * 8 + rr) * (ASTRIDE) + (mq >> 1) * 4) * 4; \
      uint32_t adB = sbase + (NO_W + (ncol + (mq >> 1) * 8 + rr) * (BSTRIDE) + (mq & 1) * 4) * 4; \
      _Pragma("unroll 4") \
      for (int ks = 0; ks < (KSTEPS); ks++) { \
          uint32_t aH[4]; \
          LDSM4(aH[0], aH[1], aH[2], aH[3], adA + ks * 32); \
          uint32_t b0, b1, b2, b3; \
          LDSM4(b0, b1, b2, b3, adB + ks * 32); \
          { uint32_t bb[2] = { b0, b1 }; mma16816h(ACC[0], aH, bb); } \
          { uint32_t bb[2] = { b2, b3 }; mma16816h(ACC[1], aH, bb); } \
      } }

__global__ void __launch_bounds__(256, 2)
k_node(const float* __restrict__ h, const float* __restrict__ x,
       const float* __restrict__ v,
       const float* __restrict__ b_post1, const float* __restrict__ b_post2,
       const float* __restrict__ b_node1, const float* __restrict__ b_node2,
       const float* __restrict__ b_vel1,  const float* __restrict__ W_vel2,
       float* __restrict__ out_h, float* __restrict__ out_x,
       float* __restrict__ out_v, int N)
{
    extern __shared__ uint32_t su[];
    float* sf = (float*)su;
    int tid = threadIdx.x, lid = tid & 31, wid = tid >> 5;
    int g = lid >> 2, tg = lid & 3;
    int mq = lid >> 3, rr = lid & 7;
    int mrow = (wid & 1) * 16;
    int ncol = (wid >> 1) * 16;
    int n0 = blockIdx.x * 32;
    int nn = min(32, N - n0);
    uint32_t sbase = smem_u32(su);

    if (tid < 64) {
        sf[NO_B + tid]       = b_post1[tid];
        sf[NO_B + 64 + tid]  = b_post2[tid];
        sf[NO_B + 128 + tid] = b_node1[tid];
        sf[NO_B + 192 + tid] = b_node2[tid];
        sf[NO_B + 256 + tid] = b_vel1[tid];
        sf[NO_B + 320 + tid] = W_vel2[tid];
    }
    // A inputs: cnorm -> NO_CN; he -> NO_N3[64..319]; h -> NO_N3[0..63] + NO_H f32
    for (int i = tid; i < 4096; i += 256) {
        int row = i >> 7, kp = i & 127;
        float2 c2 = make_float2(0.f, 0.f), e2 = make_float2(0.f, 0.f);
        if (row < nn) {
            c2 = *(const float2*)&g_cnorm[(size_t)(n0 + row) * 256 + 2 * kp];
            e2 = *(const float2*)&g_he[(size_t)(n0 + row) * 256 + 2 * kp];
        }
        su[NO_CN + row * 132 + kp]      = pack2h(c2.x, c2.y);
        su[NO_N3 + row * 196 + 32 + kp] = pack2h(e2.x, e2.y);
    }
    for (int i = tid; i < 1024; i += 256) {
        int row = i >> 5, kp = i & 31;
        float2 h2 = make_float2(0.f, 0.f);
        if (row < nn) h2 = *(const float2*)&h[(n0 + row) * 64 + 2 * kp];
        sf[NO_H + row * 64 + 2 * kp]     = h2.x;
        sf[NO_H + row * 64 + 2 * kp + 1] = h2.y;
        su[NO_N3 + row * 196 + kp] = pack2h(h2.x, h2.y);
    }
    // stage-1 W load (with inputs, one barrier)
    for (int i = tid; i < 8192; i += 256) {
        int n = i >> 7, kp = i & 127;
        su[NO_W + n * 132 + kp] = g_nwp1[i];
    }
    __syncthreads();

    float acc[2][4];
    int r0 = mrow + g, r1 = r0 + 8;

    // ---- S1: t1 = silu(cnorm @ Wp1 + b)  K=256 ----
    #pragma unroll
    for (int nt = 0; nt < 2; nt++)
        #pragma unroll
        for (int q = 0; q < 4; q++) acc[nt][q] = 0.f;
    NODE_GEMM(NO_CN, 132, 132, 16, acc)
    #pragma unroll
    for (int nt = 0; nt < 2; nt++) {
        int c0 = ncol + nt * 8 + tg * 2;
        float b0v = sf[NO_B + c0], b1v = sf[NO_B + c0 + 1];
        su[NO_T + r0 * 36 + (c0 >> 1)] = pack2h(siluf(acc[nt][0] + b0v), siluf(acc[nt][1] + b1v));
        su[NO_T + r1 * 36 + (c0 >> 1)] = pack2h(siluf(acc[nt][2] + b0v), siluf(acc[nt][3] + b1v));
    }
    __syncthreads();

    // ---- S2: h_comb = silu(t1 @ Wp2 + b) -> NO_N3 cols 320..383 ----
    for (int i = tid; i < 2048; i += 256) su[NO_W + (i >> 5) * 36 + (i & 31)] = g_nwp2[i];
    __syncthreads();
    #pragma unroll
    for (int nt = 0; nt < 2; nt++)
        #pragma unroll
        for (int q = 0; q < 4; q++) acc[nt][q] = 0.f;
    NODE_GEMM(NO_T, 36, 36, 4, acc)
    #pragma unroll
    for (int nt = 0; nt < 2; nt++) {
        int c0 = ncol + nt * 8 + tg * 2;
        float b0v = sf[NO_B + 64 + c0], b1v = sf[NO_B + 64 + c0 + 1];
        su[NO_N3 + r0 * 196 + 160 + (c0 >> 1)] = pack2h(siluf(acc[nt][0] + b0v), siluf(acc[nt][1] + b1v));
        su[NO_N3 + r1 * 196 + 160 + (c0 >> 1)] = pack2h(siluf(acc[nt][2] + b0v), siluf(acc[nt][3] + b1v));
    }
    __syncthreads();

    // ---- S3: t2 = silu(concat @ Wn1 + b)  K=384 ----
    for (int i = tid; i < 12288; i += 256) su[NO_W + (i / 192) * 196 + (i % 192)] = g_nwn1[i];
    __syncthreads();
    #pragma unroll
    for (int nt = 0; nt < 2; nt++)
        #pragma unroll
        for (int q = 0; q < 4; q++) acc[nt][q] = 0.f;
    NODE_GEMM(NO_N3, 196, 196, 24, acc)
    #pragma unroll
    for (int nt = 0; nt < 2; nt++) {
        int c0 = ncol + nt * 8 + tg * 2;
        float b0v = sf[NO_B + 128 + c0], b1v = sf[NO_B + 128 + c0 + 1];
        su[NO_T + r0 * 36 + (c0 >> 1)] = pack2h(siluf(acc[nt][0] + b0v), siluf(acc[nt][1] + b1v));
        su[NO_T + r1 * 36 + (c0 >> 1)] = pack2h(siluf(acc[nt][2] + b0v), siluf(acc[nt][3] + b1v));
    }
    __syncthreads();

    // ---- S4: h_new = h + silu(t2 @ Wn2 + b) ----
    for (int i = tid; i < 2048; i += 256) su[NO_W + (i >> 5) * 36 + (i & 31)] = g_nwn2[i];
    __syncthreads();
    #pragma unroll
    for (int nt = 0; nt < 2; nt++)
        #pragma unroll
        for (int q = 0; q < 4; q++) acc[nt][q] = 0.f;
    NODE_GEMM(NO_T, 36, 36, 4, acc)
    #pragma unroll
    for (int nt = 0; nt < 2; nt++) {
        int c0 = ncol + nt * 8 + tg * 2;
        float b0v = sf[NO_B + 192 + c0], b1v = sf[NO_B + 192 + c0 + 1];
        float v00 = sf[NO_H + r0 * 64 + c0]     + siluf(acc[nt][0] + b0v);
        float v01 = sf[NO_H + r0 * 64 + c0 + 1] + siluf(acc[nt][1] + b1v);
        float v10 = sf[NO_H + r1 * 64 + c0]     + siluf(acc[nt][2] + b0v);
        float v11 = sf[NO_H + r1 * 64 + c0 + 1] + siluf(acc[nt][3] + b1v);
        su[NO_HN + r0 * 36 + (c0 >> 1)] = pack2h(v00, v01);
        su[NO_HN + r1 * 36 + (c0 >> 1)] = pack2h(v10, v11);
        if (r0 < nn) *(float2*)&out_h[(n0 + r0) * 64 + c0] = make_float2(v00, v01);
        if (r1 < nn) *(float2*)&out_h[(n0 + r1) * 64 + c0] = make_float2(v10, v11);
    }
    __syncthreads();

    // ---- S5: t3 = silu(h_new @ Wv1 + b) * Wv2 -> NO_H (f32) ----
    for (int i = tid; i < 2048; i += 256) su[NO_W + (i >> 5) * 36 + (i & 31)] = g_nwv1[i];
    __syncthreads();
    #pragma unroll
    for (int nt = 0; nt < 2; nt++)
        #pragma unroll
        for (int q = 0; q < 4; q++) acc[nt][q] = 0.f;
    NODE_GEMM(NO_HN, 36, 36, 4, acc)
    #pragma unroll
    for (int nt = 0; nt < 2; nt++) {
        int c0 = ncol + nt * 8 + tg * 2;
        float b0v = sf[NO_B + 256 + c0], b1v = sf[NO_B + 256 + c0 + 1];
        float w0v = sf[NO_B + 320 + c0], w1v = sf[NO_B + 320 + c0 + 1];
        sf[NO_H + r0 * 64 + c0]     = siluf(acc[nt][0] + b0v) * w0v;
        sf[NO_H + r0 * 64 + c0 + 1] = siluf(acc[nt][1] + b1v) * w1v;
        sf[NO_H + r1 * 64 + c0]     = siluf(acc[nt][2] + b0v) * w0v;
        sf[NO_H + r1 * 64 + c0 + 1] = siluf(acc[nt][3] + b1v) * w1v;
    }
    __syncthreads();

    if (tid < nn) {
        int ln = tid;
        float s = 0.f;
        #pragma unroll 8
        for (int k = 0; k < 64; k++) s += sf[NO_H + ln * 64 + k];
        float scale = 2.f / (1.f + __expf(-s));
        int n = n0 + ln;
        #pragma unroll
        for (int d = 0; d < 3; d++) {
            float vn = g_dv[n * 3 + d] + scale * v[n * 3 + d];
            out_v[n * 3 + d] = vn;
            out_x[n * 3 + d] = x[n * 3 + d] + vn;
        }
    }
}

// ---------------- launch ----------------
extern "C" void kernel_launch(void* const* d_in, const int* in_sizes, int n_in,
                              void* d_out, int out_size)
{
    const float* h        = (const float*)d_in[0];
    const float* x        = (const float*)d_in[1];
    const float* v        = (const float*)d_in[2];
    const int*   idxs     = (const int*)  d_in[3];
    const float* rbf_mean = (const float*)d_in[4];
    const float* rbf_beta = (const float*)d_in[5];
    const float* W_in     = (const float*)d_in[6];
    const float* b_in     = (const float*)d_in[7];
    const float* W_out1   = (const float*)d_in[8];
    const float* b_out1   = (const float*)d_in[9];
    const float* W_out2   = (const float*)d_in[10];
    const float* b_out2   = (const float*)d_in[11];
    const float* W_att    = (const float*)d_in[12];
    const float* b_att    = (const float*)d_in[13];
    const float* W_xmix   = (const float*)d_in[14];
    const float* W_post1  = (const float*)d_in[15];
    const float* b_post1  = (const float*)d_in[16];
    const float* W_post2  = (const float*)d_in[17];
    const float* b_post2  = (const float*)d_in[18];
    const float* W_node1  = (const float*)d_in[19];
    const float* b_node1  = (const float*)d_in[20];
    const float* W_node2  = (const float*)d_in[21];
    const float* b_node2  = (const float*)d_in[22];
    const float* W_vmix   = (const float*)d_in[23];
    const float* W_vel1   = (const float*)d_in[24];
    const float* b_vel1   = (const float*)d_in[25];
    const float* W_vel2   = (const float*)d_in[26];

    int N = in_sizes[0] / 64;
    int E = in_sizes[3] / 2;

    float* out  = (float*)d_out;
    float* outh = out;
    float* outx = out + (size_t)N * 64;
    float* outv = out + (size_t)N * 67;

    cudaFuncSetAttribute(k_edge_mma, cudaFuncAttributeMaxDynamicSharedMemorySize, E_SMEM);
    cudaFuncSetAttribute(k_xagg,     cudaFuncAttributeMaxDynamicSharedMemorySize, XG_SMEM);
    cudaFuncSetAttribute(k_node,     cudaFuncAttributeMaxDynamicSharedMemorySize, N_SMEM);

    k_init<<<256, 256>>>(N, W_xmix, W_in, W_out1, W_out2,
                         W_post1, W_post2, W_node1, W_node2, W_vel1);
    k_edge_mma<<<296, 256, E_SMEM>>>(h, x, idxs, rbf_mean, rbf_beta,
                                     b_in, b_out1, b_out2, W_att, b_att, E);
    k_scan<<<1, 1024>>>(N);
    k_fill<<<(E + 255) / 256, 256>>>(idxs, E);
    k_xagg<<<(E + 63) / 64, 256, XG_SMEM>>>(idxs, W_vmix, E);
    k_fin<<<N, 256>>>(W_vmix, N);
    k_node<<<(N + 31) / 32, 256, N_SMEM>>>(h, x, v,
                                           b_post1, b_post2, b_node1, b_node2,
                                           b_vel1, W_vel2,
                                           outh, outx, outv, N);
}

// round 16
// speedup vs baseline: 1.3056x; 1.0093x over previous
#include <cuda_runtime.h>
#include <cuda_fp16.h>
#include <stdint.h>
#include <math.h>

#define NMAX 10000
#define EMAX 160000
#define NBLK ((EMAX + 63) / 64)

// ---------------- scratch ----------------
__device__ uint32_t g_hemtx2[EMAX * 32];     // h_e_mtx fp16x2 [e][32]
__device__ float g_xhat[EMAX * 3];
__device__ float g_w[EMAX * 4];
__device__ float g_expsum[NMAX * 4];
__device__ int   g_counts[NMAX];
__device__ int   g_off[NMAX + 1];
__device__ int   g_cursor[NMAX];
__device__ int   g_eid[EMAX];
__device__ float g_he[NMAX * 256];
__device__ float g_cnorm[NMAX * 256];
__device__ float g_dv[NMAX * 3];
__device__ float g_phe[NBLK * 2 * 256];
__device__ float g_pcomb[NBLK * 2 * 3 * 256];
__device__ __half g_wx[256 * 256];           // W_xmix^T fp16 [n][k]
__device__ uint32_t g_ewi[4096];
__device__ uint32_t g_ew1a[4096];
__device__ uint32_t g_ew1b[2048];
__device__ uint32_t g_ew2[2048];
// node-MLP weights, fp16x2 [n][k]
__device__ uint32_t g_nwp1[8192];
__device__ uint32_t g_nwn1[12288];
__device__ uint32_t g_nwp2[2048];
__device__ uint32_t g_nwn2[2048];
__device__ uint32_t g_nwv1[2048];

__device__ __forceinline__ float siluf(float x) { return x / (1.f + __expf(-x)); }
__device__ __forceinline__ float fast_tanh(float x) {
    float y; asm("tanh.approx.f32 %0, %1;" : "=f"(y) : "f"(x)); return y;
}
__device__ __forceinline__ void mma16816h(float* d, const uint32_t* a, const uint32_t* b) {
    asm volatile("mma.sync.aligned.m16n8k16.row.col.f32.f16.f16.f32 "
        "{%0,%1,%2,%3}, {%4,%5,%6,%7}, {%8,%9}, {%0,%1,%2,%3};"
        : "+f"(d[0]), "+f"(d[1]), "+f"(d[2]), "+f"(d[3])
        : "r"(a[0]), "r"(a[1]), "r"(a[2]), "r"(a[3]), "r"(b[0]), "r"(b[1]));
}
__device__ __forceinline__ uint32_t pack2h(float a, float b) {
    __half2 p = __floats2half2_rn(a, b);
    return *(uint32_t*)&p;
}
__device__ __forceinline__ uint32_t smem_u32(const void* p) {
    uint32_t a;
    asm("{ .reg .u64 t; cvta.to.shared.u64 t, %1; cvt.u32.u64 %0, t; }" : "=r"(a) : "l"(p));
    return a;
}
#define LDSM4(r0, r1, r2, r3, addr) \
    asm volatile("ldmatrix.sync.aligned.m8n8.x4.shared.b16 {%0,%1,%2,%3}, [%4];" \
        : "=r"(r0), "=r"(r1), "=r"(r2), "=r"(r3) : "r"(addr))
#define CP_ASYNC16(dst, src) \
    asm volatile("cp.async.cg.shared.global [%0], [%1], 16;" :: "r"(dst), "l"(src) : "memory")
#define CP_COMMIT() asm volatile("cp.async.commit_group;" ::: "memory")
#define CP_WAIT0()  asm volatile("cp.async.wait_group 0;" ::: "memory")

// ---------------- K0: init + weight prep ----------------
__global__ void k_init(int N,
                       const float* __restrict__ W_xmix,
                       const float* __restrict__ W_in,
                       const float* __restrict__ W_out1,
                       const float* __restrict__ W_out2,
                       const float* __restrict__ W_post1,
                       const float* __restrict__ W_post2,
                       const float* __restrict__ W_node1,
                       const float* __restrict__ W_node2,
                       const float* __restrict__ W_vel1) {
    int i = blockIdx.x * blockDim.x + threadIdx.x;
    if (i < N * 4) g_expsum[i] = 0.f;
    if (i < N) g_counts[i] = 0;
    if (i < 65536) {
        int n = i >> 8, k = i & 255;
        g_wx[n * 256 + k] = __float2half_rn(W_xmix[k * 256 + n]);
    }
    if (i < 4096) {
        int n = i >> 6, k0 = (i & 63) * 2;
        float w0 = (n < 50) ? W_in[k0 * 50 + n] : 0.f;
        float w1 = (n < 50) ? W_in[(k0 + 1) * 50 + n] : 0.f;
        g_ewi[i] = pack2h(w0, w1);
    } else if (i < 8192) {
        int j = i - 4096;
        int n = j >> 6, k0 = (j & 63) * 2;
        g_ew1a[j] = pack2h(W_out1[k0 * 64 + n], W_out1[(k0 + 1) * 64 + n]);
    } else if (i < 10240) {
        int j = i - 8192;
        int n = j >> 5, k0 = (j & 31) * 2;
        float w0 = (k0 < 50) ? W_out1[(128 + k0) * 64 + n] : ((k0 == 50) ? W_out1[178 * 64 + n] : 0.f);
        int k1 = k0 + 1;
        float w1 = (k1 < 50) ? W_out1[(128 + k1) * 64 + n] : ((k1 == 50) ? W_out1[178 * 64 + n] : 0.f);
        g_ew1b[j] = pack2h(w0, w1);
    } else if (i < 12288) {
        int j = i - 10240;
        int n = j >> 5, k0 = (j & 31) * 2;
        g_ew2[j] = pack2h(W_out2[k0 * 64 + n], W_out2[(k0 + 1) * 64 + n]);
    } else if (i < 20480) {
        int j = i - 12288;
        int n = j >> 7, k0 = (j & 127) * 2;
        g_nwp1[j] = pack2h(W_post1[k0 * 64 + n], W_post1[(k0 + 1) * 64 + n]);
    } else if (i < 32768) {
        int j = i - 20480;
        int n = j / 192, kp = j % 192, k0 = kp * 2;
        g_nwn1[j] = pack2h(W_node1[k0 * 64 + n], W_node1[(k0 + 1) * 64 + n]);
    } else if (i < 34816) {
        int j = i - 32768;
        int n = j >> 5, k0 = (j & 31) * 2;
        g_nwp2[j] = pack2h(W_post2[k0 * 64 + n], W_post2[(k0 + 1) * 64 + n]);
    } else if (i < 36864) {
        int j = i - 34816;
        int n = j >> 5, k0 = (j & 31) * 2;
        g_nwn2[j] = pack2h(W_node2[k0 * 64 + n], W_node2[(k0 + 1) * 64 + n]);
    } else if (i < 38912) {
        int j = i - 36864;
        int n = j >> 5, k0 = (j & 31) * 2;
        g_nwv1[j] = pack2h(W_vel1[k0 * 64 + n], W_vel1[(k0 + 1) * 64 + n]);
    }
}

// ---------------- K1: edge MLP via fp16 mma.sync + ldmatrix (fused exp/expsum) ----------------
#define O_A     0
#define O_X     4352
#define O_M     6656
#define O_WI    8960
#define O_W1A   13312
#define O_W1B   17664
#define O_W2    19968
#define O_HE    22272
#define O_BIN   26496
#define O_BO1   26560
#define O_BO2   26624
#define O_MEAN  26688
#define O_BETA  26752
#define O_WA    26816
#define O_BA    27072
#define O_NORM  27076
#define O_EX    27140
#define O_XHT   27204
#define E_SMEM  (27400 * 4)

__global__ void __launch_bounds__(256, 2)
k_edge_mma(const float* __restrict__ h, const float* __restrict__ x,
           const int* __restrict__ idxs,
           const float* __restrict__ rbf_means, const float* __restrict__ rbf_betas,
           const float* __restrict__ b_in, const float* __restrict__ b_out1,
           const float* __restrict__ b_out2,
           const float* __restrict__ W_att, const float* __restrict__ b_att, int E)
{
    extern __shared__ uint32_t su[];
    float* sf = (float*)su;
    int tid = threadIdx.x, lid = tid & 31, wid = tid >> 5;
    int g = lid >> 2, tg = lid & 3;
    int mrow = (wid & 3) * 16, ncol = (wid >> 2) * 32;

    for (int i = tid; i < 4096; i += 256) {
        int n = i >> 6, kk = i & 63;
        su[O_WI  + n * 68 + kk] = g_ewi[i];
        su[O_W1A + n * 68 + kk] = g_ew1a[i];
    }
    for (int i = tid; i < 2048; i += 256) {
        int n = i >> 5, kk = i & 31;
        su[O_W1B + n * 36 + kk] = g_ew1b[i];
        su[O_W2  + n * 36 + kk] = g_ew2[i];
    }
    if (tid < 64) {
        sf[O_BIN + tid]  = (tid < 50) ? b_in[tid] : 0.f;
        sf[O_BO1 + tid]  = b_out1[tid];
        sf[O_BO2 + tid]  = b_out2[tid];
        sf[O_MEAN + tid] = (tid < 50) ? rbf_means[tid] : 0.f;
        sf[O_BETA + tid] = (tid < 50) ? rbf_betas[tid] : 1.f;
    }
    if (tid < 256) sf[O_WA + tid] = W_att[tid];
    if (tid < 4)   sf[O_BA + tid] = b_att[tid];
    __syncthreads();

    uint32_t sbase = smem_u32(su);
    int mq = lid >> 3, rr = lid & 7;
    int rA = mrow + (mq & 1) * 8 + rr;
    int cA = (mq >> 1) * 4;
    uint32_t adA  = sbase + (O_A  + rA * 68 + cA) * 4;
    uint32_t adX  = sbase + (O_X  + rA * 36 + cA) * 4;
    uint32_t adM  = sbase + (O_M  + rA * 36 + cA) * 4;
    int rB = (mq >> 1) * 8 + rr;
    int cB = (mq & 1) * 4;
    uint32_t adWI0  = sbase + (O_WI  + (ncol + rB) * 68 + cB) * 4;
    uint32_t adWI1  = sbase + (O_WI  + (ncol + 16 + rB) * 68 + cB) * 4;
    uint32_t adW1A0 = sbase + (O_W1A + (ncol + rB) * 68 + cB) * 4;
    uint32_t adW1A1 = sbase + (O_W1A + (ncol + 16 + rB) * 68 + cB) * 4;
    uint32_t adW1B0 = sbase + (O_W1B + (ncol + rB) * 36 + cB) * 4;
    uint32_t adW1B1 = sbase + (O_W1B + (ncol + 16 + rB) * 36 + cB) * 4;
    uint32_t adW20  = sbase + (O_W2  + (ncol + rB) * 36 + cB) * 4;
    uint32_t adW21  = sbase + (O_W2  + (ncol + 16 + rB) * 36 + cB) * 4;

    int ntiles = (E + 63) / 64;
    for (int tile = blockIdx.x; tile < ntiles; tile += gridDim.x) {
        int e0 = tile * 64, ne = min(64, E - e0);

        if (tid < 64) {
            float nrm = 0.f, xh0 = 0.f, xh1 = 0.f, xh2 = 0.f;
            if (tid < ne) {
                int s = idxs[2 * (e0 + tid)], d = idxs[2 * (e0 + tid) + 1];
                float dx = x[3 * s]     - x[3 * d];
                float dy = x[3 * s + 1] - x[3 * d + 1];
                float dz = x[3 * s + 2] - x[3 * d + 2];
                nrm = sqrtf(dx * dx + dy * dy + dz * dz + 1e-14f);
                float inv = 1.f / (nrm + 1e-5f);
                xh0 = dx * inv; xh1 = dy * inv; xh2 = dz * inv;
                atomicAdd(&g_counts[s], 1);
            }
            sf[O_NORM + tid] = nrm;
            sf[O_EX + tid]   = __expf(-nrm);
            sf[O_XHT + tid * 3] = xh0; sf[O_XHT + tid * 3 + 1] = xh1; sf[O_XHT + tid * 3 + 2] = xh2;
        }
        {
            int el = tid >> 2, part = tid & 3;
            uint32_t hb[16];
            if (el < ne) {
                int node = idxs[2 * (e0 + el) + (part >> 1)];
                const float4* hp = (const float4*)&h[node * 64 + (part & 1) * 32];
                #pragma unroll
                for (int i2 = 0; i2 < 8; i2++) {
                    float4 v = hp[i2];
                    hb[i2 * 2]     = pack2h(v.x, v.y);
                    hb[i2 * 2 + 1] = pack2h(v.z, v.w);
                }
            } else {
                #pragma unroll
                for (int i2 = 0; i2 < 16; i2++) hb[i2] = 0u;
            }
            uint4* dh = (uint4*)&su[O_A + el * 68 + part * 16];
            #pragma unroll
            for (int i2 = 0; i2 < 4; i2++)
                dh[i2] = make_uint4(hb[i2*4], hb[i2*4+1], hb[i2*4+2], hb[i2*4+3]);
        }
        __syncthreads();

        float acc[4][4];

        // ---- G1 ----
        #pragma unroll
        for (int nt = 0; nt < 4; nt++)
            #pragma unroll
            for (int q = 0; q < 4; q++) acc[nt][q] = 0.f;
        #pragma unroll
        for (int ks = 0; ks < 8; ks++) {
            uint32_t aH[4];
            LDSM4(aH[0], aH[1], aH[2], aH[3], adA + ks * 32);
            uint32_t b0, b1, b2, b3;
            LDSM4(b0, b1, b2, b3, adWI0 + ks * 32);
            { uint32_t bb[2] = { b0, b1 }; mma16816h(acc[0], aH, bb); }
            { uint32_t bb[2] = { b2, b3 }; mma16816h(acc[1], aH, bb); }
            LDSM4(b0, b1, b2, b3, adWI1 + ks * 32);
            { uint32_t bb[2] = { b0, b1 }; mma16816h(acc[2], aH, bb); }
            { uint32_t bb[2] = { b2, b3 }; mma16816h(acc[3], aH, bb); }
        }
        #pragma unroll
        for (int nt = 0; nt < 4; nt++) {
            #pragma unroll
            for (int hh = 0; hh < 2; hh++) {
                int row = mrow + g + hh * 8;
                int c0 = ncol + nt * 8 + tg * 2;
                float v0 = acc[nt][hh * 2]     + sf[O_BIN + c0];
                float v1 = acc[nt][hh * 2 + 1] + sf[O_BIN + c0 + 1];
                float ex = sf[O_EX + row];
                float x0, x1;
                if (c0 < 50) { float d = ex - sf[O_MEAN + c0]; x0 = __expf(-sf[O_BETA + c0] * d * d) * v0; }
                else x0 = (c0 == 50) ? sf[O_NORM + row] : 0.f;
                if (c0 + 1 < 50) { float d = ex - sf[O_MEAN + c0 + 1]; x1 = __expf(-sf[O_BETA + c0 + 1] * d * d) * v1; }
                else x1 = 0.f;
                su[O_X + row * 36 + (c0 >> 1)] = pack2h(x0, x1);
            }
        }
        __syncthreads();

        // ---- G2 ----
        #pragma unroll
        for (int nt = 0; nt < 4; nt++)
            #pragma unroll
            for (int q = 0; q < 4; q++) acc[nt][q] = 0.f;
        #pragma unroll
        for (int ks = 0; ks < 8; ks++) {
            uint32_t aH[4];
            LDSM4(aH[0], aH[1], aH[2], aH[3], adA + ks * 32);
            uint32_t b0, b1, b2, b3;
            LDSM4(b0, b1, b2, b3, adW1A0 + ks * 32);
            { uint32_t bb[2] = { b0, b1 }; mma16816h(acc[0], aH, bb); }
            { uint32_t bb[2] = { b2, b3 }; mma16816h(acc[1], aH, bb); }
            LDSM4(b0, b1, b2, b3, adW1A1 + ks * 32);
            { uint32_t bb[2] = { b0, b1 }; mma16816h(acc[2], aH, bb); }
            { uint32_t bb[2] = { b2, b3 }; mma16816h(acc[3], aH, bb); }
        }
        #pragma unroll
        for (int ks = 0; ks < 4; ks++) {
            uint32_t aH[4];
            LDSM4(aH[0], aH[1], aH[2], aH[3], adX + ks * 32);
            uint32_t b0, b1, b2, b3;
            LDSM4(b0, b1, b2, b3, adW1B0 + ks * 32);
            { uint32_t bb[2] = { b0, b1 }; mma16816h(acc[0], aH, bb); }
            { uint32_t bb[2] = { b2, b3 }; mma16816h(acc[1], aH, bb); }
            LDSM4(b0, b1, b2, b3, adW1B1 + ks * 32);
            { uint32_t bb[2] = { b0, b1 }; mma16816h(acc[2], aH, bb); }
            { uint32_t bb[2] = { b2, b3 }; mma16816h(acc[3], aH, bb); }
        }
        #pragma unroll
        for (int nt = 0; nt < 4; nt++) {
            #pragma unroll
            for (int hh = 0; hh < 2; hh++) {
                int row = mrow + g + hh * 8;
                int c0 = ncol + nt * 8 + tg * 2;
                float m0 = siluf(acc[nt][hh * 2]     + sf[O_BO1 + c0]);
                float m1 = siluf(acc[nt][hh * 2 + 1] + sf[O_BO1 + c0 + 1]);
                su[O_M + row * 36 + (c0 >> 1)] = pack2h(m0, m1);
            }
        }
        __syncthreads();

        // ---- G3 ----
        #pragma unroll
        for (int nt = 0; nt < 4; nt++)
            #pragma unroll
            for (int q = 0; q < 4; q++) acc[nt][q] = 0.f;
        #pragma unroll
        for (int ks = 0; ks < 4; ks++) {
            uint32_t aH[4];
            LDSM4(aH[0], aH[1], aH[2], aH[3], adM + ks * 32);
            uint32_t b0, b1, b2, b3;
            LDSM4(b0, b1, b2, b3, adW20 + ks * 32);
            { uint32_t bb[2] = { b0, b1 }; mma16816h(acc[0], aH, bb); }
            { uint32_t bb[2] = { b2, b3 }; mma16816h(acc[1], aH, bb); }
            LDSM4(b0, b1, b2, b3, adW21 + ks * 32);
            { uint32_t bb[2] = { b0, b1 }; mma16816h(acc[2], aH, bb); }
            { uint32_t bb[2] = { b2, b3 }; mma16816h(acc[3], aH, bb); }
        }
        #pragma unroll
        for (int nt = 0; nt < 4; nt++) {
            #pragma unroll
            for (int hh = 0; hh < 2; hh++) {
                int row = mrow + g + hh * 8;
                int c0 = ncol + nt * 8 + tg * 2;
                sf[O_HE + row * 66 + c0]     = acc[nt][hh * 2]     + sf[O_BO2 + c0];
                sf[O_HE + row * 66 + c0 + 1] = acc[nt][hh * 2 + 1] + sf[O_BO2 + c0 + 1];
            }
        }
        __syncthreads();

        // att: logits -> exp -> g_w, expsum
        {
            int el = tid >> 2, a = tid & 3;
            if (el < ne) {
                float acc2 = sf[O_BA + a];
                const float* hv = &sf[O_HE + el * 66];
                #pragma unroll 8
                for (int c = 0; c < 64; c++) acc2 += hv[c] * sf[O_WA + c * 4 + a];
                float lg = (acc2 > 0.f) ? acc2 : 2.f * (__expf(acc2 * 0.5f) - 1.f);
                float w = __expf(lg);
                int s = idxs[2 * (e0 + el)];
                g_w[(e0 + el) * 4 + a] = w;
                atomicAdd(&g_expsum[s * 4 + a], w);
            }
        }
        // hemtx writeback as fp16x2
        for (int i = tid; i < ne * 8; i += 256) {
            int el = i >> 3, c8 = (i & 7) * 8;
            const float* hv = &sf[O_HE + el * 66 + c8];
            uint4 o = make_uint4(pack2h(hv[0], hv[1]), pack2h(hv[2], hv[3]),
                                 pack2h(hv[4], hv[5]), pack2h(hv[6], hv[7]));
            *(uint4*)&g_hemtx2[(size_t)(e0 + el) * 32 + (c8 >> 1)] = o;
        }
        for (int i = tid; i < ne * 3; i += 256) g_xhat[e0 * 3 + i] = sf[O_XHT + i];
        __syncthreads();
    }
}

// ---------------- K2: exclusive scan (shuffle-based) ----------------
__global__ void k_scan(int N) {
    __shared__ int wsum[32];
    int t = threadIdx.x, lane = t & 31, w = t >> 5;
    int chunk = (N + 1023) / 1024;
    int base = t * chunk;
    int vals[16];
    int loc = 0;
    for (int k = 0; k < chunk; k++) {
        int idx = base + k;
        int v = (idx < N) ? g_counts[idx] : 0;
        vals[k] = loc; loc += v;
    }
    int inc = loc;
    #pragma unroll
    for (int o = 1; o < 32; o <<= 1) {
        int v = __shfl_up_sync(0xFFFFFFFFu, inc, o);
        if (lane >= o) inc += v;
    }
    if (lane == 31) wsum[w] = inc;
    __syncthreads();
    if (w == 0) {
        int v2 = wsum[lane];
        int i2 = v2;
        #pragma unroll
        for (int o = 1; o < 32; o <<= 1) {
            int x2 = __shfl_up_sync(0xFFFFFFFFu, i2, o);
            if (lane >= o) i2 += x2;
        }
        wsum[lane] = i2 - v2;
    }
    __syncthreads();
    int excl = wsum[w] + (inc - loc);
    for (int k = 0; k < chunk; k++) {
        int idx = base + k;
        if (idx < N) { g_off[idx] = excl + vals[k]; g_cursor[idx] = excl + vals[k]; }
    }
    if (t == 1023) g_off[N] = excl + loc;
}

// ---------------- K3: CSR fill (pure) ----------------
__global__ void k_fill(const int* __restrict__ idxs, int E) {
    int e = blockIdx.x * blockDim.x + threadIdx.x;
    if (e >= E) return;
    int s = idxs[2 * e];
    int p = atomicAdd(&g_cursor[s], 1);
    g_eid[p] = e;
}

// ---------------- K5: fused xmix GEMM + aggregation ----------------
#define XG_A    0
#define XG_W0   8448
#define XG_W1   17664
#define XG_XH   26880
#define XG_NODE 27072
#define XG_WV   27136
#define XG_SDV  27392
#define XG_SEGN 27584
#define XG_SMEM (27660 * 4)

__global__ void __launch_bounds__(256, 2)
k_xagg(const int* __restrict__ idxs, const float* __restrict__ W_vmix, int E)
{
    extern __shared__ uint32_t su[];
    float* sf = (float*)su;
    int tid = threadIdx.x, lid = tid & 31, wid = tid >> 5;
    int p0 = blockIdx.x * 64;
    uint32_t* pA = su + XG_A;
    uint32_t* pC = su + XG_W0;
    int* sN = (int*)(su + XG_NODE);
    int* sSegN = (int*)(su + XG_SEGN);
    uint32_t sbase = smem_u32(su);

    {
        uint32_t dst = sbase + (XG_W0 + tid * 36) * 4;
        const char* src = (const char*)&g_wx[tid * 256];
        #pragma unroll
        for (int i = 0; i < 9; i++) CP_ASYNC16(dst + i * 16, src + i * 16);
        CP_COMMIT();
    }

    {
        int sl = tid & 63, kq = tid >> 6;
        int e = -1, s = -1;
        float att[4], hm[16];
        int p = p0 + sl;
        if (p < E) {
            e = g_eid[p];
            s = idxs[2 * e];
            #pragma unroll
            for (int a = 0; a < 4; a++) att[a] = g_w[e * 4 + a] / g_expsum[s * 4 + a];
            const uint4* hp = (const uint4*)&g_hemtx2[(size_t)e * 32 + kq * 8];
            uint4 v0 = hp[0], v1 = hp[1];
            uint32_t hraw[8] = { v0.x, v0.y, v0.z, v0.w, v1.x, v1.y, v1.z, v1.w };
            #pragma unroll
            for (int i = 0; i < 8; i++) {
                __half2 hh = *(__half2*)&hraw[i];
                hm[2 * i]     = __low2float(hh);
                hm[2 * i + 1] = __high2float(hh);
            }
        } else {
            #pragma unroll
            for (int a = 0; a < 4; a++) att[a] = 0.f;
            #pragma unroll
            for (int i = 0; i < 16; i++) hm[i] = 0.f;
        }
        if (kq == 0) {
            sN[sl] = s;
            sSegN[sl] = -1;
            float x0 = 0.f, x1 = 0.f, x2 = 0.f;
            if (e >= 0) { x0 = g_xhat[e * 3]; x1 = g_xhat[e * 3 + 1]; x2 = g_xhat[e * 3 + 2]; }
            sf[XG_XH + sl * 3] = x0; sf[XG_XH + sl * 3 + 1] = x1; sf[XG_XH + sl * 3 + 2] = x2;
        }
        #pragma unroll
        for (int j = 0; j < 32; j++) {
            int kl = 2 * j;
            float m = hm[kl >> 2];
            pA[sl * 132 + ((kq * 64 + kl) >> 1)] = pack2h(m * att[kl & 3], m * att[(kl + 1) & 3]);
        }
        sf[XG_WV + tid] = W_vmix[tid];
        if (tid < 192) sf[XG_SDV + tid] = 0.f;
    }
    CP_WAIT0();
    __syncthreads();

    int g = lid >> 2, tg = lid & 3;
    int mrow = (wid & 1) * 32;
    int ncol = (wid >> 1) * 64;

    int mq = lid >> 3, rr = lid & 7;
    uint32_t adA0 = sbase + (XG_A + (mrow + (mq & 1) * 8 + rr) * 132 + (mq >> 1) * 4) * 4;
    uint32_t adA1 = adA0 + 16 * 132 * 4;
    int rB = (mq >> 1) * 8 + rr;
    int cB = (mq & 1) * 4;
    uint32_t adW0 = sbase + (XG_W0 + (ncol + rB) * 36 + cB) * 4;
    uint32_t adW1 = adW0 + 16 * 36 * 4;
    uint32_t adW2 = adW0 + 32 * 36 * 4;
    uint32_t adW3 = adW0 + 48 * 36 * 4;
    const uint32_t BUFD = (XG_W1 - XG_W0) * 4;

    float acc[2][8][4];
    #pragma unroll
    for (int mt = 0; mt < 2; mt++)
        #pragma unroll
        for (int nt = 0; nt < 8; nt++)
            #pragma unroll
            for (int q = 0; q < 4; q++) acc[mt][nt][q] = 0.f;

    #pragma unroll
    for (int kc = 0; kc < 4; kc++) {
        if (kc < 3) {
            uint32_t dst = sbase + ((((kc + 1) & 1) ? XG_W1 : XG_W0) + tid * 36) * 4;
            const char* src = (const char*)&g_wx[tid * 256 + (kc + 1) * 64];
            #pragma unroll
            for (int i = 0; i < 9; i++) CP_ASYNC16(dst + i * 16, src + i * 16);
            CP_COMMIT();
        }
        uint32_t boff = (kc & 1) ? BUFD : 0u;
        #pragma unroll
        for (int ks = 0; ks < 4; ks++) {
            uint32_t aoff = kc * 128 + ks * 32;
            uint32_t aH[2][4];
            LDSM4(aH[0][0], aH[0][1], aH[0][2], aH[0][3], adA0 + aoff);
            LDSM4(aH[1][0], aH[1][1], aH[1][2], aH[1][3], adA1 + aoff);
            uint32_t woff = boff + ks * 32;
            uint32_t b0, b1, b2, b3;
            #define XAGG_PAIR(ADDR, NT) \
                LDSM4(b0, b1, b2, b3, (ADDR) + woff); \
                { uint32_t bb[2] = { b0, b1 }; mma16816h(acc[0][NT], aH[0], bb); mma16816h(acc[1][NT], aH[1], bb); } \
                { uint32_t bb[2] = { b2, b3 }; mma16816h(acc[0][(NT)+1], aH[0], bb); mma16816h(acc[1][(NT)+1], aH[1], bb); }
            XAGG_PAIR(adW0, 0)
            XAGG_PAIR(adW1, 2)
            XAGG_PAIR(adW2, 4)
            XAGG_PAIR(adW3, 6)
            #undef XAGG_PAIR
        }
        if (kc < 3) {
            CP_WAIT0();
            __syncthreads();
        }
    }

    #pragma unroll
    for (int mt = 0; mt < 2; mt++)
        #pragma unroll
        for (int nt = 0; nt < 8; nt++) {
            int rl = mrow + mt * 16 + g;
            int col = ncol + nt * 8 + tg * 2;
            float* a = acc[mt][nt];
            pC[rl * 132 + (col >> 1)]       = pack2h(fast_tanh(a[0]), fast_tanh(a[1]));
            pC[(rl + 8) * 132 + (col >> 1)] = pack2h(fast_tanh(a[2]), fast_tanh(a[3]));
        }
    __syncthreads();

    // ---- segmented per-node reduction; dv via smem atomics (no in-loop barriers) ----
    {
        int c = tid;
        int blk = blockIdx.x;
        float wv = sf[XG_WV + c];
        float accH = 0.f, a0 = 0.f, a1 = 0.f, a2 = 0.f;
        int segStart = 0, seg = 0;
        for (int sl = 0; sl < 64; sl++) {
            int n = sN[sl];
            if (n >= 0) {
                uint32_t ap = pA[sl * 132 + (c >> 1)];
                __half2 av2 = *(__half2*)&ap;
                float Av = (c & 1) ? __high2float(av2) : __low2float(av2);
                accH += Av;
                uint32_t cp = pC[sl * 132 + (c >> 1)];
                __half2 h2 = *(__half2*)&cp;
                float cf = (c & 1) ? __high2float(h2) : __low2float(h2);
                a0 += cf * sf[XG_XH + sl * 3];
                a1 += cf * sf[XG_XH + sl * 3 + 1];
                a2 += cf * sf[XG_XH + sl * 3 + 2];
            }
            bool segEnd = (sl == 63) || (sN[sl + 1] != n);
            if (segEnd) {
                if (n >= 0) {
                    int beg = g_off[n], end = g_off[n + 1];
                    bool full = (beg == p0 + segStart) && (end == p0 + sl + 1);
                    if (full) {
                        float invc = 1.f / ((float)(end - beg) + 1.f);
                        g_he[n * 256 + c] = accH;
                        float s0 = a0 * invc, s1 = a1 * invc, s2 = a2 * invc;
                        g_cnorm[n * 256 + c] = s0 * s0 + s1 * s1 + s2 * s2;
                        float r0 = wv * s0, r1 = wv * s1, r2 = wv * s2;
                        #pragma unroll
                        for (int o = 16; o > 0; o >>= 1) {
                            r0 += __shfl_xor_sync(0xFFFFFFFFu, r0, o);
                            r1 += __shfl_xor_sync(0xFFFFFFFFu, r1, o);
                            r2 += __shfl_xor_sync(0xFFFFFFFFu, r2, o);
                        }
                        if (lid == 0) {
                            atomicAdd(&sf[XG_SDV + seg * 3],     r0);
                            atomicAdd(&sf[XG_SDV + seg * 3 + 1], r1);
                            atomicAdd(&sf[XG_SDV + seg * 3 + 2], r2);
                        }
                        if (c == 0) sSegN[seg] = n;
                    } else {
                        int slot = (segStart == 0) ? 0 : 1;
                        g_phe[((size_t)blk * 2 + slot) * 256 + c] = accH;
                        g_pcomb[(((size_t)blk * 2 + slot) * 3 + 0) * 256 + c] = a0;
                        g_pcomb[(((size_t)blk * 2 + slot) * 3 + 1) * 256 + c] = a1;
                        g_pcomb[(((size_t)blk * 2 + slot) * 3 + 2) * 256 + c] = a2;
                    }
                }
                accH = 0.f; a0 = 0.f; a1 = 0.f; a2 = 0.f;
                segStart = sl + 1;
                seg++;
            }
        }
    }
    __syncthreads();
    if (tid < 64) {
        int n = sSegN[tid];
        if (n >= 0) {
            g_dv[n * 3]     = sf[XG_SDV + tid * 3];
            g_dv[n * 3 + 1] = sf[XG_SDV + tid * 3 + 1];
            g_dv[n * 3 + 2] = sf[XG_SDV + tid * 3 + 2];
        }
    }
}

// ---------------- K_fin: finish boundary + empty nodes ----------------
__global__ void k_fin(const float* __restrict__ W_vmix, int N) {
    __shared__ float red[24];
    int n = blockIdx.x;
    int c = threadIdx.x, lid = c & 31, wid = c >> 5;
    int beg = g_off[n], end = g_off[n + 1];
    if (end == beg) {
        g_he[n * 256 + c] = 0.f;
        g_cnorm[n * 256 + c] = 0.f;
        if (c < 3) g_dv[n * 3 + c] = 0.f;
        return;
    }
    int b0 = beg >> 6, b1 = (end - 1) >> 6;
    if (b0 == b1) return;

    float accH = 0.f, a0 = 0.f, a1 = 0.f, a2 = 0.f;
    for (int b = b0; b <= b1; b++) {
        int slot = (b == b0 && (beg & 63) != 0) ? 1 : 0;
        size_t base = ((size_t)b * 2 + slot);
        accH += g_phe[base * 256 + c];
        a0 += g_pcomb[(base * 3 + 0) * 256 + c];
        a1 += g_pcomb[(base * 3 + 1) * 256 + c];
        a2 += g_pcomb[(base * 3 + 2) * 256 + c];
    }
    g_he[n * 256 + c] = accH;
    float invc = 1.f / ((float)(end - beg) + 1.f);
    float s0 = a0 * invc, s1 = a1 * invc, s2 = a2 * invc;
    g_cnorm[n * 256 + c] = s0 * s0 + s1 * s1 + s2 * s2;
    float wv = W_vmix[c];
    float r0 = wv * s0, r1 = wv * s1, r2 = wv * s2;
    #pragma unroll
    for (int o = 16; o > 0; o >>= 1) {
        r0 += __shfl_xor_sync(0xFFFFFFFFu, r0, o);
        r1 += __shfl_xor_sync(0xFFFFFFFFu, r1, o);
        r2 += __shfl_xor_sync(0xFFFFFFFFu, r2, o);
    }
    if (lid == 0) { red[wid * 3] = r0; red[wid * 3 + 1] = r1; red[wid * 3 + 2] = r2; }
    __syncthreads();
    if (c < 3) {
        float s = 0.f;
        #pragma unroll
        for (int w = 0; w < 8; w++) s += red[w * 3 + c];
        g_dv[n * 3 + c] = s;
    }
}

// ---------------- K7: node MLPs via fp16 mma.sync ----------------
#define NO_CN   0
#define NO_N3   4224
#define NO_T    10496
#define NO_HN   11648
#define NO_H    12800
#define NO_B    14848
#define NO_W    15232
#define N_SMEM  (27776 * 4)

#define NODE_GEMM(ABASE, ASTRIDE, BSTRIDE, KSTEPS, ACC) \
    { uint32_t adA = sbase + ((ABASE) + (mrow + (mq & 1) * 8 + rr) * (ASTRIDE) + (mq >> 1) * 4) * 4; \
      uint32_t adB = sbase + (NO_W + (ncol + (mq >> 1) * 8 + rr) * (BSTRIDE) + (mq & 1) * 4) * 4; \
      _Pragma("unroll 4") \
      for (int ks = 0; ks < (KSTEPS); ks++) { \
          uint32_t aH[4]; \
          LDSM4(aH[0], aH[1], aH[2], aH[3], adA + ks * 32); \
          uint32_t b0, b1, b2, b3; \
          LDSM4(b0, b1, b2, b3, adB + ks * 32); \
          { uint32_t bb[2] = { b0, b1 }; mma16816h(ACC[0], aH, bb); } \
          { uint32_t bb[2] = { b2, b3 }; mma16816h(ACC[1], aH, bb); } \
      } }

__global__ void __launch_bounds__(256, 2)
k_node(const float* __restrict__ h, const float* __restrict__ x,
       const float* __restrict__ v,
       const float* __restrict__ b_post1, const float* __restrict__ b_post2,
       const float* __restrict__ b_node1, const float* __restrict__ b_node2,
       const float* __restrict__ b_vel1,  const float* __restrict__ W_vel2,
       float* __restrict__ out_h, float* __restrict__ out_x,
       float* __restrict__ out_v, int N)
{
    extern __shared__ uint32_t su[];
    float* sf = (float*)su;
    int tid = threadIdx.x, lid = tid & 31, wid = tid >> 5;
    int g = lid >> 2, tg = lid & 3;
    int mq = lid >> 3, rr = lid & 7;
    int mrow = (wid & 1) * 16;
    int ncol = (wid >> 1) * 16;
    int n0 = blockIdx.x * 32;
    int nn = min(32, N - n0);
    uint32_t sbase = smem_u32(su);

    if (tid < 64) {
        sf[NO_B + tid]       = b_post1[tid];
        sf[NO_B + 64 + tid]  = b_post2[tid];
        sf[NO_B + 128 + tid] = b_node1[tid];
        sf[NO_B + 192 + tid] = b_node2[tid];
        sf[NO_B + 256 + tid] = b_vel1[tid];
        sf[NO_B + 320 + tid] = W_vel2[tid];
    }
    for (int i = tid; i < 4096; i += 256) {
        int row = i >> 7, kp = i & 127;
        float2 c2 = make_float2(0.f, 0.f), e2 = make_float2(0.f, 0.f);
        if (row < nn) {
            c2 = *(const float2*)&g_cnorm[(size_t)(n0 + row) * 256 + 2 * kp];
            e2 = *(const float2*)&g_he[(size_t)(n0 + row) * 256 + 2 * kp];
        }
        su[NO_CN + row * 132 + kp]      = pack2h(c2.x, c2.y);
        su[NO_N3 + row * 196 + 32 + kp] = pack2h(e2.x, e2.y);
    }
    for (int i = tid; i < 1024; i += 256) {
        int row = i >> 5, kp = i & 31;
        float2 h2 = make_float2(0.f, 0.f);
        if (row < nn) h2 = *(const float2*)&h[(n0 + row) * 64 + 2 * kp];
        sf[NO_H + row * 64 + 2 * kp]     = h2.x;
        sf[NO_H + row * 64 + 2 * kp + 1] = h2.y;
        su[NO_N3 + row * 196 + kp] = pack2h(h2.x, h2.y);
    }
    for (int i = tid; i < 8192; i += 256) {
        int n = i >> 7, kp = i & 127;
        su[NO_W + n * 132 + kp] = g_nwp1[i];
    }
    __syncthreads();

    float acc[2][4];
    int r0 = mrow + g, r1 = r0 + 8;

    // S1
    #pragma unroll
    for (int nt = 0; nt < 2; nt++)
        #pragma unroll
        for (int q = 0; q < 4; q++) acc[nt][q] = 0.f;
    NODE_GEMM(NO_CN, 132, 132, 16, acc)
    #pragma unroll
    for (int nt = 0; nt < 2; nt++) {
        int c0 = ncol + nt * 8 + tg * 2;
        float b0v = sf[NO_B + c0], b1v = sf[NO_B + c0 + 1];
        su[NO_T + r0 * 36 + (c0 >> 1)] = pack2h(siluf(acc[nt][0] + b0v), siluf(acc[nt][1] + b1v));
        su[NO_T + r1 * 36 + (c0 >> 1)] = pack2h(siluf(acc[nt][2] + b0v), siluf(acc[nt][3] + b1v));
    }
    __syncthreads();

    // S2
    for (int i = tid; i < 2048; i += 256) su[NO_W + (i >> 5) * 36 + (i & 31)] = g_nwp2[i];
    __syncthreads();
    #pragma unroll
    for (int nt = 0; nt < 2; nt++)
        #pragma unroll
        for (int q = 0; q < 4; q++) acc[nt][q] = 0.f;
    NODE_GEMM(NO_T, 36, 36, 4, acc)
    #pragma unroll
    for (int nt = 0; nt < 2; nt++) {
        int c0 = ncol + nt * 8 + tg * 2;
        float b0v = sf[NO_B + 64 + c0], b1v = sf[NO_B + 64 + c0 + 1];
        su[NO_N3 + r0 * 196 + 160 + (c0 >> 1)] = pack2h(siluf(acc[nt][0] + b0v), siluf(acc[nt][1] + b1v));
        su[NO_N3 + r1 * 196 + 160 + (c0 >> 1)] = pack2h(siluf(acc[nt][2] + b0v), siluf(acc[nt][3] + b1v));
    }
    __syncthreads();

    // S3
    for (int i = tid; i < 12288; i += 256) su[NO_W + (i / 192) * 196 + (i % 192)] = g_nwn1[i];
    __syncthreads();
    #pragma unroll
    for (int nt = 0; nt < 2; nt++)
        #pragma unroll
        for (int q = 0; q < 4; q++) acc[nt][q] = 0.f;
    NODE_GEMM(NO_N3, 196, 196, 24, acc)
    #pragma unroll
    for (int nt = 0; nt < 2; nt++) {
        int c0 = ncol + nt * 8 + tg * 2;
        float b0v = sf[NO_B + 128 + c0], b1v = sf[NO_B + 128 + c0 + 1];
        su[NO_T + r0 * 36 + (c0 >> 1)] = pack2h(siluf(acc[nt][0] + b0v), siluf(acc[nt][1] + b1v));
        su[NO_T + r1 * 36 + (c0 >> 1)] = pack2h(siluf(acc[nt][2] + b0v), siluf(acc[nt][3] + b1v));
    }
    __syncthreads();

    // S4
    for (int i = tid; i < 2048; i += 256) su[NO_W + (i >> 5) * 36 + (i & 31)] = g_nwn2[i];
    __syncthreads();
    #pragma unroll
    for (int nt = 0; nt < 2; nt++)
        #pragma unroll
        for (int q = 0; q < 4; q++) acc[nt][q] = 0.f;
    NODE_GEMM(NO_T, 36, 36, 4, acc)
    #pragma unroll
    for (int nt = 0; nt < 2; nt++) {
        int c0 = ncol + nt * 8 + tg * 2;
        float b0v = sf[NO_B + 192 + c0], b1v = sf[NO_B + 192 + c0 + 1];
        float v00 = sf[NO_H + r0 * 64 + c0]     + siluf(acc[nt][0] + b0v);
        float v01 = sf[NO_H + r0 * 64 + c0 + 1] + siluf(acc[nt][1] + b1v);
        float v10 = sf[NO_H + r1 * 64 + c0]     + siluf(acc[nt][2] + b0v);
        float v11 = sf[NO_H + r1 * 64 + c0 + 1] + siluf(acc[nt][3] + b1v);
        su[NO_HN + r0 * 36 + (c0 >> 1)] = pack2h(v00, v01);
        su[NO_HN + r1 * 36 + (c0 >> 1)] = pack2h(v10, v11);
        if (r0 < nn) *(float2*)&out_h[(n0 + r0) * 64 + c0] = make_float2(v00, v01);
        if (r1 < nn) *(float2*)&out_h[(n0 + r1) * 64 + c0] = make_float2(v10, v11);
    }
    __syncthreads();

    // S5
    for (int i = tid; i < 2048; i += 256) su[NO_W + (i >> 5) * 36 + (i & 31)] = g_nwv1[i];
    __syncthreads();
    #pragma unroll
    for (int nt = 0; nt < 2; nt++)
        #pragma unroll
        for (int q = 0; q < 4; q++) acc[nt][q] = 0.f;
    NODE_GEMM(NO_HN, 36, 36, 4, acc)
    #pragma unroll
    for (int nt = 0; nt < 2; nt++) {
        int c0 = ncol + nt * 8 + tg * 2;
        float b0v = sf[NO_B + 256 + c0], b1v = sf[NO_B + 256 + c0 + 1];
        float w0v = sf[NO_B + 320 + c0], w1v = sf[NO_B + 320 + c0 + 1];
        sf[NO_H + r0 * 64 + c0]     = siluf(acc[nt][0] + b0v) * w0v;
        sf[NO_H + r0 * 64 + c0 + 1] = siluf(acc[nt][1] + b1v) * w1v;
        sf[NO_H + r1 * 64 + c0]     = siluf(acc[nt][2] + b0v) * w0v;
        sf[NO_H + r1 * 64 + c0 + 1] = siluf(acc[nt][3] + b1v) * w1v;
    }
    __syncthreads();

    if (tid < nn) {
        int ln = tid;
        float s = 0.f;
        #pragma unroll 8
        for (int k = 0; k < 64; k++) s += sf[NO_H + ln * 64 + k];
        float scale = 2.f / (1.f + __expf(-s));
        int n = n0 + ln;
        #pragma unroll
        for (int d = 0; d < 3; d++) {
            float vn = g_dv[n * 3 + d] + scale * v[n * 3 + d];
            out_v[n * 3 + d] = vn;
            out_x[n * 3 + d] = x[n * 3 + d] + vn;
        }
    }
}

// ---------------- launch ----------------
extern "C" void kernel_launch(void* const* d_in, const int* in_sizes, int n_in,
                              void* d_out, int out_size)
{
    const float* h        = (const float*)d_in[0];
    const float* x        = (const float*)d_in[1];
    const float* v        = (const float*)d_in[2];
    const int*   idxs     = (const int*)  d_in[3];
    const float* rbf_mean = (const float*)d_in[4];
    const float* rbf_beta = (const float*)d_in[5];
    const float* W_in     = (const float*)d_in[6];
    const float* b_in     = (const float*)d_in[7];
    const float* W_out1   = (const float*)d_in[8];
    const float* b_out1   = (const float*)d_in[9];
    const float* W_out2   = (const float*)d_in[10];
    const float* b_out2   = (const float*)d_in[11];
    const float* W_att    = (const float*)d_in[12];
    const float* b_att    = (const float*)d_in[13];
    const float* W_xmix   = (const float*)d_in[14];
    const float* W_post1  = (const float*)d_in[15];
    const float* b_post1  = (const float*)d_in[16];
    const float* W_post2  = (const float*)d_in[17];
    const float* b_post2  = (const float*)d_in[18];
    const float* W_node1  = (const float*)d_in[19];
    const float* b_node1  = (const float*)d_in[20];
    const float* W_node2  = (const float*)d_in[21];
    const float* b_node2  = (const float*)d_in[22];
    const float* W_vmix   = (const float*)d_in[23];
    const float* W_vel1   = (const float*)d_in[24];
    const float* b_vel1   = (const float*)d_in[25];
    const float* W_vel2   = (const float*)d_in[26];

    int N = in_sizes[0] / 64;
    int E = in_sizes[3] / 2;

    float* out  = (float*)d_out;
    float* outh = out;
    float* outx = out + (size_t)N * 64;
    float* outv = out + (size_t)N * 67;

    cudaFuncSetAttribute(k_edge_mma, cudaFuncAttributeMaxDynamicSharedMemorySize, E_SMEM);
    cudaFuncSetAttribute(k_xagg,     cudaFuncAttributeMaxDynamicSharedMemorySize, XG_SMEM);
    cudaFuncSetAttribute(k_node,     cudaFuncAttributeMaxDynamicSharedMemorySize, N_SMEM);

    k_init<<<256, 256>>>(N, W_xmix, W_in, W_out1, W_out2,
                         W_post1, W_post2, W_node1, W_node2, W_vel1);
    k_edge_mma<<<296, 256, E_SMEM>>>(h, x, idxs, rbf_mean, rbf_beta,
                                     b_in, b_out1, b_out2, W_att, b_att, E);
    k_scan<<<1, 1024>>>(N);
    k_fill<<<(E + 255) / 256, 256>>>(idxs, E);
    k_xagg<<<(E + 63) / 64, 256, XG_SMEM>>>(idxs, W_vmix, E);
    k_fin<<<N, 256>>>(W_vmix, N);
    k_node<<<(N + 31) / 32, 256, N_SMEM>>>(h, x, v,
                                           b_post1, b_post2, b_node1, b_node2,
                                           b_vel1, W_vel2,
                                           outh, outx, outv, N);
}

// round 17
// speedup vs baseline: 1.3186x; 1.0099x over previous
#include <cuda_runtime.h>
#include <cuda_fp16.h>
#include <stdint.h>
#include <math.h>

#define NMAX 10000
#define EMAX 160000
#define NBLK ((EMAX + 63) / 64)

// ---------------- scratch ----------------
__device__ uint32_t g_hemtx2[EMAX * 32];     // h_e_mtx fp16x2 [e][32]
__device__ float g_xhat[EMAX * 3];
__device__ float g_w[EMAX * 4];
__device__ float g_expsum[NMAX * 4];
__device__ int   g_counts[NMAX];
__device__ int   g_off[NMAX + 1];
__device__ int   g_cursor[NMAX];
__device__ int   g_eid[EMAX];
__device__ float g_he[NMAX * 256];
__device__ float g_cnorm[NMAX * 256];
__device__ float g_dv[NMAX * 3];
__device__ float g_phe[NBLK * 2 * 256];
__device__ float g_pcomb[NBLK * 2 * 3 * 256];
__device__ __half g_wx[256 * 256];           // W_xmix^T fp16 [n][k]
__device__ uint32_t g_ewi[4096];
__device__ uint32_t g_ew1a[4096];
__device__ uint32_t g_ew1b[2048];
__device__ uint32_t g_ew2[2048];
// node-MLP weights, fp16x2 [n][k]
__device__ uint32_t g_nwp1[8192];
__device__ uint32_t g_nwn1[12288];
__device__ uint32_t g_nwp2[2048];
__device__ uint32_t g_nwn2[2048];
__device__ uint32_t g_nwv1[2048];

__device__ __forceinline__ float siluf(float x) { return x / (1.f + __expf(-x)); }
__device__ __forceinline__ float fast_tanh(float x) {
    float y; asm("tanh.approx.f32 %0, %1;" : "=f"(y) : "f"(x)); return y;
}
__device__ __forceinline__ void mma16816h(float* d, const uint32_t* a, const uint32_t* b) {
    asm volatile("mma.sync.aligned.m16n8k16.row.col.f32.f16.f16.f32 "
        "{%0,%1,%2,%3}, {%4,%5,%6,%7}, {%8,%9}, {%0,%1,%2,%3};"
        : "+f"(d[0]), "+f"(d[1]), "+f"(d[2]), "+f"(d[3])
        : "r"(a[0]), "r"(a[1]), "r"(a[2]), "r"(a[3]), "r"(b[0]), "r"(b[1]));
}
__device__ __forceinline__ uint32_t pack2h(float a, float b) {
    __half2 p = __floats2half2_rn(a, b);
    return *(uint32_t*)&p;
}
__device__ __forceinline__ uint32_t smem_u32(const void* p) {
    uint32_t a;
    asm("{ .reg .u64 t; cvta.to.shared.u64 t, %1; cvt.u32.u64 %0, t; }" : "=r"(a) : "l"(p));
    return a;
}
#define LDSM4(r0, r1, r2, r3, addr) \
    asm volatile("ldmatrix.sync.aligned.m8n8.x4.shared.b16 {%0,%1,%2,%3}, [%4];" \
        : "=r"(r0), "=r"(r1), "=r"(r2), "=r"(r3) : "r"(addr))
#define CP_ASYNC16(dst, src) \
    asm volatile("cp.async.cg.shared.global [%0], [%1], 16;" :: "r"(dst), "l"(src) : "memory")
#define CP_COMMIT() asm volatile("cp.async.commit_group;" ::: "memory")
#define CP_WAIT0()  asm volatile("cp.async.wait_group 0;" ::: "memory")

// ---------------- K0: init + weight prep ----------------
__global__ void k_init(int N,
                       const float* __restrict__ W_xmix,
                       const float* __restrict__ W_in,
                       const float* __restrict__ W_out1,
                       const float* __restrict__ W_out2,
                       const float* __restrict__ W_post1,
                       const float* __restrict__ W_post2,
                       const float* __restrict__ W_node1,
                       const float* __restrict__ W_node2,
                       const float* __restrict__ W_vel1) {
    int i = blockIdx.x * blockDim.x + threadIdx.x;
    if (i < N * 4) g_expsum[i] = 0.f;
    if (i < N) g_counts[i] = 0;
    if (i < 65536) {
        int n = i >> 8, k = i & 255;
        g_wx[n * 256 + k] = __float2half_rn(W_xmix[k * 256 + n]);
    }
    if (i < 4096) {
        int n = i >> 6, k0 = (i & 63) * 2;
        float w0 = (n < 50) ? W_in[k0 * 50 + n] : 0.f;
        float w1 = (n < 50) ? W_in[(k0 + 1) * 50 + n] : 0.f;
        g_ewi[i] = pack2h(w0, w1);
    } else if (i < 8192) {
        int j = i - 4096;
        int n = j >> 6, k0 = (j & 63) * 2;
        g_ew1a[j] = pack2h(W_out1[k0 * 64 + n], W_out1[(k0 + 1) * 64 + n]);
    } else if (i < 10240) {
        int j = i - 8192;
        int n = j >> 5, k0 = (j & 31) * 2;
        float w0 = (k0 < 50) ? W_out1[(128 + k0) * 64 + n] : ((k0 == 50) ? W_out1[178 * 64 + n] : 0.f);
        int k1 = k0 + 1;
        float w1 = (k1 < 50) ? W_out1[(128 + k1) * 64 + n] : ((k1 == 50) ? W_out1[178 * 64 + n] : 0.f);
        g_ew1b[j] = pack2h(w0, w1);
    } else if (i < 12288) {
        int j = i - 10240;
        int n = j >> 5, k0 = (j & 31) * 2;
        g_ew2[j] = pack2h(W_out2[k0 * 64 + n], W_out2[(k0 + 1) * 64 + n]);
    } else if (i < 20480) {
        int j = i - 12288;
        int n = j >> 7, k0 = (j & 127) * 2;
        g_nwp1[j] = pack2h(W_post1[k0 * 64 + n], W_post1[(k0 + 1) * 64 + n]);
    } else if (i < 32768) {
        int j = i - 20480;
        int n = j / 192, kp = j % 192, k0 = kp * 2;
        g_nwn1[j] = pack2h(W_node1[k0 * 64 + n], W_node1[(k0 + 1) * 64 + n]);
    } else if (i < 34816) {
        int j = i - 32768;
        int n = j >> 5, k0 = (j & 31) * 2;
        g_nwp2[j] = pack2h(W_post2[k0 * 64 + n], W_post2[(k0 + 1) * 64 + n]);
    } else if (i < 36864) {
        int j = i - 34816;
        int n = j >> 5, k0 = (j & 31) * 2;
        g_nwn2[j] = pack2h(W_node2[k0 * 64 + n], W_node2[(k0 + 1) * 64 + n]);
    } else if (i < 38912) {
        int j = i - 36864;
        int n = j >> 5, k0 = (j & 31) * 2;
        g_nwv1[j] = pack2h(W_vel1[k0 * 64 + n], W_vel1[(k0 + 1) * 64 + n]);
    }
}

// ---------------- K1: edge MLP via fp16 mma.sync + ldmatrix (G1+G2a fused) ----------------
#define O_A     0
#define O_X     4352
#define O_M     6656
#define O_WI    8960
#define O_W1A   13312
#define O_W1B   17664
#define O_W2    19968
#define O_HE    22272
#define O_BIN   26496
#define O_BO1   26560
#define O_BO2   26624
#define O_MEAN  26688
#define O_BETA  26752
#define O_WA    26816
#define O_BA    27072
#define O_NORM  27076
#define O_EX    27140
#define O_XHT   27204
#define E_SMEM  (27400 * 4)

__global__ void __launch_bounds__(256, 2)
k_edge_mma(const float* __restrict__ h, const float* __restrict__ x,
           const int* __restrict__ idxs,
           const float* __restrict__ rbf_means, const float* __restrict__ rbf_betas,
           const float* __restrict__ b_in, const float* __restrict__ b_out1,
           const float* __restrict__ b_out2,
           const float* __restrict__ W_att, const float* __restrict__ b_att, int E)
{
    extern __shared__ uint32_t su[];
    float* sf = (float*)su;
    int tid = threadIdx.x, lid = tid & 31, wid = tid >> 5;
    int g = lid >> 2, tg = lid & 3;
    int mrow = (wid & 3) * 16, ncol = (wid >> 2) * 32;

    for (int i = tid; i < 4096; i += 256) {
        int n = i >> 6, kk = i & 63;
        su[O_WI  + n * 68 + kk] = g_ewi[i];
        su[O_W1A + n * 68 + kk] = g_ew1a[i];
    }
    for (int i = tid; i < 2048; i += 256) {
        int n = i >> 5, kk = i & 31;
        su[O_W1B + n * 36 + kk] = g_ew1b[i];
        su[O_W2  + n * 36 + kk] = g_ew2[i];
    }
    if (tid < 64) {
        sf[O_BIN + tid]  = (tid < 50) ? b_in[tid] : 0.f;
        sf[O_BO1 + tid]  = b_out1[tid];
        sf[O_BO2 + tid]  = b_out2[tid];
        sf[O_MEAN + tid] = (tid < 50) ? rbf_means[tid] : 0.f;
        sf[O_BETA + tid] = (tid < 50) ? rbf_betas[tid] : 1.f;
    }
    if (tid < 256) sf[O_WA + tid] = W_att[tid];
    if (tid < 4)   sf[O_BA + tid] = b_att[tid];
    __syncthreads();

    uint32_t sbase = smem_u32(su);
    int mq = lid >> 3, rr = lid & 7;
    int rA = mrow + (mq & 1) * 8 + rr;
    int cA = (mq >> 1) * 4;
    uint32_t adA  = sbase + (O_A  + rA * 68 + cA) * 4;
    uint32_t adX  = sbase + (O_X  + rA * 36 + cA) * 4;
    uint32_t adM  = sbase + (O_M  + rA * 36 + cA) * 4;
    int rB = (mq >> 1) * 8 + rr;
    int cB = (mq & 1) * 4;
    uint32_t adWI0  = sbase + (O_WI  + (ncol + rB) * 68 + cB) * 4;
    uint32_t adWI1  = sbase + (O_WI  + (ncol + 16 + rB) * 68 + cB) * 4;
    uint32_t adW1A0 = sbase + (O_W1A + (ncol + rB) * 68 + cB) * 4;
    uint32_t adW1A1 = sbase + (O_W1A + (ncol + 16 + rB) * 68 + cB) * 4;
    uint32_t adW1B0 = sbase + (O_W1B + (ncol + rB) * 36 + cB) * 4;
    uint32_t adW1B1 = sbase + (O_W1B + (ncol + 16 + rB) * 36 + cB) * 4;
    uint32_t adW20  = sbase + (O_W2  + (ncol + rB) * 36 + cB) * 4;
    uint32_t adW21  = sbase + (O_W2  + (ncol + 16 + rB) * 36 + cB) * 4;

    int ntiles = (E + 63) / 64;
    for (int tile = blockIdx.x; tile < ntiles; tile += gridDim.x) {
        int e0 = tile * 64, ne = min(64, E - e0);

        if (tid < 64) {
            float nrm = 0.f, xh0 = 0.f, xh1 = 0.f, xh2 = 0.f;
            if (tid < ne) {
                int s = idxs[2 * (e0 + tid)], d = idxs[2 * (e0 + tid) + 1];
                float dx = x[3 * s]     - x[3 * d];
                float dy = x[3 * s + 1] - x[3 * d + 1];
                float dz = x[3 * s + 2] - x[3 * d + 2];
                nrm = sqrtf(dx * dx + dy * dy + dz * dz + 1e-14f);
                float inv = 1.f / (nrm + 1e-5f);
                xh0 = dx * inv; xh1 = dy * inv; xh2 = dz * inv;
                atomicAdd(&g_counts[s], 1);
            }
            sf[O_NORM + tid] = nrm;
            sf[O_EX + tid]   = __expf(-nrm);
            sf[O_XHT + tid * 3] = xh0; sf[O_XHT + tid * 3 + 1] = xh1; sf[O_XHT + tid * 3 + 2] = xh2;
        }
        {
            int el = tid >> 2, part = tid & 3;
            uint32_t hb[16];
            if (el < ne) {
                int node = idxs[2 * (e0 + el) + (part >> 1)];
                const float4* hp = (const float4*)&h[node * 64 + (part & 1) * 32];
                #pragma unroll
                for (int i2 = 0; i2 < 8; i2++) {
                    float4 v = hp[i2];
                    hb[i2 * 2]     = pack2h(v.x, v.y);
                    hb[i2 * 2 + 1] = pack2h(v.z, v.w);
                }
            } else {
                #pragma unroll
                for (int i2 = 0; i2 < 16; i2++) hb[i2] = 0u;
            }
            uint4* dh = (uint4*)&su[O_A + el * 68 + part * 16];
            #pragma unroll
            for (int i2 = 0; i2 < 4; i2++)
                dh[i2] = make_uint4(hb[i2*4], hb[i2*4+1], hb[i2*4+2], hb[i2*4+3]);
        }
        __syncthreads();

        float accA[4][4], accB[4][4];

        // ---- fused pass: G1 (hcat@Wi -> accA) + G2a (hcat@W1a -> accB) ----
        #pragma unroll
        for (int nt = 0; nt < 4; nt++)
            #pragma unroll
            for (int q = 0; q < 4; q++) { accA[nt][q] = 0.f; accB[nt][q] = 0.f; }
        #pragma unroll
        for (int ks = 0; ks < 8; ks++) {
            uint32_t aH[4];
            LDSM4(aH[0], aH[1], aH[2], aH[3], adA + ks * 32);
            uint32_t b0, b1, b2, b3;
            LDSM4(b0, b1, b2, b3, adWI0 + ks * 32);
            { uint32_t bb[2] = { b0, b1 }; mma16816h(accA[0], aH, bb); }
            { uint32_t bb[2] = { b2, b3 }; mma16816h(accA[1], aH, bb); }
            LDSM4(b0, b1, b2, b3, adWI1 + ks * 32);
            { uint32_t bb[2] = { b0, b1 }; mma16816h(accA[2], aH, bb); }
            { uint32_t bb[2] = { b2, b3 }; mma16816h(accA[3], aH, bb); }
            LDSM4(b0, b1, b2, b3, adW1A0 + ks * 32);
            { uint32_t bb[2] = { b0, b1 }; mma16816h(accB[0], aH, bb); }
            { uint32_t bb[2] = { b2, b3 }; mma16816h(accB[1], aH, bb); }
            LDSM4(b0, b1, b2, b3, adW1A1 + ks * 32);
            { uint32_t bb[2] = { b0, b1 }; mma16816h(accB[2], aH, bb); }
            { uint32_t bb[2] = { b2, b3 }; mma16816h(accB[3], aH, bb); }
        }
        // G1 epilogue: _x = rbf * (h_in + b_in); col50 = norm; else 0
        #pragma unroll
        for (int nt = 0; nt < 4; nt++) {
            #pragma unroll
            for (int hh = 0; hh < 2; hh++) {
                int row = mrow + g + hh * 8;
                int c0 = ncol + nt * 8 + tg * 2;
                float v0 = accA[nt][hh * 2]     + sf[O_BIN + c0];
                float v1 = accA[nt][hh * 2 + 1] + sf[O_BIN + c0 + 1];
                float ex = sf[O_EX + row];
                float x0, x1;
                if (c0 < 50) { float d = ex - sf[O_MEAN + c0]; x0 = __expf(-sf[O_BETA + c0] * d * d) * v0; }
                else x0 = (c0 == 50) ? sf[O_NORM + row] : 0.f;
                if (c0 + 1 < 50) { float d = ex - sf[O_MEAN + c0 + 1]; x1 = __expf(-sf[O_BETA + c0 + 1] * d * d) * v1; }
                else x1 = 0.f;
                su[O_X + row * 36 + (c0 >> 1)] = pack2h(x0, x1);
            }
        }
        __syncthreads();

        // ---- G2b: accB += _x @ W1b; mid = silu(accB + b1) ----
        #pragma unroll
        for (int ks = 0; ks < 4; ks++) {
            uint32_t aH[4];
            LDSM4(aH[0], aH[1], aH[2], aH[3], adX + ks * 32);
            uint32_t b0, b1, b2, b3;
            LDSM4(b0, b1, b2, b3, adW1B0 + ks * 32);
            { uint32_t bb[2] = { b0, b1 }; mma16816h(accB[0], aH, bb); }
            { uint32_t bb[2] = { b2, b3 }; mma16816h(accB[1], aH, bb); }
            LDSM4(b0, b1, b2, b3, adW1B1 + ks * 32);
            { uint32_t bb[2] = { b0, b1 }; mma16816h(accB[2], aH, bb); }
            { uint32_t bb[2] = { b2, b3 }; mma16816h(accB[3], aH, bb); }
        }
        #pragma unroll
        for (int nt = 0; nt < 4; nt++) {
            #pragma unroll
            for (int hh = 0; hh < 2; hh++) {
                int row = mrow + g + hh * 8;
                int c0 = ncol + nt * 8 + tg * 2;
                float m0 = siluf(accB[nt][hh * 2]     + sf[O_BO1 + c0]);
                float m1 = siluf(accB[nt][hh * 2 + 1] + sf[O_BO1 + c0 + 1]);
                su[O_M + row * 36 + (c0 >> 1)] = pack2h(m0, m1);
            }
        }
        __syncthreads();

        // ---- G3: h_e = mid @ W2 + b2 (reuse accA) ----
        #pragma unroll
        for (int nt = 0; nt < 4; nt++)
            #pragma unroll
            for (int q = 0; q < 4; q++) accA[nt][q] = 0.f;
        #pragma unroll
        for (int ks = 0; ks < 4; ks++) {
            uint32_t aH[4];
            LDSM4(aH[0], aH[1], aH[2], aH[3], adM + ks * 32);
            uint32_t b0, b1, b2, b3;
            LDSM4(b0, b1, b2, b3, adW20 + ks * 32);
            { uint32_t bb[2] = { b0, b1 }; mma16816h(accA[0], aH, bb); }
            { uint32_t bb[2] = { b2, b3 }; mma16816h(accA[1], aH, bb); }
            LDSM4(b0, b1, b2, b3, adW21 + ks * 32);
            { uint32_t bb[2] = { b0, b1 }; mma16816h(accA[2], aH, bb); }
            { uint32_t bb[2] = { b2, b3 }; mma16816h(accA[3], aH, bb); }
        }
        #pragma unroll
        for (int nt = 0; nt < 4; nt++) {
            #pragma unroll
            for (int hh = 0; hh < 2; hh++) {
                int row = mrow + g + hh * 8;
                int c0 = ncol + nt * 8 + tg * 2;
                sf[O_HE + row * 66 + c0]     = accA[nt][hh * 2]     + sf[O_BO2 + c0];
                sf[O_HE + row * 66 + c0 + 1] = accA[nt][hh * 2 + 1] + sf[O_BO2 + c0 + 1];
            }
        }
        __syncthreads();

        // att: logits -> exp -> g_w, expsum
        {
            int el = tid >> 2, a = tid & 3;
            if (el < ne) {
                float acc2 = sf[O_BA + a];
                const float* hv = &sf[O_HE + el * 66];
                #pragma unroll 8
                for (int c = 0; c < 64; c++) acc2 += hv[c] * sf[O_WA + c * 4 + a];
                float lg = (acc2 > 0.f) ? acc2 : 2.f * (__expf(acc2 * 0.5f) - 1.f);
                float w = __expf(lg);
                int s = idxs[2 * (e0 + el)];
                g_w[(e0 + el) * 4 + a] = w;
                atomicAdd(&g_expsum[s * 4 + a], w);
            }
        }
        // hemtx writeback as fp16x2
        for (int i = tid; i < ne * 8; i += 256) {
            int el = i >> 3, c8 = (i & 7) * 8;
            const float* hv = &sf[O_HE + el * 66 + c8];
            uint4 o = make_uint4(pack2h(hv[0], hv[1]), pack2h(hv[2], hv[3]),
                                 pack2h(hv[4], hv[5]), pack2h(hv[6], hv[7]));
            *(uint4*)&g_hemtx2[(size_t)(e0 + el) * 32 + (c8 >> 1)] = o;
        }
        for (int i = tid; i < ne * 3; i += 256) g_xhat[e0 * 3 + i] = sf[O_XHT + i];
        __syncthreads();
    }
}

// ---------------- K2: exclusive scan (shuffle-based) ----------------
__global__ void k_scan(int N) {
    __shared__ int wsum[32];
    int t = threadIdx.x, lane = t & 31, w = t >> 5;
    int chunk = (N + 1023) / 1024;
    int base = t * chunk;
    int vals[16];
    int loc = 0;
    for (int k = 0; k < chunk; k++) {
        int idx = base + k;
        int v = (idx < N) ? g_counts[idx] : 0;
        vals[k] = loc; loc += v;
    }
    int inc = loc;
    #pragma unroll
    for (int o = 1; o < 32; o <<= 1) {
        int v = __shfl_up_sync(0xFFFFFFFFu, inc, o);
        if (lane >= o) inc += v;
    }
    if (lane == 31) wsum[w] = inc;
    __syncthreads();
    if (w == 0) {
        int v2 = wsum[lane];
        int i2 = v2;
        #pragma unroll
        for (int o = 1; o < 32; o <<= 1) {
            int x2 = __shfl_up_sync(0xFFFFFFFFu, i2, o);
            if (lane >= o) i2 += x2;
        }
        wsum[lane] = i2 - v2;
    }
    __syncthreads();
    int excl = wsum[w] + (inc - loc);
    for (int k = 0; k < chunk; k++) {
        int idx = base + k;
        if (idx < N) { g_off[idx] = excl + vals[k]; g_cursor[idx] = excl + vals[k]; }
    }
    if (t == 1023) g_off[N] = excl + loc;
}

// ---------------- K3: CSR fill (pure) ----------------
__global__ void k_fill(const int* __restrict__ idxs, int E) {
    int e = blockIdx.x * blockDim.x + threadIdx.x;
    if (e >= E) return;
    int s = idxs[2 * e];
    int p = atomicAdd(&g_cursor[s], 1);
    g_eid[p] = e;
}

// ---------------- K5: fused xmix GEMM + aggregation ----------------
#define XG_A    0
#define XG_W0   8448
#define XG_W1   17664
#define XG_XH   26880
#define XG_NODE 27072
#define XG_WV   27136
#define XG_SDV  27392
#define XG_SEGN 27584
#define XG_SMEM (27660 * 4)

__global__ void __launch_bounds__(256, 2)
k_xagg(const int* __restrict__ idxs, const float* __restrict__ W_vmix, int E)
{
    extern __shared__ uint32_t su[];
    float* sf = (float*)su;
    int tid = threadIdx.x, lid = tid & 31, wid = tid >> 5;
    int p0 = blockIdx.x * 64;
    uint32_t* pA = su + XG_A;
    uint32_t* pC = su + XG_W0;
    int* sN = (int*)(su + XG_NODE);
    int* sSegN = (int*)(su + XG_SEGN);
    uint32_t sbase = smem_u32(su);

    {
        uint32_t dst = sbase + (XG_W0 + tid * 36) * 4;
        const char* src = (const char*)&g_wx[tid * 256];
        #pragma unroll
        for (int i = 0; i < 9; i++) CP_ASYNC16(dst + i * 16, src + i * 16);
        CP_COMMIT();
    }

    {
        int sl = tid & 63, kq = tid >> 6;
        int e = -1, s = -1;
        float att[4], hm[16];
        int p = p0 + sl;
        if (p < E) {
            e = g_eid[p];
            s = idxs[2 * e];
            #pragma unroll
            for (int a = 0; a < 4; a++) att[a] = g_w[e * 4 + a] / g_expsum[s * 4 + a];
            const uint4* hp = (const uint4*)&g_hemtx2[(size_t)e * 32 + kq * 8];
            uint4 v0 = hp[0], v1 = hp[1];
            uint32_t hraw[8] = { v0.x, v0.y, v0.z, v0.w, v1.x, v1.y, v1.z, v1.w };
            #pragma unroll
            for (int i = 0; i < 8; i++) {
                __half2 hh = *(__half2*)&hraw[i];
                hm[2 * i]     = __low2float(hh);
                hm[2 * i + 1] = __high2float(hh);
            }
        } else {
            #pragma unroll
            for (int a = 0; a < 4; a++) att[a] = 0.f;
            #pragma unroll
            for (int i = 0; i < 16; i++) hm[i] = 0.f;
        }
        if (kq == 0) {
            sN[sl] = s;
            sSegN[sl] = -1;
            float x0 = 0.f, x1 = 0.f, x2 = 0.f;
            if (e >= 0) { x0 = g_xhat[e * 3]; x1 = g_xhat[e * 3 + 1]; x2 = g_xhat[e * 3 + 2]; }
            sf[XG_XH + sl * 3] = x0; sf[XG_XH + sl * 3 + 1] = x1; sf[XG_XH + sl * 3 + 2] = x2;
        }
        #pragma unroll
        for (int j = 0; j < 32; j++) {
            int kl = 2 * j;
            float m = hm[kl >> 2];
            pA[sl * 132 + ((kq * 64 + kl) >> 1)] = pack2h(m * att[kl & 3], m * att[(kl + 1) & 3]);
        }
        sf[XG_WV + tid] = W_vmix[tid];
        if (tid < 192) sf[XG_SDV + tid] = 0.f;
    }
    CP_WAIT0();
    __syncthreads();

    int g = lid >> 2, tg = lid & 3;
    int mrow = (wid & 1) * 32;
    int ncol = (wid >> 1) * 64;

    int mq = lid >> 3, rr = lid & 7;
    uint32_t adA0 = sbase + (XG_A + (mrow + (mq & 1) * 8 + rr) * 132 + (mq >> 1) * 4) * 4;
    uint32_t adA1 = adA0 + 16 * 132 * 4;
    int rB = (mq >> 1) * 8 + rr;
    int cB = (mq & 1) * 4;
    uint32_t adW0 = sbase + (XG_W0 + (ncol + rB) * 36 + cB) * 4;
    uint32_t adW1 = adW0 + 16 * 36 * 4;
    uint32_t adW2 = adW0 + 32 * 36 * 4;
    uint32_t adW3 = adW0 + 48 * 36 * 4;
    const uint32_t BUFD = (XG_W1 - XG_W0) * 4;

    float acc[2][8][4];
    #pragma unroll
    for (int mt = 0; mt < 2; mt++)
        #pragma unroll
        for (int nt = 0; nt < 8; nt++)
            #pragma unroll
            for (int q = 0; q < 4; q++) acc[mt][nt][q] = 0.f;

    #pragma unroll
    for (int kc = 0; kc < 4; kc++) {
        if (kc < 3) {
            uint32_t dst = sbase + ((((kc + 1) & 1) ? XG_W1 : XG_W0) + tid * 36) * 4;
            const char* src = (const char*)&g_wx[tid * 256 + (kc + 1) * 64];
            #pragma unroll
            for (int i = 0; i < 9; i++) CP_ASYNC16(dst + i * 16, src + i * 16);
            CP_COMMIT();
        }
        uint32_t boff = (kc & 1) ? BUFD : 0u;
        #pragma unroll
        for (int ks = 0; ks < 4; ks++) {
            uint32_t aoff = kc * 128 + ks * 32;
            uint32_t aH[2][4];
            LDSM4(aH[0][0], aH[0][1], aH[0][2], aH[0][3], adA0 + aoff);
            LDSM4(aH[1][0], aH[1][1], aH[1][2], aH[1][3], adA1 + aoff);
            uint32_t woff = boff + ks * 32;
            uint32_t b0, b1, b2, b3;
            #define XAGG_PAIR(ADDR, NT) \
                LDSM4(b0, b1, b2, b3, (ADDR) + woff); \
                { uint32_t bb[2] = { b0, b1 }; mma16816h(acc[0][NT], aH[0], bb); mma16816h(acc[1][NT], aH[1], bb); } \
                { uint32_t bb[2] = { b2, b3 }; mma16816h(acc[0][(NT)+1], aH[0], bb); mma16816h(acc[1][(NT)+1], aH[1], bb); }
            XAGG_PAIR(adW0, 0)
            XAGG_PAIR(adW1, 2)
            XAGG_PAIR(adW2, 4)
            XAGG_PAIR(adW3, 6)
            #undef XAGG_PAIR
        }
        if (kc < 3) {
            CP_WAIT0();
            __syncthreads();
        }
    }

    #pragma unroll
    for (int mt = 0; mt < 2; mt++)
        #pragma unroll
        for (int nt = 0; nt < 8; nt++) {
            int rl = mrow + mt * 16 + g;
            int col = ncol + nt * 8 + tg * 2;
            float* a = acc[mt][nt];
            pC[rl * 132 + (col >> 1)]       = pack2h(fast_tanh(a[0]), fast_tanh(a[1]));
            pC[(rl + 8) * 132 + (col >> 1)] = pack2h(fast_tanh(a[2]), fast_tanh(a[3]));
        }
    __syncthreads();

    // ---- segmented per-node reduction; dv via smem atomics ----
    {
        int c = tid;
        int blk = blockIdx.x;
        float wv = sf[XG_WV + c];
        float accH = 0.f, a0 = 0.f, a1 = 0.f, a2 = 0.f;
        int segStart = 0, seg = 0;
        for (int sl = 0; sl < 64; sl++) {
            int n = sN[sl];
            if (n >= 0) {
                uint32_t ap = pA[sl * 132 + (c >> 1)];
                __half2 av2 = *(__half2*)&ap;
                float Av = (c & 1) ? __high2float(av2) : __low2float(av2);
                accH += Av;
                uint32_t cp = pC[sl * 132 + (c >> 1)];
                __half2 h2 = *(__half2*)&cp;
                float cf = (c & 1) ? __high2float(h2) : __low2float(h2);
                a0 += cf * sf[XG_XH + sl * 3];
                a1 += cf * sf[XG_XH + sl * 3 + 1];
                a2 += cf * sf[XG_XH + sl * 3 + 2];
            }
            bool segEnd = (sl == 63) || (sN[sl + 1] != n);
            if (segEnd) {
                if (n >= 0) {
                    int beg = g_off[n], end = g_off[n + 1];
                    bool full = (beg == p0 + segStart) && (end == p0 + sl + 1);
                    if (full) {
                        float invc = 1.f / ((float)(end - beg) + 1.f);
                        g_he[n * 256 + c] = accH;
                        float s0 = a0 * invc, s1 = a1 * invc, s2 = a2 * invc;
                        g_cnorm[n * 256 + c] = s0 * s0 + s1 * s1 + s2 * s2;
                        float r0 = wv * s0, r1 = wv * s1, r2 = wv * s2;
                        #pragma unroll
                        for (int o = 16; o > 0; o >>= 1) {
                            r0 += __shfl_xor_sync(0xFFFFFFFFu, r0, o);
                            r1 += __shfl_xor_sync(0xFFFFFFFFu, r1, o);
                            r2 += __shfl_xor_sync(0xFFFFFFFFu, r2, o);
                        }
                        if (lid == 0) {
                            atomicAdd(&sf[XG_SDV + seg * 3],     r0);
                            atomicAdd(&sf[XG_SDV + seg * 3 + 1], r1);
                            atomicAdd(&sf[XG_SDV + seg * 3 + 2], r2);
                        }
                        if (c == 0) sSegN[seg] = n;
                    } else {
                        int slot = (segStart == 0) ? 0 : 1;
                        g_phe[((size_t)blk * 2 + slot) * 256 + c] = accH;
                        g_pcomb[(((size_t)blk * 2 + slot) * 3 + 0) * 256 + c] = a0;
                        g_pcomb[(((size_t)blk * 2 + slot) * 3 + 1) * 256 + c] = a1;
                        g_pcomb[(((size_t)blk * 2 + slot) * 3 + 2) * 256 + c] = a2;
                    }
                }
                accH = 0.f; a0 = 0.f; a1 = 0.f; a2 = 0.f;
                segStart = sl + 1;
                seg++;
            }
        }
    }
    __syncthreads();
    if (tid < 64) {
        int n = sSegN[tid];
        if (n >= 0) {
            g_dv[n * 3]     = sf[XG_SDV + tid * 3];
            g_dv[n * 3 + 1] = sf[XG_SDV + tid * 3 + 1];
            g_dv[n * 3 + 2] = sf[XG_SDV + tid * 3 + 2];
        }
    }
}

// ---------------- K_fin: finish boundary + empty nodes ----------------
__global__ void k_fin(const float* __restrict__ W_vmix, int N) {
    __shared__ float red[24];
    int n = blockIdx.x;
    int c = threadIdx.x, lid = c & 31, wid = c >> 5;
    int beg = g_off[n], end = g_off[n + 1];
    if (end == beg) {
        g_he[n * 256 + c] = 0.f;
        g_cnorm[n * 256 + c] = 0.f;
        if (c < 3) g_dv[n * 3 + c] = 0.f;
        return;
    }
    int b0 = beg >> 6, b1 = (end - 1) >> 6;
    if (b0 == b1) return;

    float accH = 0.f, a0 = 0.f, a1 = 0.f, a2 = 0.f;
    for (int b = b0; b <= b1; b++) {
        int slot = (b == b0 && (beg & 63) != 0) ? 1 : 0;
        size_t base = ((size_t)b * 2 + slot);
        accH += g_phe[base * 256 + c];
        a0 += g_pcomb[(base * 3 + 0) * 256 + c];
        a1 += g_pcomb[(base * 3 + 1) * 256 + c];
        a2 += g_pcomb[(base * 3 + 2) * 256 + c];
    }
    g_he[n * 256 + c] = accH;
    float invc = 1.f / ((float)(end - beg) + 1.f);
    float s0 = a0 * invc, s1 = a1 * invc, s2 = a2 * invc;
    g_cnorm[n * 256 + c] = s0 * s0 + s1 * s1 + s2 * s2;
    float wv = W_vmix[c];
    float r0 = wv * s0, r1 = wv * s1, r2 = wv * s2;
    #pragma unroll
    for (int o = 16; o > 0; o >>= 1) {
        r0 += __shfl_xor_sync(0xFFFFFFFFu, r0, o);
        r1 += __shfl_xor_sync(0xFFFFFFFFu, r1, o);
        r2 += __shfl_xor_sync(0xFFFFFFFFu, r2, o);
    }
    if (lid == 0) { red[wid * 3] = r0; red[wid * 3 + 1] = r1; red[wid * 3 + 2] = r2; }
    __syncthreads();
    if (c < 3) {
        float s = 0.f;
        #pragma unroll
        for (int w = 0; w < 8; w++) s += red[w * 3 + c];
        g_dv[n * 3 + c] = s;
    }
}

// ---------------- K7: node MLPs via fp16 mma.sync ----------------
#define NO_CN   0
#define NO_N3   4224
#define NO_T    10496
#define NO_HN   11648
#define NO_H    12800
#define NO_B    14848
#define NO_W    15232
#define N_SMEM  (27776 * 4)

#define NODE_GEMM(ABASE, ASTRIDE, BSTRIDE, KSTEPS, ACC) \
    { uint32_t adA = sbase + ((ABASE) + (mrow + (mq & 1) * 8 + rr) * (ASTRIDE) + (mq >> 1) * 4) * 4; \
      uint32_t adB = sbase + (NO_W + (ncol + (mq >> 1) * 8 + rr) * (BSTRIDE) + (mq & 1) * 4) * 4; \
      _Pragma("unroll 4") \
      for (int ks = 0; ks < (KSTEPS); ks++) { \
          uint32_t aH[4]; \
          LDSM4(aH[0], aH[1], aH[2], aH[3], adA + ks * 32); \
          uint32_t b0, b1, b2, b3; \
          LDSM4(b0, b1, b2, b3, adB + ks * 32); \
          { uint32_t bb[2] = { b0, b1 }; mma16816h(ACC[0], aH, bb); } \
          { uint32_t bb[2] = { b2, b3 }; mma16816h(ACC[1], aH, bb); } \
      } }

__global__ void __launch_bounds__(256, 2)
k_node(const float* __restrict__ h, const float* __restrict__ x,
       const float* __restrict__ v,
       const float* __restrict__ b_post1, const float* __restrict__ b_post2,
       const float* __restrict__ b_node1, const float* __restrict__ b_node2,
       const float* __restrict__ b_vel1,  const float* __restrict__ W_vel2,
       float* __restrict__ out_h, float* __restrict__ out_x,
       float* __restrict__ out_v, int N)
{
    extern __shared__ uint32_t su[];
    float* sf = (float*)su;
    int tid = threadIdx.x, lid = tid & 31, wid = tid >> 5;
    int g = lid >> 2, tg = lid & 3;
    int mq = lid >> 3, rr = lid & 7;
    int mrow = (wid & 1) * 16;
    int ncol = (wid >> 1) * 16;
    int n0 = blockIdx.x * 32;
    int nn = min(32, N - n0);
    uint32_t sbase = smem_u32(su);

    if (tid < 64) {
        sf[NO_B + tid]       = b_post1[tid];
        sf[NO_B + 64 + tid]  = b_post2[tid];
        sf[NO_B + 128 + tid] = b_node1[tid];
        sf[NO_B + 192 + tid] = b_node2[tid];
        sf[NO_B + 256 + tid] = b_vel1[tid];
        sf[NO_B + 320 + tid] = W_vel2[tid];
    }
    for (int i = tid; i < 4096; i += 256) {
        int row = i >> 7, kp = i & 127;
        float2 c2 = make_float2(0.f, 0.f), e2 = make_float2(0.f, 0.f);
        if (row < nn) {
            c2 = *(const float2*)&g_cnorm[(size_t)(n0 + row) * 256 + 2 * kp];
            e2 = *(const float2*)&g_he[(size_t)(n0 + row) * 256 + 2 * kp];
        }
        su[NO_CN + row * 132 + kp]      = pack2h(c2.x, c2.y);
        su[NO_N3 + row * 196 + 32 + kp] = pack2h(e2.x, e2.y);
    }
    for (int i = tid; i < 1024; i += 256) {
        int row = i >> 5, kp = i & 31;
        float2 h2 = make_float2(0.f, 0.f);
        if (row < nn) h2 = *(const float2*)&h[(n0 + row) * 64 + 2 * kp];
        sf[NO_H + row * 64 + 2 * kp]     = h2.x;
        sf[NO_H + row * 64 + 2 * kp + 1] = h2.y;
        su[NO_N3 + row * 196 + kp] = pack2h(h2.x, h2.y);
    }
    for (int i = tid; i < 8192; i += 256) {
        int n = i >> 7, kp = i & 127;
        su[NO_W + n * 132 + kp] = g_nwp1[i];
    }
    __syncthreads();

    float acc[2][4];
    int r0 = mrow + g, r1 = r0 + 8;

    // S1
    #pragma unroll
    for (int nt = 0; nt < 2; nt++)
        #pragma unroll
        for (int q = 0; q < 4; q++) acc[nt][q] = 0.f;
    NODE_GEMM(NO_CN, 132, 132, 16, acc)
    #pragma unroll
    for (int nt = 0; nt < 2; nt++) {
        int c0 = ncol + nt * 8 + tg * 2;
        float b0v = sf[NO_B + c0], b1v = sf[NO_B + c0 + 1];
        su[NO_T + r0 * 36 + (c0 >> 1)] = pack2h(siluf(acc[nt][0] + b0v), siluf(acc[nt][1] + b1v));
        su[NO_T + r1 * 36 + (c0 >> 1)] = pack2h(siluf(acc[nt][2] + b0v), siluf(acc[nt][3] + b1v));
    }
    __syncthreads();

    // S2
    for (int i = tid; i < 2048; i += 256) su[NO_W + (i >> 5) * 36 + (i & 31)] = g_nwp2[i];
    __syncthreads();
    #pragma unroll
    for (int nt = 0; nt < 2; nt++)
        #pragma unroll
        for (int q = 0; q < 4; q++) acc[nt][q] = 0.f;
    NODE_GEMM(NO_T, 36, 36, 4, acc)
    #pragma unroll
    for (int nt = 0; nt < 2; nt++) {
        int c0 = ncol + nt * 8 + tg * 2;
        float b0v = sf[NO_B + 64 + c0], b1v = sf[NO_B + 64 + c0 + 1];
        su[NO_N3 + r0 * 196 + 160 + (c0 >> 1)] = pack2h(siluf(acc[nt][0] + b0v), siluf(acc[nt][1] + b1v));
        su[NO_N3 + r1 * 196 + 160 + (c0 >> 1)] = pack2h(siluf(acc[nt][2] + b0v), siluf(acc[nt][3] + b1v));
    }
    __syncthreads();

    // S3
    for (int i = tid; i < 12288; i += 256) su[NO_W + (i / 192) * 196 + (i % 192)] = g_nwn1[i];
    __syncthreads();
    #pragma unroll
    for (int nt = 0; nt < 2; nt++)
        #pragma unroll
        for (int q = 0; q < 4; q++) acc[nt][q] = 0.f;
    NODE_GEMM(NO_N3, 196, 196, 24, acc)
    #pragma unroll
    for (int nt = 0; nt < 2; nt++) {
        int c0 = ncol + nt * 8 + tg * 2;
        float b0v = sf[NO_B + 128 + c0], b1v = sf[NO_B + 128 + c0 + 1];
        su[NO_T + r0 * 36 + (c0 >> 1)] = pack2h(siluf(acc[nt][0] + b0v), siluf(acc[nt][1] + b1v));
        su[NO_T + r1 * 36 + (c0 >> 1)] = pack2h(siluf(acc[nt][2] + b0v), siluf(acc[nt][3] + b1v));
    }
    __syncthreads();

    // S4
    for (int i = tid; i < 2048; i += 256) su[NO_W + (i >> 5) * 36 + (i & 31)] = g_nwn2[i];
    __syncthreads();
    #pragma unroll
    for (int nt = 0; nt < 2; nt++)
        #pragma unroll
        for (int q = 0; q < 4; q++) acc[nt][q] = 0.f;
    NODE_GEMM(NO_T, 36, 36, 4, acc)
    #pragma unroll
    for (int nt = 0; nt < 2; nt++) {
        int c0 = ncol + nt * 8 + tg * 2;
        float b0v = sf[NO_B + 192 + c0], b1v = sf[NO_B + 192 + c0 + 1];
        float v00 = sf[NO_H + r0 * 64 + c0]     + siluf(acc[nt][0] + b0v);
        float v01 = sf[NO_H + r0 * 64 + c0 + 1] + siluf(acc[nt][1] + b1v);
        float v10 = sf[NO_H + r1 * 64 + c0]     + siluf(acc[nt][2] + b0v);
        float v11 = sf[NO_H + r1 * 64 + c0 + 1] + siluf(acc[nt][3] + b1v);
        su[NO_HN + r0 * 36 + (c0 >> 1)] = pack2h(v00, v01);
        su[NO_HN + r1 * 36 + (c0 >> 1)] = pack2h(v10, v11);
        if (r0 < nn) *(float2*)&out_h[(n0 + r0) * 64 + c0] = make_float2(v00, v01);
        if (r1 < nn) *(float2*)&out_h[(n0 + r1) * 64 + c0] = make_float2(v10, v11);
    }
    __syncthreads();

    // S5
    for (int i = tid; i < 2048; i += 256) su[NO_W + (i >> 5) * 36 + (i & 31)] = g_nwv1[i];
    __syncthreads();
    #pragma unroll
    for (int nt = 0; nt < 2; nt++)
        #pragma unroll
        for (int q = 0; q < 4; q++) acc[nt][q] = 0.f;
    NODE_GEMM(NO_HN, 36, 36, 4, acc)
    #pragma unroll
    for (int nt = 0; nt < 2; nt++) {
        int c0 = ncol + nt * 8 + tg * 2;
        float b0v = sf[NO_B + 256 + c0], b1v = sf[NO_B + 256 + c0 + 1];
        float w0v = sf[NO_B + 320 + c0], w1v = sf[NO_B + 320 + c0 + 1];
        sf[NO_H + r0 * 64 + c0]     = siluf(acc[nt][0] + b0v) * w0v;
        sf[NO_H + r0 * 64 + c0 + 1] = siluf(acc[nt][1] + b1v) * w1v;
        sf[NO_H + r1 * 64 + c0]     = siluf(acc[nt][2] + b0v) * w0v;
        sf[NO_H + r1 * 64 + c0 + 1] = siluf(acc[nt][3] + b1v) * w1v;
    }
    __syncthreads();

    if (tid < nn) {
        int ln = tid;
        float s = 0.f;
        #pragma unroll 8
        for (int k = 0; k < 64; k++) s += sf[NO_H + ln * 64 + k];
        float scale = 2.f / (1.f + __expf(-s));
        int n = n0 + ln;
        #pragma unroll
        for (int d = 0; d < 3; d++) {
            float vn = g_dv[n * 3 + d] + scale * v[n * 3 + d];
            out_v[n * 3 + d] = vn;
            out_x[n * 3 + d] = x[n * 3 + d] + vn;
        }
    }
}

// ---------------- launch ----------------
extern "C" void kernel_launch(void* const* d_in, const int* in_sizes, int n_in,
                              void* d_out, int out_size)
{
    const float* h        = (const float*)d_in[0];
    const float* x        = (const float*)d_in[1];
    const float* v        = (const float*)d_in[2];
    const int*   idxs     = (const int*)  d_in[3];
    const float* rbf_mean = (const float*)d_in[4];
    const float* rbf_beta = (const float*)d_in[5];
    const float* W_in     = (const float*)d_in[6];
    const float* b_in     = (const float*)d_in[7];
    const float* W_out1   = (const float*)d_in[8];
    const float* b_out1   = (const float*)d_in[9];
    const float* W_out2   = (const float*)d_in[10];
    const float* b_out2   = (const float*)d_in[11];
    const float* W_att    = (const float*)d_in[12];
    const float* b_att    = (const float*)d_in[13];
    const float* W_xmix   = (const float*)d_in[14];
    const float* W_post1  = (const float*)d_in[15];
    const float* b_post1  = (const float*)d_in[16];
    const float* W_post2  = (const float*)d_in[17];
    const float* b_post2  = (const float*)d_in[18];
    const float* W_node1  = (const float*)d_in[19];
    const float* b_node1  = (const float*)d_in[20];
    const float* W_node2  = (const float*)d_in[21];
    const float* b_node2  = (const float*)d_in[22];
    const float* W_vmix   = (const float*)d_in[23];
    const float* W_vel1   = (const float*)d_in[24];
    const float* b_vel1   = (const float*)d_in[25];
    const float* W_vel2   = (const float*)d_in[26];

    int N = in_sizes[0] / 64;
    int E = in_sizes[3] / 2;

    float* out  = (float*)d_out;
    float* outh = out;
    float* outx = out + (size_t)N * 64;
    float* outv = out + (size_t)N * 67;

    cudaFuncSetAttribute(k_edge_mma, cudaFuncAttributeMaxDynamicSharedMemorySize, E_SMEM);
    cudaFuncSetAttribute(k_xagg,     cudaFuncAttributeMaxDynamicSharedMemorySize, XG_SMEM);
    cudaFuncSetAttribute(k_node,     cudaFuncAttributeMaxDynamicSharedMemorySize, N_SMEM);

    k_init<<<256, 256>>>(N, W_xmix, W_in, W_out1, W_out2,
                         W_post1, W_post2, W_node1, W_node2, W_vel1);
    k_edge_mma<<<296, 256, E_SMEM>>>(h, x, idxs, rbf_mean, rbf_beta,
                                     b_in, b_out1, b_out2, W_att, b_att, E);
    k_scan<<<1, 1024>>>(N);
    k_fill<<<(E + 255) / 256, 256>>>(idxs, E);
    k_xagg<<<(E + 63) / 64, 256, XG_SMEM>>>(idxs, W_vmix, E);
    k_fin<<<N, 256>>>(W_vmix, N);
    k_node<<<(N + 31) / 32, 256, N_SMEM>>>(h, x, v,
                                           b_post1, b_post2, b_node1, b_node2,
                                           b_vel1, W_vel2,
                                           outh, outx, outv, N);
}